// round 4
// baseline (speedup 1.0000x reference)
#include <cuda_runtime.h>
#include <cstdint>
#include <math.h>

#define HID   1024
#define NHEAD 16
#define HDIM  64
#define BB    8
#define LQ    16
#define LK    8192
#define RPB   (NHEAD*LQ)   /* 256 rows per batch */

// ---------------- scratch (device globals; no allocation allowed) ----------------
__device__ float g_q[BB*LQ*HID];                    // projected queries [128][1024]
__device__ float g_qk[BB*RPB*HID];                  // scale * q_h @ Wk_h  [8][256][1024]
__device__ float g_logits[(size_t)BB*RPB*LK];       // logits / probs in place [8][256][8192]
__device__ float g_ctx[4*BB*RPB*HID];               // split-K=4 partial ctx
__device__ float g_attn[BB*LQ*HID];                 // per-head V-projected ctx [128][1024]

// =====================================================================
// helpers
// =====================================================================
__device__ __forceinline__ unsigned f2tf(float x) {
    unsigned u;
    asm("cvt.rna.tf32.f32 %0, %1;" : "=r"(u) : "f"(x));
    return u;
}
__device__ __forceinline__ void mma_tf32(float c[4], const unsigned a[4], const unsigned b[2]) {
    asm("mma.sync.aligned.m16n8k8.row.col.f32.tf32.tf32.f32 "
        "{%0,%1,%2,%3}, {%4,%5,%6,%7}, {%8,%9}, {%0,%1,%2,%3};"
        : "+f"(c[0]), "+f"(c[1]), "+f"(c[2]), "+f"(c[3])
        : "r"(a[0]), "r"(a[1]), "r"(a[2]), "r"(a[3]), "r"(b[0]), "r"(b[1]));
}

// =====================================================================
// Fragment-layout tf32 mma.sync GEMM.
//   C[m][n] = sum_k A[m][k] * B[.][.]   (A always k-contiguous)
//   LAYB=0 (NT): B[n*ldb + k]   (logits = qk @ key^T)
//   LAYB=1 (NN): B[k*ldb + n]   (ctx   = probs @ value)
// BM=256, BN=128, BK=32, 512 threads (16 warps = 4m x 4n), warp tile 64x32.
// SMEM holds tf32 fragments in mma register order:
//   Afrag[s][mi][lane][r4]  (s = k8 step 0..3, mi = m16 tile 0..15)
//   Bfrag[s][ni][lane][r2]  (ni = n8 tile 0..15)
// Double buffered; one __syncthreads per K-chunk.
// grid.z = nbatch*ksplit -> (batch, part); each z writes its own C slab.
// =====================================================================
#define FG_BM 256
#define FG_BN 128
#define FG_BK 32
#define FG_AFRAG (4*16*32*4)            /* floats = 8192 -> 32 KB */
#define FG_BFRAG (4*16*32*2)            /* floats = 4096 -> 16 KB */
#define FG_BUF   (FG_AFRAG + FG_BFRAG)
#define FG_SMEM  (2*FG_BUF*4)           /* 96 KB */

template<int LAYB>
__global__ void __launch_bounds__(512)
gemm_frag(const float* __restrict__ A, const float* __restrict__ B,
          float* __restrict__ C, int Kpart, int lda, int ldb, int ldc,
          long sA, long sB, long sC, int ksplit)
{
    extern __shared__ __align__(16) unsigned smem[];
    unsigned* const abuf[2] = { smem,              smem + FG_BUF };
    unsigned* const bbuf[2] = { smem + FG_AFRAG,   smem + FG_BUF + FG_AFRAG };

    const int tid  = threadIdx.x;
    const int wid  = tid >> 5;
    const int lane = tid & 31;
    const int g    = lane >> 2;      // 0..7
    const int tg   = lane & 3;       // 0..3

    const int batch = blockIdx.z / ksplit;
    const int part  = blockIdx.z % ksplit;
    const int bn    = blockIdx.x * FG_BN;
    A += (long)batch*sA + (long)part*Kpart;
    if (LAYB == 0) B += (long)batch*sB + (long)part*Kpart;
    else           B += (long)batch*sB + (long)part*Kpart*ldb;
    C += (long)blockIdx.z*sC;

    // ---------- staging coordinates ----------
    // A: 256 rows x 8 u-slots (u = float4 index in k) = 2048 float4 / 512 thr = 4 each
    const int a_row = tid >> 1;
    const int a_ub  = (tid & 1) * 4;
    // A dest (per j): s=(u>>1), half=u&1, mi=row>>4, gg=row&7, sub=(row>>3)&1, r=half*2+sub
    // idx = ((s*16+mi)*32 + gg*4)*4 + r ; +4 floats per tg
    int a_dst[4];
#pragma unroll
    for (int j = 0; j < 4; j++) {
        const int u = a_ub + j, s = u >> 1, half = u & 1;
        const int mi = a_row >> 4, gg = a_row & 7, sub = (a_row >> 3) & 1;
        a_dst[j] = ((s*16 + mi)*32 + gg*4)*4 + half*2 + sub;
    }
    // B NT: 128 rows x 8 u = 1024 float4 / 512 = 2 each
    const int bnt_row = tid >> 2;
    const int bnt_ub  = (tid & 3) * 2;
    int bnt_dst[2];
#pragma unroll
    for (int j = 0; j < 2; j++) {
        const int u = bnt_ub + j, s = u >> 1, half = u & 1;
        const int ni = bnt_row >> 3, gg = bnt_row & 7;
        bnt_dst[j] = ((s*16 + ni)*32 + gg*4)*2 + half;
    }
    // B NN: 32 k x 32 v-slots (v = float4 index in n) = 1024 float4 / 512 = 2 each
    const int bnn_k  = tid >> 4;
    const int bnn_vb = (tid & 15) * 2;
    int bnn_dst[2];
#pragma unroll
    for (int j = 0; j < 2; j++) {
        const int v = bnn_vb + j;
        const int n0 = v*4;
        const int s = bnn_k >> 3, kk = bnn_k & 7, half = kk >> 2, ktg = kk & 3;
        const int ni = n0 >> 3, g0 = n0 & 7;
        bnn_dst[j] = ((s*16 + ni)*32 + g0*4 + ktg)*2 + half;  // +8 floats per n step
    }

    // ---------- compute coordinates ----------
    const int mib = (wid >> 2) * 4;     // first m16 tile of this warp
    const int nib = (wid & 3) * 4;      // first n8 tile
    const int wm  = (wid >> 2) * 64;
    const int wn  = (wid & 3) * 32;

    float acc[4][4][4];
#pragma unroll
    for (int i = 0; i < 4; i++)
#pragma unroll
        for (int j = 0; j < 4; j++)
#pragma unroll
            for (int r = 0; r < 4; r++) acc[i][j][r] = 0.f;

    const int chunks = Kpart / FG_BK;
    float4 ra[4], rb[2];

    // ---- load regs for chunk c ----
    auto load_regs = [&](int c) {
        const int k0 = c * FG_BK;
#pragma unroll
        for (int j = 0; j < 4; j++)
            ra[j] = *reinterpret_cast<const float4*>(&A[(long)a_row*lda + k0 + (a_ub + j)*4]);
        if (LAYB == 0) {
#pragma unroll
            for (int j = 0; j < 2; j++)
                rb[j] = *reinterpret_cast<const float4*>(&B[(long)(bn + bnt_row)*ldb + k0 + (bnt_ub + j)*4]);
        } else {
#pragma unroll
            for (int j = 0; j < 2; j++)
                rb[j] = *reinterpret_cast<const float4*>(&B[(long)(k0 + bnn_k)*ldb + bn + (bnn_vb + j)*4]);
        }
    };
    // ---- stage regs into fragment buffers ----
    auto stage = [&](int buf) {
        unsigned* ab = abuf[buf];
        unsigned* bb = bbuf[buf];
#pragma unroll
        for (int j = 0; j < 4; j++) {
            unsigned* d = ab + a_dst[j];
            d[0]  = f2tf(ra[j].x);
            d[4]  = f2tf(ra[j].y);
            d[8]  = f2tf(ra[j].z);
            d[12] = f2tf(ra[j].w);
        }
        if (LAYB == 0) {
#pragma unroll
            for (int j = 0; j < 2; j++) {
                unsigned* d = bb + bnt_dst[j];
                d[0] = f2tf(rb[j].x);
                d[2] = f2tf(rb[j].y);
                d[4] = f2tf(rb[j].z);
                d[6] = f2tf(rb[j].w);
            }
        } else {
#pragma unroll
            for (int j = 0; j < 2; j++) {
                unsigned* d = bb + bnn_dst[j];
                d[0]  = f2tf(rb[j].x);
                d[8]  = f2tf(rb[j].y);
                d[16] = f2tf(rb[j].z);
                d[24] = f2tf(rb[j].w);
            }
        }
    };
    // ---- compute one chunk from buffer ----
    auto compute = [&](int buf) {
        const unsigned* ab = abuf[buf];
        const unsigned* bb = bbuf[buf];
#pragma unroll
        for (int s = 0; s < 4; s++) {
            unsigned af[4][4], bf[4][2];
#pragma unroll
            for (int i = 0; i < 4; i++) {
                const unsigned* p = ab + ((s*16 + mib + i)*32 + lane)*4;
                uint4 v = *reinterpret_cast<const uint4*>(p);
                af[i][0] = v.x; af[i][1] = v.y; af[i][2] = v.z; af[i][3] = v.w;
            }
#pragma unroll
            for (int j = 0; j < 4; j++) {
                const unsigned* p = bb + ((s*16 + nib + j)*32 + lane)*2;
                uint2 v = *reinterpret_cast<const uint2*>(p);
                bf[j][0] = v.x; bf[j][1] = v.y;
            }
#pragma unroll
            for (int i = 0; i < 4; i++)
#pragma unroll
                for (int j = 0; j < 4; j++)
                    mma_tf32(acc[i][j], af[i], bf[j]);
        }
    };

    // ---- pipeline ----
    load_regs(0);
    stage(0);
    load_regs(1);
    __syncthreads();
    for (int c = 0; c < chunks; c++) {
        if (c + 1 < chunks) {
            stage((c + 1) & 1);
            if (c + 2 < chunks) load_regs(c + 2);
        }
        compute(c & 1);
        __syncthreads();
    }

    // ---- epilogue ----
#pragma unroll
    for (int i = 0; i < 4; i++) {
        const int row0 = wm + i*16 + g;
#pragma unroll
        for (int j = 0; j < 4; j++) {
            const int col = bn + wn + j*8 + 2*tg;
            *reinterpret_cast<float2*>(&C[(long)row0*ldc + col]) =
                make_float2(acc[i][j][0], acc[i][j][1]);
            *reinterpret_cast<float2*>(&C[(long)(row0 + 8)*ldc + col]) =
                make_float2(acc[i][j][2], acc[i][j][3]);
        }
    }
}

// =====================================================================
// fp32 FFMA NT GEMM for small projections K1/K7
// =====================================================================
template<int BM,int BN,int BK,int TM,int TN,bool BIAS>
__global__ void __launch_bounds__((BM/TM)*(BN/TN))
gemm_nt(const float* __restrict__ A, const float* __restrict__ Bm,
        const float* __restrict__ bias, float* __restrict__ C,
        int K, int lda, int ldb, int ldc)
{
    constexpr int TX = BN/TN, TY = BM/TM, NT = TX*TY;
    const int tid = threadIdx.x;
    const int tx  = tid % TX, ty = tid / TX;
    const int bm  = blockIdx.y*BM, bn = blockIdx.x*BN;

    __shared__ float As[BK][BM+4];
    __shared__ float Bs[BK][BN+4];

    float acc[TM][TN];
#pragma unroll
    for (int i=0;i<TM;i++)
#pragma unroll
        for (int j=0;j<TN;j++) acc[i][j] = 0.f;

    for (int k0 = 0; k0 < K; k0 += BK) {
#pragma unroll
        for (int i = tid; i < BM*BK/4; i += NT) {
            int m  = i / (BK/4);
            int k4 = (i % (BK/4)) * 4;
            float4 v = *reinterpret_cast<const float4*>(&A[(long)(bm+m)*lda + k0 + k4]);
            As[k4+0][m] = v.x; As[k4+1][m] = v.y; As[k4+2][m] = v.z; As[k4+3][m] = v.w;
        }
#pragma unroll
        for (int i = tid; i < BN*BK/4; i += NT) {
            int n  = i / (BK/4);
            int k4 = (i % (BK/4)) * 4;
            float4 v = *reinterpret_cast<const float4*>(&Bm[(long)(bn+n)*ldb + k0 + k4]);
            Bs[k4+0][n] = v.x; Bs[k4+1][n] = v.y; Bs[k4+2][n] = v.z; Bs[k4+3][n] = v.w;
        }
        __syncthreads();
#pragma unroll
        for (int k = 0; k < BK; k++) {
            float af[TM], bf[TN];
#pragma unroll
            for (int i=0;i<TM;i+=4)
                *reinterpret_cast<float4*>(&af[i]) =
                    *reinterpret_cast<const float4*>(&As[k][ty*TM + i]);
#pragma unroll
            for (int j=0;j<TN;j+=4)
                *reinterpret_cast<float4*>(&bf[j]) =
                    *reinterpret_cast<const float4*>(&Bs[k][tx*TN + j]);
#pragma unroll
            for (int i=0;i<TM;i++)
#pragma unroll
                for (int j=0;j<TN;j++)
                    acc[i][j] = fmaf(af[i], bf[j], acc[i][j]);
        }
        __syncthreads();
    }

#pragma unroll
    for (int i=0;i<TM;i++) {
        const int m = bm + ty*TM + i;
        float* crow = &C[(long)m*ldc + bn + tx*TN];
#pragma unroll
        for (int j=0;j<TN;j+=4) {
            float4 v;
            v.x = acc[i][j+0]; v.y = acc[i][j+1]; v.z = acc[i][j+2]; v.w = acc[i][j+3];
            if (BIAS) {
                const float* bp = &bias[bn + tx*TN + j];
                v.x += bp[0]; v.y += bp[1]; v.z += bp[2]; v.w += bp[3];
            }
            *reinterpret_cast<float4*>(&crow[j]) = v;
        }
    }
}

// =====================================================================
// qk = scale * q_h @ Wk_h
// =====================================================================
__global__ void qk_kernel(const float* __restrict__ q,
                          const float* __restrict__ Wk,
                          float* __restrict__ qk)
{
    const int bh = blockIdx.y;
    const int b = bh >> 4, h = bh & 15;
    const int col = blockIdx.x*128 + threadIdx.x;
    __shared__ float a[LQ][HDIM];
    for (int i = threadIdx.x; i < LQ*HDIM; i += 128) {
        int qq = i >> 6, e = i & 63;
        a[qq][e] = q[(b*LQ + qq)*HID + h*HDIM + e];
    }
    __syncthreads();
    float acc[LQ];
#pragma unroll
    for (int i=0;i<LQ;i++) acc[i] = 0.f;
#pragma unroll 8
    for (int e = 0; e < HDIM; e++) {
        float w = Wk[(h*HDIM + e)*HID + col];
#pragma unroll
        for (int qq = 0; qq < LQ; qq++) acc[qq] = fmaf(a[qq][e], w, acc[qq]);
    }
    const float scale = 0.125f;
#pragma unroll
    for (int qq = 0; qq < LQ; qq++)
        qk[((long)b*RPB + h*LQ + qq)*HID + col] = acc[qq] * scale;
}

// =====================================================================
// In-place row softmax over LK=8192 (pointer pre-offset; grid = #rows)
// =====================================================================
__global__ void softmax_kernel(float* __restrict__ logits)
{
    const size_t row = blockIdx.x;
    float* p = logits + row * (size_t)LK;
    __shared__ float buf[LK];
    __shared__ float red[8];
    const int tid = threadIdx.x;
    const int lane = tid & 31, warp = tid >> 5;
    float4*       b4 = reinterpret_cast<float4*>(buf);
    const float4* p4 = reinterpret_cast<const float4*>(p);

    float mx = -3.0e38f;
    for (int i = tid; i < LK/4; i += 256) {
        float4 v = p4[i]; b4[i] = v;
        mx = fmaxf(mx, fmaxf(fmaxf(v.x,v.y), fmaxf(v.z,v.w)));
    }
#pragma unroll
    for (int o=16;o;o>>=1) mx = fmaxf(mx, __shfl_xor_sync(0xffffffffu, mx, o));
    if (lane==0) red[warp] = mx;
    __syncthreads();
    mx = red[0];
#pragma unroll
    for (int w=1;w<8;w++) mx = fmaxf(mx, red[w]);

    float sum = 0.f;
    for (int i = tid; i < LK/4; i += 256) {
        float4 v = b4[i];
        v.x = expf(v.x - mx); v.y = expf(v.y - mx);
        v.z = expf(v.z - mx); v.w = expf(v.w - mx);
        b4[i] = v;
        sum += (v.x + v.y) + (v.z + v.w);
    }
#pragma unroll
    for (int o=16;o;o>>=1) sum += __shfl_xor_sync(0xffffffffu, sum, o);
    __syncthreads();
    if (lane==0) red[warp] = sum;
    __syncthreads();
    sum = 0.f;
#pragma unroll
    for (int w=0;w<8;w++) sum += red[w];
    const float inv = 1.f / sum;

    float4* o4 = reinterpret_cast<float4*>(p);
    for (int i = tid; i < LK/4; i += 256) {
        float4 v = b4[i];
        v.x *= inv; v.y *= inv; v.z *= inv; v.w *= inv;
        o4[i] = v;
    }
}

// =====================================================================
// attn = (sum of 4 ctx slabs) @ Wv_h^T + bv, per (b,h)
// =====================================================================
__global__ void attnv_kernel(const float* __restrict__ ctx,
                             const float* __restrict__ Wv,
                             const float* __restrict__ bv,
                             float* __restrict__ attn)
{
    const int bh = blockIdx.x;
    const int b = bh >> 4, h = bh & 15;
    const int t = threadIdx.x;
    const int d = t & 63, qg = t >> 6;
    __shared__ float cs[LQ][129];
    __shared__ float ws[HDIM][129];
    float acc[4] = {0.f,0.f,0.f,0.f};

    long row[4];
#pragma unroll
    for (int p = 0; p < 4; p++) row[p] = (long)(b*4 + p)*RPB + h*LQ;

    for (int e0 = 0; e0 < HID; e0 += 128) {
        __syncthreads();
        for (int i = t; i < LQ*128; i += 256) {
            int qq = i >> 7, e = i & 127;
            float v = 0.f;
#pragma unroll
            for (int p = 0; p < 4; p++) v += ctx[(row[p] + qq)*HID + e0 + e];
            cs[qq][e] = v;
        }
        for (int i = t; i < HDIM*128; i += 256) {
            int dd = i >> 7, e = i & 127;
            ws[dd][e] = Wv[(long)(h*HDIM + dd)*HID + e0 + e];
        }
        __syncthreads();
#pragma unroll 4
        for (int e = 0; e < 128; e++) {
            float w = ws[d][e];
#pragma unroll
            for (int j = 0; j < 4; j++)
                acc[j] = fmaf(cs[qg*4 + j][e], w, acc[j]);
        }
    }
    const float bvv = bv[h*HDIM + d];
#pragma unroll
    for (int j = 0; j < 4; j++)
        attn[(long)(b*LQ + qg*4 + j)*HID + h*HDIM + d] = acc[j] + bvv;
}

// =====================================================================
// launch
// =====================================================================
extern "C" void kernel_launch(void* const* d_in, const int* in_sizes, int n_in,
                              void* d_out, int out_size)
{
    const float* query = (const float*)d_in[0];
    const float* key   = (const float*)d_in[1];
    const float* value = (const float*)d_in[2];
    const float* Wq    = (const float*)d_in[3];
    const float* bq    = (const float*)d_in[4];
    const float* Wk    = (const float*)d_in[5];
    /* bk = d_in[6] : softmax-invariant, dropped */
    const float* Wv    = (const float*)d_in[7];
    const float* bv    = (const float*)d_in[8];
    const float* Wo    = (const float*)d_in[9];
    const float* bo    = (const float*)d_in[10];
    float* out = (float*)d_out;

    float *gq, *gqk, *glog, *gctx, *gattn;
    cudaGetSymbolAddress((void**)&gq,    g_q);
    cudaGetSymbolAddress((void**)&gqk,   g_qk);
    cudaGetSymbolAddress((void**)&glog,  g_logits);
    cudaGetSymbolAddress((void**)&gctx,  g_ctx);
    cudaGetSymbolAddress((void**)&gattn, g_attn);

    cudaFuncSetAttribute(gemm_frag<0>, cudaFuncAttributeMaxDynamicSharedMemorySize, FG_SMEM);
    cudaFuncSetAttribute(gemm_frag<1>, cudaFuncAttributeMaxDynamicSharedMemorySize, FG_SMEM);

    // #1  K1: q = query @ Wq^T + bq
    gemm_nt<64,64,16,4,4,true><<<dim3(HID/64, (BB*LQ)/64), 256>>>(
        query, Wq, bq, gq, HID, HID, HID, HID);

    // #2  K2: qk = scale * q_h @ Wk_h
    qk_kernel<<<dim3(HID/128, BB*NHEAD), 128>>>(gq, Wk, gqk);

    // #3  K3: logits = qk @ key^T   [256 x 8192] per batch, K=1024
    gemm_frag<0><<<dim3(LK/FG_BN, 1, BB), 512, FG_SMEM>>>(
        gqk, key, glog, HID, HID, HID, LK,
        (long)RPB*HID, (long)LK*HID, (long)RPB*LK, 1);

    // #4,#5  K4: row softmax, split into two launches (so ncu -s5 -c1 captures K5)
    softmax_kernel<<<1024, 256>>>(glog);
    softmax_kernel<<<1024, 256>>>(glog + (size_t)1024*LK);

    // #6  K5: ctx = probs @ value   [256 x 1024] per batch, K=8192, split-K=4
    gemm_frag<1><<<dim3(HID/FG_BN, 1, BB*4), 512, FG_SMEM>>>(
        glog, value, gctx, LK/4, LK, HID, HID,
        (long)RPB*LK, (long)LK*HID, (long)RPB*HID, 4);

    // #7  K6: attn = ctx @ Wv_h^T + bv
    attnv_kernel<<<BB*NHEAD, 256>>>(gctx, Wv, bv, gattn);

    // #8  K7: out = attn @ Wo^T + bo
    gemm_nt<64,64,16,4,4,true><<<dim3(HID/64, (BB*LQ)/64), 256>>>(
        gattn, Wo, bo, out, HID, HID, HID, HID);
}

// round 5
// speedup vs baseline: 1.3457x; 1.3457x over previous
#include <cuda_runtime.h>
#include <cuda_fp16.h>
#include <cstdint>
#include <math.h>

#define HID   1024
#define NHEAD 16
#define HDIM  64
#define BB    8
#define LQ    16
#define LK    8192
#define RPB   (NHEAD*LQ)   /* 256 rows per batch */

// ---------------- scratch ----------------
__device__ float g_q[BB*LQ*HID];
__device__ float g_qk[BB*RPB*HID];
__device__ float g_logits[(size_t)BB*RPB*LK];
__device__ float g_ctx[2*BB*RPB*HID];
__device__ float g_attn[BB*LQ*HID];

// =====================================================================
// f16 m16n8k16 mma (fp32 accumulate)
// =====================================================================
__device__ __forceinline__ void mma_f16(float c[4], const unsigned a[4], const unsigned b[2]) {
    asm("mma.sync.aligned.m16n8k16.row.col.f32.f16.f16.f32 "
        "{%0,%1,%2,%3}, {%4,%5,%6,%7}, {%8,%9}, {%0,%1,%2,%3};"
        : "+f"(c[0]), "+f"(c[1]), "+f"(c[2]), "+f"(c[3])
        : "r"(a[0]), "r"(a[1]), "r"(a[2]), "r"(a[3]), "r"(b[0]), "r"(b[1]));
}
__device__ __forceinline__ unsigned f2h2(float x, float y) {
    __half2 h = __floats2half2_rn(x, y);
    return *reinterpret_cast<unsigned*>(&h);
}

// =====================================================================
// fp16 tensor-core GEMM, BM=256 (full M), BN=64, BK=16, 256 threads.
// 8 warps (4m x 2n), warp tile 64x32. Double-buffered SMEM, 1 sync/chunk.
// SMEM layout (32-bit words = half2):
//   As[m][k2]  stride SA=12  (8 data half2 + 4 pad)  -> conflict-free frags
//   Bs NT [n][k2] stride 12 ; Bs NN [k2][n] stride 68
// LAYB=0 (NT): B[n*ldb+k] (logits = qk @ key^T)
// LAYB=1 (NN): B[k*ldb+n] (ctx = probs @ value)
// grid.z = batch*ksplit; each z writes its own C slab.
// =====================================================================
#define SA 12
#define SBNN 68

template<int LAYB>
__global__ void __launch_bounds__(256, 2)
gemm_h(const float* __restrict__ A, const float* __restrict__ B,
       float* __restrict__ C, int Kpart, int lda, int ldb, int ldc,
       long sA_, long sB_, long sC_, int ksplit)
{
    constexpr int BM = 256, BN = 64, BK = 16;
    constexpr int BSZ = (LAYB == 0) ? BN * SA : (BK/2) * SBNN;

    __shared__ __align__(16) unsigned As[2][BM * SA];
    __shared__ __align__(16) unsigned Bs[2][BSZ];

    const int tid  = threadIdx.x;
    const int w    = tid >> 5;
    const int lane = tid & 31;
    const int g    = lane >> 2;
    const int tg   = lane & 3;
    const int wm   = (w >> 1) * 64;
    const int wn   = (w & 1) * 32;

    const int batch = blockIdx.z / ksplit;
    const int part  = blockIdx.z % ksplit;
    const int bn    = blockIdx.x * BN;
    A += (long)batch*sA_ + (long)part*Kpart;
    if (LAYB == 0) B += (long)batch*sB_ + (long)part*Kpart;
    else           B += (long)batch*sB_ + (long)part*Kpart*ldb;
    C += (long)blockIdx.z*sC_;

    // staging coords
    const int a_row  = tid;                 // one A row per thread, 16 floats
    const int bnt_row = tid >> 2;           // NT: 64 rows x 4 thr
    const int bnt_f4  = tid & 3;            // float4 index (k)
    const int bnn_k   = tid >> 4;           // NN: 16 k-rows x 16 thr
    const int bnn_n0  = (tid & 15) * 4;

    float acc[4][4][4];
#pragma unroll
    for (int i = 0; i < 4; i++)
#pragma unroll
        for (int j = 0; j < 4; j++)
#pragma unroll
            for (int r = 0; r < 4; r++) acc[i][j][r] = 0.f;

    const int chunks = Kpart / BK;
    float4 ra[4], rb;

    auto load_regs = [&](int c) {
        const int k0 = c * BK;
#pragma unroll
        for (int j = 0; j < 4; j++)
            ra[j] = *reinterpret_cast<const float4*>(&A[(long)a_row*lda + k0 + j*4]);
        if (LAYB == 0)
            rb = *reinterpret_cast<const float4*>(&B[(long)(bn + bnt_row)*ldb + k0 + bnt_f4*4]);
        else
            rb = *reinterpret_cast<const float4*>(&B[(long)(k0 + bnn_k)*ldb + bn + bnn_n0]);
    };
    auto stage = [&](int buf) {
        // A: 16 floats -> 8 half2 -> 2 STS.128
        uint4 v0, v1;
        v0.x = f2h2(ra[0].x, ra[0].y); v0.y = f2h2(ra[0].z, ra[0].w);
        v0.z = f2h2(ra[1].x, ra[1].y); v0.w = f2h2(ra[1].z, ra[1].w);
        v1.x = f2h2(ra[2].x, ra[2].y); v1.y = f2h2(ra[2].z, ra[2].w);
        v1.z = f2h2(ra[3].x, ra[3].y); v1.w = f2h2(ra[3].z, ra[3].w);
        *reinterpret_cast<uint4*>(&As[buf][a_row*SA])     = v0;
        *reinterpret_cast<uint4*>(&As[buf][a_row*SA + 4]) = v1;
        if (LAYB == 0) {
            uint2 b2;
            b2.x = f2h2(rb.x, rb.y); b2.y = f2h2(rb.z, rb.w);
            *reinterpret_cast<uint2*>(&Bs[buf][bnt_row*SA + bnt_f4*2]) = b2;
        } else {
            // value row k: 4 n-values -> halves of Bs[k/2][n]
            __half* hp = reinterpret_cast<__half*>(&Bs[buf][(bnn_k >> 1)*SBNN + bnn_n0]);
            const int hoff = bnn_k & 1;
            hp[0*2 + hoff] = __float2half_rn(rb.x);
            hp[1*2 + hoff] = __float2half_rn(rb.y);
            hp[2*2 + hoff] = __float2half_rn(rb.z);
            hp[3*2 + hoff] = __float2half_rn(rb.w);
        }
    };
    auto compute = [&](int buf) {
        const unsigned* ab = As[buf];
        const unsigned* bb = Bs[buf];
        unsigned af[4][4], bf[4][2];
#pragma unroll
        for (int i = 0; i < 4; i++) {
            const int mb = wm + i*16;
            af[i][0] = ab[(mb + g    )*SA + tg    ];
            af[i][1] = ab[(mb + g + 8)*SA + tg    ];
            af[i][2] = ab[(mb + g    )*SA + tg + 4];
            af[i][3] = ab[(mb + g + 8)*SA + tg + 4];
        }
#pragma unroll
        for (int j = 0; j < 4; j++) {
            const int nb = wn + j*8;
            if (LAYB == 0) {
                bf[j][0] = bb[(nb + g)*SA + tg    ];
                bf[j][1] = bb[(nb + g)*SA + tg + 4];
            } else {
                bf[j][0] = bb[(tg    )*SBNN + nb + g];
                bf[j][1] = bb[(tg + 4)*SBNN + nb + g];
            }
        }
#pragma unroll
        for (int i = 0; i < 4; i++)
#pragma unroll
            for (int j = 0; j < 4; j++)
                mma_f16(acc[i][j], af[i], bf[j]);
    };

    load_regs(0);
    stage(0);
    if (chunks > 1) load_regs(1);
    __syncthreads();
    for (int c = 0; c < chunks; c++) {
        if (c + 1 < chunks) {
            stage((c + 1) & 1);
            if (c + 2 < chunks) load_regs(c + 2);
        }
        compute(c & 1);
        __syncthreads();
    }

    // epilogue
#pragma unroll
    for (int i = 0; i < 4; i++) {
        const int row0 = wm + i*16 + g;
#pragma unroll
        for (int j = 0; j < 4; j++) {
            const int col = bn + wn + j*8 + 2*tg;
            *reinterpret_cast<float2*>(&C[(long)row0*ldc + col]) =
                make_float2(acc[i][j][0], acc[i][j][1]);
            *reinterpret_cast<float2*>(&C[(long)(row0 + 8)*ldc + col]) =
                make_float2(acc[i][j][2], acc[i][j][3]);
        }
    }
}

// =====================================================================
// fp32 FFMA NT GEMM for small projections K1/K7
// =====================================================================
template<int BM,int BN,int BK,int TM,int TN,bool BIAS>
__global__ void __launch_bounds__((BM/TM)*(BN/TN))
gemm_nt(const float* __restrict__ A, const float* __restrict__ Bm,
        const float* __restrict__ bias, float* __restrict__ C,
        int K, int lda, int ldb, int ldc)
{
    constexpr int TX = BN/TN, TY = BM/TM, NT = TX*TY;
    const int tid = threadIdx.x;
    const int tx  = tid % TX, ty = tid / TX;
    const int bm  = blockIdx.y*BM, bn = blockIdx.x*BN;

    __shared__ float As[BK][BM+4];
    __shared__ float Bs[BK][BN+4];

    float acc[TM][TN];
#pragma unroll
    for (int i=0;i<TM;i++)
#pragma unroll
        for (int j=0;j<TN;j++) acc[i][j] = 0.f;

    for (int k0 = 0; k0 < K; k0 += BK) {
#pragma unroll
        for (int i = tid; i < BM*BK/4; i += NT) {
            int m  = i / (BK/4);
            int k4 = (i % (BK/4)) * 4;
            float4 v = *reinterpret_cast<const float4*>(&A[(long)(bm+m)*lda + k0 + k4]);
            As[k4+0][m] = v.x; As[k4+1][m] = v.y; As[k4+2][m] = v.z; As[k4+3][m] = v.w;
        }
#pragma unroll
        for (int i = tid; i < BN*BK/4; i += NT) {
            int n  = i / (BK/4);
            int k4 = (i % (BK/4)) * 4;
            float4 v = *reinterpret_cast<const float4*>(&Bm[(long)(bn+n)*ldb + k0 + k4]);
            Bs[k4+0][n] = v.x; Bs[k4+1][n] = v.y; Bs[k4+2][n] = v.z; Bs[k4+3][n] = v.w;
        }
        __syncthreads();
#pragma unroll
        for (int k = 0; k < BK; k++) {
            float af[TM], bf[TN];
#pragma unroll
            for (int i=0;i<TM;i+=4)
                *reinterpret_cast<float4*>(&af[i]) =
                    *reinterpret_cast<const float4*>(&As[k][ty*TM + i]);
#pragma unroll
            for (int j=0;j<TN;j+=4)
                *reinterpret_cast<float4*>(&bf[j]) =
                    *reinterpret_cast<const float4*>(&Bs[k][tx*TN + j]);
#pragma unroll
            for (int i=0;i<TM;i++)
#pragma unroll
                for (int j=0;j<TN;j++)
                    acc[i][j] = fmaf(af[i], bf[j], acc[i][j]);
        }
        __syncthreads();
    }

#pragma unroll
    for (int i=0;i<TM;i++) {
        const int m = bm + ty*TM + i;
        float* crow = &C[(long)m*ldc + bn + tx*TN];
#pragma unroll
        for (int j=0;j<TN;j+=4) {
            float4 v;
            v.x = acc[i][j+0]; v.y = acc[i][j+1]; v.z = acc[i][j+2]; v.w = acc[i][j+3];
            if (BIAS) {
                const float* bp = &bias[bn + tx*TN + j];
                v.x += bp[0]; v.y += bp[1]; v.z += bp[2]; v.w += bp[3];
            }
            *reinterpret_cast<float4*>(&crow[j]) = v;
        }
    }
}

// =====================================================================
// qk = scale * q_h @ Wk_h
// =====================================================================
__global__ void qk_kernel(const float* __restrict__ q,
                          const float* __restrict__ Wk,
                          float* __restrict__ qk)
{
    const int bh = blockIdx.y;
    const int b = bh >> 4, h = bh & 15;
    const int col = blockIdx.x*128 + threadIdx.x;
    __shared__ float a[LQ][HDIM];
    for (int i = threadIdx.x; i < LQ*HDIM; i += 128) {
        int qq = i >> 6, e = i & 63;
        a[qq][e] = q[(b*LQ + qq)*HID + h*HDIM + e];
    }
    __syncthreads();
    float acc[LQ];
#pragma unroll
    for (int i=0;i<LQ;i++) acc[i] = 0.f;
#pragma unroll 8
    for (int e = 0; e < HDIM; e++) {
        float w = Wk[(h*HDIM + e)*HID + col];
#pragma unroll
        for (int qq = 0; qq < LQ; qq++) acc[qq] = fmaf(a[qq][e], w, acc[qq]);
    }
    const float scale = 0.125f;
#pragma unroll
    for (int qq = 0; qq < LQ; qq++)
        qk[((long)b*RPB + h*LQ + qq)*HID + col] = acc[qq] * scale;
}

// =====================================================================
// In-place row softmax over LK=8192
// =====================================================================
__global__ void softmax_kernel(float* __restrict__ logits)
{
    const size_t row = blockIdx.x;
    float* p = logits + row * (size_t)LK;
    __shared__ float buf[LK];
    __shared__ float red[8];
    const int tid = threadIdx.x;
    const int lane = tid & 31, warp = tid >> 5;
    float4*       b4 = reinterpret_cast<float4*>(buf);
    const float4* p4 = reinterpret_cast<const float4*>(p);

    float mx = -3.0e38f;
    for (int i = tid; i < LK/4; i += 256) {
        float4 v = p4[i]; b4[i] = v;
        mx = fmaxf(mx, fmaxf(fmaxf(v.x,v.y), fmaxf(v.z,v.w)));
    }
#pragma unroll
    for (int o=16;o;o>>=1) mx = fmaxf(mx, __shfl_xor_sync(0xffffffffu, mx, o));
    if (lane==0) red[warp] = mx;
    __syncthreads();
    mx = red[0];
#pragma unroll
    for (int w=1;w<8;w++) mx = fmaxf(mx, red[w]);

    float sum = 0.f;
    for (int i = tid; i < LK/4; i += 256) {
        float4 v = b4[i];
        v.x = expf(v.x - mx); v.y = expf(v.y - mx);
        v.z = expf(v.z - mx); v.w = expf(v.w - mx);
        b4[i] = v;
        sum += (v.x + v.y) + (v.z + v.w);
    }
#pragma unroll
    for (int o=16;o;o>>=1) sum += __shfl_xor_sync(0xffffffffu, sum, o);
    __syncthreads();
    if (lane==0) red[warp] = sum;
    __syncthreads();
    sum = 0.f;
#pragma unroll
    for (int w=0;w<8;w++) sum += red[w];
    const float inv = 1.f / sum;

    float4* o4 = reinterpret_cast<float4*>(p);
    for (int i = tid; i < LK/4; i += 256) {
        float4 v = b4[i];
        v.x *= inv; v.y *= inv; v.z *= inv; v.w *= inv;
        o4[i] = v;
    }
}

// =====================================================================
// attn = (ctx slab A + slab B) @ Wv_h^T + bv, per (b,h)
// =====================================================================
__global__ void attnv_kernel(const float* __restrict__ ctx,
                             const float* __restrict__ Wv,
                             const float* __restrict__ bv,
                             float* __restrict__ attn)
{
    const int bh = blockIdx.x;
    const int b = bh >> 4, h = bh & 15;
    const int t = threadIdx.x;
    const int d = t & 63, qg = t >> 6;
    __shared__ float cs[LQ][129];
    __shared__ float ws[HDIM][129];
    float acc[4] = {0.f,0.f,0.f,0.f};

    const long rowA = (long)(b*2    )*RPB + h*LQ;
    const long rowB = (long)(b*2 + 1)*RPB + h*LQ;

    for (int e0 = 0; e0 < HID; e0 += 128) {
        __syncthreads();
        for (int i = t; i < LQ*128; i += 256) {
            int qq = i >> 7, e = i & 127;
            cs[qq][e] = ctx[(rowA + qq)*HID + e0 + e] + ctx[(rowB + qq)*HID + e0 + e];
        }
        for (int i = t; i < HDIM*128; i += 256) {
            int dd = i >> 7, e = i & 127;
            ws[dd][e] = Wv[(long)(h*HDIM + dd)*HID + e0 + e];
        }
        __syncthreads();
#pragma unroll 4
        for (int e = 0; e < 128; e++) {
            float wv = ws[d][e];
#pragma unroll
            for (int j = 0; j < 4; j++)
                acc[j] = fmaf(cs[qg*4 + j][e], wv, acc[j]);
        }
    }
    const float bvv = bv[h*HDIM + d];
#pragma unroll
    for (int j = 0; j < 4; j++)
        attn[(long)(b*LQ + qg*4 + j)*HID + h*HDIM + d] = acc[j] + bvv;
}

// =====================================================================
// launch
// =====================================================================
extern "C" void kernel_launch(void* const* d_in, const int* in_sizes, int n_in,
                              void* d_out, int out_size)
{
    const float* query = (const float*)d_in[0];
    const float* key   = (const float*)d_in[1];
    const float* value = (const float*)d_in[2];
    const float* Wq    = (const float*)d_in[3];
    const float* bq    = (const float*)d_in[4];
    const float* Wk    = (const float*)d_in[5];
    /* bk = d_in[6] : softmax-invariant, dropped */
    const float* Wv    = (const float*)d_in[7];
    const float* bv    = (const float*)d_in[8];
    const float* Wo    = (const float*)d_in[9];
    const float* bo    = (const float*)d_in[10];
    float* out = (float*)d_out;

    float *gq, *gqk, *glog, *gctx, *gattn;
    cudaGetSymbolAddress((void**)&gq,    g_q);
    cudaGetSymbolAddress((void**)&gqk,   g_qk);
    cudaGetSymbolAddress((void**)&glog,  g_logits);
    cudaGetSymbolAddress((void**)&gctx,  g_ctx);
    cudaGetSymbolAddress((void**)&gattn, g_attn);

    // #1  K1: q = query @ Wq^T + bq
    gemm_nt<64,64,16,4,4,true><<<dim3(HID/64, (BB*LQ)/64), 256>>>(
        query, Wq, bq, gq, HID, HID, HID, HID);

    // #2  K2: qk = scale * q_h @ Wk_h
    qk_kernel<<<dim3(HID/128, BB*NHEAD), 128>>>(gq, Wk, gqk);

    // #3  K3: logits = qk @ key^T   [256 x 8192] per batch, K=1024  (f16 TC)
    gemm_h<0><<<dim3(LK/64, 1, BB), 256>>>(
        gqk, key, glog, HID, HID, HID, LK,
        (long)RPB*HID, (long)LK*HID, (long)RPB*LK, 1);

    // #4,#5  K4: row softmax (two launches so ncu -s5 -c1 lands on K5)
    softmax_kernel<<<1024, 256>>>(glog);
    softmax_kernel<<<1024, 256>>>(glog + (size_t)1024*LK);

    // #6  K5: ctx = probs @ value   [256 x 1024] per batch, K=8192, split-K=2  (f16 TC)
    gemm_h<1><<<dim3(HID/64, 1, BB*2), 256>>>(
        glog, value, gctx, LK/2, LK, HID, HID,
        (long)RPB*LK, (long)LK*HID, (long)RPB*HID, 2);

    // #7  K6: attn = ctx @ Wv_h^T + bv
    attnv_kernel<<<BB*NHEAD, 256>>>(gctx, Wv, bv, gattn);

    // #8  K7: out = attn @ Wo^T + bo
    gemm_nt<64,64,16,4,4,true><<<dim3(HID/64, (BB*LQ)/64), 256>>>(
        gattn, Wo, bo, out, HID, HID, HID, HID);
}

// round 6
// speedup vs baseline: 2.1875x; 1.6256x over previous
#include <cuda_runtime.h>
#include <cuda_fp16.h>
#include <cstdint>
#include <math.h>

#define HID   1024
#define NHEAD 16
#define HDIM  64
#define BB    8
#define LQ    16
#define LK    8192
#define RPB   (NHEAD*LQ)   /* 256 rows per batch */

// ---------------- scratch ----------------
__device__ float  g_q[BB*LQ*HID];
__device__ __half g_qkh[BB*RPB*HID];
__device__ float  g_logits[(size_t)BB*RPB*LK];
__device__ __half g_ph[(size_t)BB*RPB*LK];
__device__ __half g_kh[(size_t)BB*LK*HID];
__device__ __half g_vth[(size_t)BB*HID*LK];
__device__ float  g_ctx[4*BB*RPB*HID];
__device__ float  g_attn[BB*LQ*HID];

// =====================================================================
// asm helpers
// =====================================================================
__device__ __forceinline__ uint32_t smem_u32(const void* p) {
    uint32_t a;
    asm("{ .reg .u64 t; cvta.to.shared.u64 t, %1; cvt.u32.u64 %0, t; }" : "=r"(a) : "l"(p));
    return a;
}
#define CP_ASYNC16(dst, src) \
    asm volatile("cp.async.cg.shared.global [%0], [%1], 16;" :: "r"(dst), "l"(src) : "memory")
#define CP_COMMIT()  asm volatile("cp.async.commit_group;" ::: "memory")
#define CP_WAIT2()   asm volatile("cp.async.wait_group 2;" ::: "memory")
#define LDSM4(r, addr) \
    asm volatile("ldmatrix.sync.aligned.m8n8.x4.shared.b16 {%0,%1,%2,%3}, [%4];" \
        : "=r"((r)[0]), "=r"((r)[1]), "=r"((r)[2]), "=r"((r)[3]) : "r"(addr))

__device__ __forceinline__ void mma_f16(float c[4], const unsigned a[4], const unsigned b[2]) {
    asm("mma.sync.aligned.m16n8k16.row.col.f32.f16.f16.f32 "
        "{%0,%1,%2,%3}, {%4,%5,%6,%7}, {%8,%9}, {%0,%1,%2,%3};"
        : "+f"(c[0]), "+f"(c[1]), "+f"(c[2]), "+f"(c[3])
        : "r"(a[0]), "r"(a[1]), "r"(a[2]), "r"(a[3]), "r"(b[0]), "r"(b[1]));
}

// =====================================================================
// gemm_ha: half NT GEMM, fp32 out.  C[m][n] = sum_k A[m][k]*B[n][k]
// BM=256, BN=64, BK=32, 256 thr (8 warps = 4m x 2n, warp tile 64x32).
// 4-stage cp.async pipeline; ldmatrix fragment loads.
// SMEM per stage: A 256 rows x 64B, B 64 rows x 64B at +16384; row layout:
//   addr(row, kc) = row*64 + ((kc ^ ((row>>1)&3))<<4), kc = k8-chunk 0..3
// grid.z = batch*ksplit; slab C per z.
// =====================================================================
#define ST_BYTES 20480
#define B_OFF    16384
#define GH_SMEM  (4*ST_BYTES)

__global__ void __launch_bounds__(256, 2)
gemm_ha(const __half* __restrict__ A, const __half* __restrict__ B,
        float* __restrict__ C, int Kpart, int lda, int ldb, int ldc,
        long sA, long sB, long sC, int ksplit)
{
    extern __shared__ __align__(16) char smem[];
    const uint32_t sb = smem_u32(smem);

    const int tid  = threadIdx.x;
    const int w    = tid >> 5;
    const int lane = tid & 31;
    const int g    = lane >> 2;
    const int tg   = lane & 3;
    const int wm   = (w >> 1) * 64;
    const int wn   = (w & 1) * 32;

    const int batch = blockIdx.z / ksplit;
    const int part  = blockIdx.z % ksplit;
    const int bn    = blockIdx.x * 64;
    A += (long)batch*sA + (long)part*Kpart;
    B += (long)batch*sB + (long)part*Kpart;
    C += (long)blockIdx.z*sC;

    // ---- cp.async coordinates ----
    const int kc = tid & 3;          // 16B chunk in k (k8)
    const int ar = tid >> 2;         // 0..63
    const __half* aP = A + (long)ar*lda + kc*8;          // rows ar + 64*i
    const __half* bP = B + (long)(bn + ar)*ldb + kc*8;
    const long aStride64 = (long)64*lda;
    const uint32_t aDst0 = (uint32_t)(ar*64 + ((kc ^ ((ar>>1)&3)) << 4));
    const uint32_t bDst  = (uint32_t)(B_OFF + ar*64 + ((kc ^ ((ar>>1)&3)) << 4));

    // ---- ldmatrix offsets (within stage) ----
    // A tiles: m = wm + mt*16 + (lane&7) + ((lane>>3)&1)*8 ; kcc = 2s + (lane>>4)
    // swizzle sel invariant under mt*16, so only s matters: store 2 bases.
    uint32_t aLd[2], bLd[2];
    {
        const int mrow = wm + (lane & 7) + ((lane >> 3) & 1) * 8;
        const int msel = (mrow >> 1) & 3;
#pragma unroll
        for (int s = 0; s < 2; s++) {
            const int kcc = 2*s + (lane >> 4);
            aLd[s] = (uint32_t)(mrow*64 + ((kcc ^ msel) << 4));
        }
        const int nrow = wn + (lane & 7) + ((lane >> 4) << 3);
        const int nsel = (nrow >> 1) & 3;
#pragma unroll
        for (int s = 0; s < 2; s++) {
            const int kcc = 2*s + ((lane >> 3) & 1);
            bLd[s] = (uint32_t)(B_OFF + nrow*64 + ((kcc ^ nsel) << 4));
        }
    }

    float acc[4][4][4];
#pragma unroll
    for (int i = 0; i < 4; i++)
#pragma unroll
        for (int j = 0; j < 4; j++)
#pragma unroll
            for (int r = 0; r < 4; r++) acc[i][j][r] = 0.f;

    const int chunks = Kpart / 32;

    // issue one stage of copies
    auto issue = [&](int slot) {
        const uint32_t base = sb + slot*ST_BYTES;
#pragma unroll
        for (int i = 0; i < 4; i++)
            CP_ASYNC16(base + aDst0 + i*4096, aP + i*aStride64);
        CP_ASYNC16(base + bDst, bP);
        aP += 32; bP += 32;
    };

    issue(0); CP_COMMIT();
    issue(1); CP_COMMIT();
    issue(2); CP_COMMIT();

    for (int c = 0; c < chunks; c++) {
        CP_WAIT2();
        __syncthreads();
        if (c + 3 < chunks) issue((c + 3) & 3);
        CP_COMMIT();

        const uint32_t base = sb + (c & 3)*ST_BYTES;
#pragma unroll
        for (int s = 0; s < 2; s++) {
            unsigned af[4][4], bq[8];
#pragma unroll
            for (int mt = 0; mt < 4; mt++)
                LDSM4(af[mt], base + aLd[s] + mt*1024);
            LDSM4(bq + 0, base + bLd[s]);
            LDSM4(bq + 4, base + bLd[s] + 1024);
#pragma unroll
            for (int i = 0; i < 4; i++)
#pragma unroll
                for (int j = 0; j < 4; j++)
                    mma_f16(acc[i][j], af[i], &bq[j*2]);
        }
    }

    // epilogue
#pragma unroll
    for (int i = 0; i < 4; i++) {
        const int row0 = wm + i*16 + g;
#pragma unroll
        for (int j = 0; j < 4; j++) {
            const int col = bn + wn + j*8 + 2*tg;
            *reinterpret_cast<float2*>(&C[(long)row0*ldc + col]) =
                make_float2(acc[i][j][0], acc[i][j][1]);
            *reinterpret_cast<float2*>(&C[(long)(row0 + 8)*ldc + col]) =
                make_float2(acc[i][j][2], acc[i][j][3]);
        }
    }
}

// =====================================================================
// key -> half (same layout), grid-stride
// =====================================================================
__global__ void tohalf_kernel(const float4* __restrict__ src, uint2* __restrict__ dst, int n4)
{
    for (int i = blockIdx.x*blockDim.x + threadIdx.x; i < n4; i += gridDim.x*blockDim.x) {
        float4 v = src[i];
        __half2 a = __floats2half2_rn(v.x, v.y);
        __half2 b = __floats2half2_rn(v.z, v.w);
        uint2 o;
        o.x = *reinterpret_cast<unsigned*>(&a);
        o.y = *reinterpret_cast<unsigned*>(&b);
        dst[i] = o;
    }
}

// =====================================================================
// value [b][8192][1024] f32 -> g_vth [b][1024][8192] half
// =====================================================================
__global__ void vtrans_kernel(const float* __restrict__ src, __half* __restrict__ dst)
{
    __shared__ float tile[32][33];
    const int b  = blockIdx.z;
    const int k0 = blockIdx.x * 32;
    const int n0 = blockIdx.y * 32;
    const float* s = src + (size_t)b * LK * HID;
    __half* d      = dst + (size_t)b * HID * LK;
    const int x = threadIdx.x, y = threadIdx.y;
#pragma unroll
    for (int j = 0; j < 32; j += 8)
        tile[y+j][x] = s[(size_t)(k0 + y + j) * HID + n0 + x];
    __syncthreads();
#pragma unroll
    for (int j = 0; j < 32; j += 8)
        d[(size_t)(n0 + y + j) * LK + k0 + x] = __float2half_rn(tile[x][y+j]);
}

// =====================================================================
// fp32 FFMA NT GEMM for small projections K1/K7
// =====================================================================
template<int BM,int BN,int BK,int TM,int TN,bool BIAS>
__global__ void __launch_bounds__((BM/TM)*(BN/TN))
gemm_nt(const float* __restrict__ A, const float* __restrict__ Bm,
        const float* __restrict__ bias, float* __restrict__ C,
        int K, int lda, int ldb, int ldc)
{
    constexpr int TX = BN/TN, TY = BM/TM, NT = TX*TY;
    const int tid = threadIdx.x;
    const int tx  = tid % TX, ty = tid / TX;
    const int bm  = blockIdx.y*BM, bn = blockIdx.x*BN;

    __shared__ float As[BK][BM+4];
    __shared__ float Bs[BK][BN+4];

    float acc[TM][TN];
#pragma unroll
    for (int i=0;i<TM;i++)
#pragma unroll
        for (int j=0;j<TN;j++) acc[i][j] = 0.f;

    for (int k0 = 0; k0 < K; k0 += BK) {
#pragma unroll
        for (int i = tid; i < BM*BK/4; i += NT) {
            int m  = i / (BK/4);
            int k4 = (i % (BK/4)) * 4;
            float4 v = *reinterpret_cast<const float4*>(&A[(long)(bm+m)*lda + k0 + k4]);
            As[k4+0][m] = v.x; As[k4+1][m] = v.y; As[k4+2][m] = v.z; As[k4+3][m] = v.w;
        }
#pragma unroll
        for (int i = tid; i < BN*BK/4; i += NT) {
            int n  = i / (BK/4);
            int k4 = (i % (BK/4)) * 4;
            float4 v = *reinterpret_cast<const float4*>(&Bm[(long)(bn+n)*ldb + k0 + k4]);
            Bs[k4+0][n] = v.x; Bs[k4+1][n] = v.y; Bs[k4+2][n] = v.z; Bs[k4+3][n] = v.w;
        }
        __syncthreads();
#pragma unroll
        for (int k = 0; k < BK; k++) {
            float af[TM], bf[TN];
#pragma unroll
            for (int i=0;i<TM;i+=4)
                *reinterpret_cast<float4*>(&af[i]) =
                    *reinterpret_cast<const float4*>(&As[k][ty*TM + i]);
#pragma unroll
            for (int j=0;j<TN;j+=4)
                *reinterpret_cast<float4*>(&bf[j]) =
                    *reinterpret_cast<const float4*>(&Bs[k][tx*TN + j]);
#pragma unroll
            for (int i=0;i<TM;i++)
#pragma unroll
                for (int j=0;j<TN;j++)
                    acc[i][j] = fmaf(af[i], bf[j], acc[i][j]);
        }
        __syncthreads();
    }

#pragma unroll
    for (int i=0;i<TM;i++) {
        const int m = bm + ty*TM + i;
        float* crow = &C[(long)m*ldc + bn + tx*TN];
#pragma unroll
        for (int j=0;j<TN;j+=4) {
            float4 v;
            v.x = acc[i][j+0]; v.y = acc[i][j+1]; v.z = acc[i][j+2]; v.w = acc[i][j+3];
            if (BIAS) {
                const float* bp = &bias[bn + tx*TN + j];
                v.x += bp[0]; v.y += bp[1]; v.z += bp[2]; v.w += bp[3];
            }
            *reinterpret_cast<float4*>(&crow[j]) = v;
        }
    }
}

// =====================================================================
// qk = scale * q_h @ Wk_h  -> half output
// =====================================================================
__global__ void qk_kernel(const float* __restrict__ q,
                          const float* __restrict__ Wk,
                          __half* __restrict__ qkh)
{
    const int bh = blockIdx.y;
    const int b = bh >> 4, h = bh & 15;
    const int col = blockIdx.x*128 + threadIdx.x;
    __shared__ float a[LQ][HDIM];
    for (int i = threadIdx.x; i < LQ*HDIM; i += 128) {
        int qq = i >> 6, e = i & 63;
        a[qq][e] = q[(b*LQ + qq)*HID + h*HDIM + e];
    }
    __syncthreads();
    float acc[LQ];
#pragma unroll
    for (int i=0;i<LQ;i++) acc[i] = 0.f;
#pragma unroll 8
    for (int e = 0; e < HDIM; e++) {
        float w = Wk[(h*HDIM + e)*HID + col];
#pragma unroll
        for (int qq = 0; qq < LQ; qq++) acc[qq] = fmaf(a[qq][e], w, acc[qq]);
    }
    const float scale = 0.125f;
#pragma unroll
    for (int qq = 0; qq < LQ; qq++)
        qkh[((long)b*RPB + h*LQ + qq)*HID + col] = __float2half_rn(acc[qq] * scale);
}

// =====================================================================
// softmax: fp32 logits in, half probs out
// =====================================================================
__global__ void softmax_kernel(const float* __restrict__ logits, __half* __restrict__ probs)
{
    const size_t row = blockIdx.x;
    const float* p = logits + row * (size_t)LK;
    __half2* o2 = reinterpret_cast<__half2*>(probs + row * (size_t)LK);
    __shared__ float buf[LK];
    __shared__ float red[8];
    const int tid = threadIdx.x;
    const int lane = tid & 31, warp = tid >> 5;
    float4*       b4 = reinterpret_cast<float4*>(buf);
    const float4* p4 = reinterpret_cast<const float4*>(p);

    float mx = -3.0e38f;
    for (int i = tid; i < LK/4; i += 256) {
        float4 v = p4[i]; b4[i] = v;
        mx = fmaxf(mx, fmaxf(fmaxf(v.x,v.y), fmaxf(v.z,v.w)));
    }
#pragma unroll
    for (int o=16;o;o>>=1) mx = fmaxf(mx, __shfl_xor_sync(0xffffffffu, mx, o));
    if (lane==0) red[warp] = mx;
    __syncthreads();
    mx = red[0];
#pragma unroll
    for (int w=1;w<8;w++) mx = fmaxf(mx, red[w]);

    float sum = 0.f;
    for (int i = tid; i < LK/4; i += 256) {
        float4 v = b4[i];
        v.x = expf(v.x - mx); v.y = expf(v.y - mx);
        v.z = expf(v.z - mx); v.w = expf(v.w - mx);
        b4[i] = v;
        sum += (v.x + v.y) + (v.z + v.w);
    }
#pragma unroll
    for (int o=16;o;o>>=1) sum += __shfl_xor_sync(0xffffffffu, sum, o);
    __syncthreads();
    if (lane==0) red[warp] = sum;
    __syncthreads();
    sum = 0.f;
#pragma unroll
    for (int w=0;w<8;w++) sum += red[w];
    const float inv = 1.f / sum;

    for (int i = tid; i < LK/4; i += 256) {
        float4 v = b4[i];
        o2[2*i]   = __floats2half2_rn(v.x*inv, v.y*inv);
        o2[2*i+1] = __floats2half2_rn(v.z*inv, v.w*inv);
    }
}

// =====================================================================
// attn = (sum of 4 ctx slabs) @ Wv_h^T + bv, per (b,h)
// =====================================================================
__global__ void attnv_kernel(const float* __restrict__ ctx,
                             const float* __restrict__ Wv,
                             const float* __restrict__ bv,
                             float* __restrict__ attn)
{
    const int bh = blockIdx.x;
    const int b = bh >> 4, h = bh & 15;
    const int t = threadIdx.x;
    const int d = t & 63, qg = t >> 6;
    __shared__ float cs[LQ][129];
    __shared__ float ws[HDIM][129];
    float acc[4] = {0.f,0.f,0.f,0.f};

    long row[4];
#pragma unroll
    for (int p = 0; p < 4; p++) row[p] = (long)(b*4 + p)*RPB + h*LQ;

    for (int e0 = 0; e0 < HID; e0 += 128) {
        __syncthreads();
        for (int i = t; i < LQ*128; i += 256) {
            int qq = i >> 7, e = i & 127;
            float v = 0.f;
#pragma unroll
            for (int p = 0; p < 4; p++) v += ctx[(row[p] + qq)*HID + e0 + e];
            cs[qq][e] = v;
        }
        for (int i = t; i < HDIM*128; i += 256) {
            int dd = i >> 7, e = i & 127;
            ws[dd][e] = Wv[(long)(h*HDIM + dd)*HID + e0 + e];
        }
        __syncthreads();
#pragma unroll 4
        for (int e = 0; e < 128; e++) {
            float wv = ws[d][e];
#pragma unroll
            for (int j = 0; j < 4; j++)
                acc[j] = fmaf(cs[qg*4 + j][e], wv, acc[j]);
        }
    }
    const float bvv = bv[h*HDIM + d];
#pragma unroll
    for (int j = 0; j < 4; j++)
        attn[(long)(b*LQ + qg*4 + j)*HID + h*HDIM + d] = acc[j] + bvv;
}

// =====================================================================
// launch
// =====================================================================
extern "C" void kernel_launch(void* const* d_in, const int* in_sizes, int n_in,
                              void* d_out, int out_size)
{
    const float* query = (const float*)d_in[0];
    const float* key   = (const float*)d_in[1];
    const float* value = (const float*)d_in[2];
    const float* Wq    = (const float*)d_in[3];
    const float* bq    = (const float*)d_in[4];
    const float* Wk    = (const float*)d_in[5];
    /* bk = d_in[6] : softmax-invariant, dropped */
    const float* Wv    = (const float*)d_in[7];
    const float* bv    = (const float*)d_in[8];
    const float* Wo    = (const float*)d_in[9];
    const float* bo    = (const float*)d_in[10];
    float* out = (float*)d_out;

    float *gq, *glog, *gctx, *gattn;
    __half *gqkh, *gph, *gkh, *gvth;
    cudaGetSymbolAddress((void**)&gq,    g_q);
    cudaGetSymbolAddress((void**)&gqkh,  g_qkh);
    cudaGetSymbolAddress((void**)&glog,  g_logits);
    cudaGetSymbolAddress((void**)&gph,   g_ph);
    cudaGetSymbolAddress((void**)&gkh,   g_kh);
    cudaGetSymbolAddress((void**)&gvth,  g_vth);
    cudaGetSymbolAddress((void**)&gctx,  g_ctx);
    cudaGetSymbolAddress((void**)&gattn, g_attn);

    cudaFuncSetAttribute(gemm_ha, cudaFuncAttributeMaxDynamicSharedMemorySize, GH_SMEM);

    // key -> half (same layout)
    tohalf_kernel<<<1024, 256>>>((const float4*)key, (uint2*)gkh, BB*LK*HID/4);
    // value -> half transposed [b][n][k]
    vtrans_kernel<<<dim3(LK/32, HID/32, BB), dim3(32,8)>>>(value, gvth);

    // K1: q = query @ Wq^T + bq (fp32)
    gemm_nt<64,64,16,4,4,true><<<dim3(HID/64, (BB*LQ)/64), 256>>>(
        query, Wq, bq, gq, HID, HID, HID, HID);

    // K2: qk = scale * q_h @ Wk_h -> half
    qk_kernel<<<dim3(HID/128, BB*NHEAD), 128>>>(gq, Wk, gqkh);

    // K3: logits = qkh @ kh^T  [256 x 8192] per batch, K=1024
    gemm_ha<<<dim3(LK/64, 1, BB), 256, GH_SMEM>>>(
        gqkh, gkh, glog, HID, HID, HID, LK,
        (long)RPB*HID, (long)LK*HID, (long)RPB*LK, 1);

    // K4: softmax fp32 -> half probs
    softmax_kernel<<<BB*RPB, 256>>>(glog, gph);

    // K5: ctx = probs @ value = ph @ vth^T  [256 x 1024] per batch, K=8192, split-K=4
    gemm_ha<<<dim3(HID/64, 1, BB*4), 256, GH_SMEM>>>(
        gph, gvth, gctx, LK/4, LK, LK, HID,
        (long)RPB*LK, (long)HID*LK, (long)RPB*HID, 4);

    // K6: attn = ctx @ Wv_h^T + bv
    attnv_kernel<<<BB*NHEAD, 256>>>(gctx, Wv, bv, gattn);

    // K7: out = attn @ Wo^T + bo
    gemm_nt<64,64,16,4,4,true><<<dim3(HID/64, (BB*LQ)/64), 256>>>(
        gattn, Wo, bo, out, HID, HID, HID, HID);
}

// round 7
// speedup vs baseline: 2.2922x; 1.0478x over previous
#include <cuda_runtime.h>
#include <cuda_fp16.h>
#include <cstdint>
#include <math.h>

#define HID   1024
#define NHEAD 16
#define HDIM  64
#define BB    8
#define LQ    16
#define LK    8192
#define RPB   (NHEAD*LQ)   /* 256 rows per batch */

// ---------------- scratch ----------------
__device__ float  g_q[BB*LQ*HID];
__device__ __half g_qkh[BB*RPB*HID];
__device__ float  g_logits[(size_t)BB*RPB*LK];
__device__ __half g_ph[(size_t)BB*RPB*LK];
__device__ __half g_kh[(size_t)BB*LK*HID];
__device__ __half g_vth[(size_t)BB*HID*LK];
__device__ float  g_ctx[4*BB*RPB*HID];
__device__ float  g_attn[BB*LQ*HID];

// =====================================================================
// asm helpers
// =====================================================================
__device__ __forceinline__ uint32_t smem_u32(const void* p) {
    uint32_t a;
    asm("{ .reg .u64 t; cvta.to.shared.u64 t, %1; cvt.u32.u64 %0, t; }" : "=r"(a) : "l"(p));
    return a;
}
#define CP_ASYNC16(dst, src) \
    asm volatile("cp.async.cg.shared.global [%0], [%1], 16;" :: "r"(dst), "l"(src) : "memory")
#define CP_COMMIT()  asm volatile("cp.async.commit_group;" ::: "memory")
#define CP_WAIT2()   asm volatile("cp.async.wait_group 2;" ::: "memory")
#define LDSM4(r, addr) \
    asm volatile("ldmatrix.sync.aligned.m8n8.x4.shared.b16 {%0,%1,%2,%3}, [%4];" \
        : "=r"((r)[0]), "=r"((r)[1]), "=r"((r)[2]), "=r"((r)[3]) : "r"(addr))

__device__ __forceinline__ void mma_f16(float c[4], const unsigned a[4], const unsigned b[2]) {
    asm("mma.sync.aligned.m16n8k16.row.col.f32.f16.f16.f32 "
        "{%0,%1,%2,%3}, {%4,%5,%6,%7}, {%8,%9}, {%0,%1,%2,%3};"
        : "+f"(c[0]), "+f"(c[1]), "+f"(c[2]), "+f"(c[3])
        : "r"(a[0]), "r"(a[1]), "r"(a[2]), "r"(a[3]), "r"(b[0]), "r"(b[1]));
}

// =====================================================================
// gemm_ha: half NT GEMM, fp32 out.  C[m][n] = sum_k A[m][k]*B[n][k]
// BM=256, BN=64, BK=32, 256 thr (8 warps = 4m x 2n, warp tile 64x32).
// 4-stage cp.async pipeline; ldmatrix fragment loads.
// =====================================================================
#define ST_BYTES 20480
#define B_OFF    16384
#define GH_SMEM  (4*ST_BYTES)

__global__ void __launch_bounds__(256, 2)
gemm_ha(const __half* __restrict__ A, const __half* __restrict__ B,
        float* __restrict__ C, int Kpart, int lda, int ldb, int ldc,
        long sA, long sB, long sC, int ksplit)
{
    extern __shared__ __align__(16) char smem[];
    const uint32_t sb = smem_u32(smem);

    const int tid  = threadIdx.x;
    const int w    = tid >> 5;
    const int lane = tid & 31;
    const int g    = lane >> 2;
    const int tg   = lane & 3;
    const int wm   = (w >> 1) * 64;
    const int wn   = (w & 1) * 32;

    const int batch = blockIdx.z / ksplit;
    const int part  = blockIdx.z % ksplit;
    const int bn    = blockIdx.x * 64;
    A += (long)batch*sA + (long)part*Kpart;
    B += (long)batch*sB + (long)part*Kpart;
    C += (long)blockIdx.z*sC;

    // ---- cp.async coordinates ----
    const int kc = tid & 3;
    const int ar = tid >> 2;
    const __half* aP = A + (long)ar*lda + kc*8;
    const __half* bP = B + (long)(bn + ar)*ldb + kc*8;
    const long aStride64 = (long)64*lda;
    const uint32_t aDst0 = (uint32_t)(ar*64 + ((kc ^ ((ar>>1)&3)) << 4));
    const uint32_t bDst  = (uint32_t)(B_OFF + ar*64 + ((kc ^ ((ar>>1)&3)) << 4));

    // ---- ldmatrix offsets ----
    uint32_t aLd[2], bLd[2];
    {
        const int mrow = wm + (lane & 7) + ((lane >> 3) & 1) * 8;
        const int msel = (mrow >> 1) & 3;
#pragma unroll
        for (int s = 0; s < 2; s++) {
            const int kcc = 2*s + (lane >> 4);
            aLd[s] = (uint32_t)(mrow*64 + ((kcc ^ msel) << 4));
        }
        const int nrow = wn + (lane & 7) + ((lane >> 4) << 3);
        const int nsel = (nrow >> 1) & 3;
#pragma unroll
        for (int s = 0; s < 2; s++) {
            const int kcc = 2*s + ((lane >> 3) & 1);
            bLd[s] = (uint32_t)(B_OFF + nrow*64 + ((kcc ^ nsel) << 4));
        }
    }

    float acc[4][4][4];
#pragma unroll
    for (int i = 0; i < 4; i++)
#pragma unroll
        for (int j = 0; j < 4; j++)
#pragma unroll
            for (int r = 0; r < 4; r++) acc[i][j][r] = 0.f;

    const int chunks = Kpart / 32;

    auto issue = [&](int slot) {
        const uint32_t base = sb + slot*ST_BYTES;
#pragma unroll
        for (int i = 0; i < 4; i++)
            CP_ASYNC16(base + aDst0 + i*4096, aP + i*aStride64);
        CP_ASYNC16(base + bDst, bP);
        aP += 32; bP += 32;
    };

    issue(0); CP_COMMIT();
    issue(1); CP_COMMIT();
    issue(2); CP_COMMIT();

    for (int c = 0; c < chunks; c++) {
        CP_WAIT2();
        __syncthreads();
        if (c + 3 < chunks) issue((c + 3) & 3);
        CP_COMMIT();

        const uint32_t base = sb + (c & 3)*ST_BYTES;
#pragma unroll
        for (int s = 0; s < 2; s++) {
            unsigned af[4][4], bq[8];
#pragma unroll
            for (int mt = 0; mt < 4; mt++)
                LDSM4(af[mt], base + aLd[s] + mt*1024);
            LDSM4(bq + 0, base + bLd[s]);
            LDSM4(bq + 4, base + bLd[s] + 1024);
#pragma unroll
            for (int i = 0; i < 4; i++)
#pragma unroll
                for (int j = 0; j < 4; j++)
                    mma_f16(acc[i][j], af[i], &bq[j*2]);
        }
    }

    // epilogue
#pragma unroll
    for (int i = 0; i < 4; i++) {
        const int row0 = wm + i*16 + g;
#pragma unroll
        for (int j = 0; j < 4; j++) {
            const int col = bn + wn + j*8 + 2*tg;
            *reinterpret_cast<float2*>(&C[(long)row0*ldc + col]) =
                make_float2(acc[i][j][0], acc[i][j][1]);
            *reinterpret_cast<float2*>(&C[(long)(row0 + 8)*ldc + col]) =
                make_float2(acc[i][j][2], acc[i][j][3]);
        }
    }
}

// =====================================================================
// key -> half (same layout), uint4 stores
// =====================================================================
__global__ void tohalf_kernel(const float4* __restrict__ src, uint4* __restrict__ dst, int n8)
{
    for (int i = blockIdx.x*blockDim.x + threadIdx.x; i < n8; i += gridDim.x*blockDim.x) {
        float4 v0 = src[2*i], v1 = src[2*i+1];
        __half2 a = __floats2half2_rn(v0.x, v0.y);
        __half2 b = __floats2half2_rn(v0.z, v0.w);
        __half2 c = __floats2half2_rn(v1.x, v1.y);
        __half2 d = __floats2half2_rn(v1.z, v1.w);
        uint4 o;
        o.x = *reinterpret_cast<unsigned*>(&a);
        o.y = *reinterpret_cast<unsigned*>(&b);
        o.z = *reinterpret_cast<unsigned*>(&c);
        o.w = *reinterpret_cast<unsigned*>(&d);
        dst[i] = o;
    }
}

// =====================================================================
// value [b][8192][1024] f32 -> g_vth [b][1024][8192] half
// 64x64 tiles, 256 thr (x=16 k4-groups on write / n4-groups on read, y=16)
// =====================================================================
__global__ void vtrans_kernel(const float* __restrict__ src, __half* __restrict__ dst)
{
    __shared__ float tile[64][65];
    const int b  = blockIdx.z;
    const int k0 = blockIdx.x * 64;
    const int n0 = blockIdx.y * 64;
    const float* s = src + (size_t)b * LK * HID;
    __half* d      = dst + (size_t)b * HID * LK;
    const int x = threadIdx.x & 15, y = threadIdx.x >> 4;

#pragma unroll
    for (int j = 0; j < 4; j++) {
        const int r = 16*j + y;
        float4 v = *reinterpret_cast<const float4*>(&s[(size_t)(k0 + r)*HID + n0 + 4*x]);
        tile[r][4*x+0] = v.x; tile[r][4*x+1] = v.y;
        tile[r][4*x+2] = v.z; tile[r][4*x+3] = v.w;
    }
    __syncthreads();
#pragma unroll
    for (int j = 0; j < 4; j++) {
        const int n = 16*j + y;                 // column of tile = dst row offset
        __half2 h0 = __floats2half2_rn(tile[4*x+0][n], tile[4*x+1][n]);
        __half2 h1 = __floats2half2_rn(tile[4*x+2][n], tile[4*x+3][n]);
        uint2 o;
        o.x = *reinterpret_cast<unsigned*>(&h0);
        o.y = *reinterpret_cast<unsigned*>(&h1);
        *reinterpret_cast<uint2*>(&d[(size_t)(n0 + n)*LK + k0 + 4*x]) = o;
    }
}

// =====================================================================
// fp32 FFMA NT GEMM for small projections K1/K7
// =====================================================================
template<int BM,int BN,int BK,int TM,int TN,bool BIAS>
__global__ void __launch_bounds__((BM/TM)*(BN/TN))
gemm_nt(const float* __restrict__ A, const float* __restrict__ Bm,
        const float* __restrict__ bias, float* __restrict__ C,
        int K, int lda, int ldb, int ldc)
{
    constexpr int TX = BN/TN, TY = BM/TM, NT = TX*TY;
    const int tid = threadIdx.x;
    const int tx  = tid % TX, ty = tid / TX;
    const int bm  = blockIdx.y*BM, bn = blockIdx.x*BN;

    __shared__ float As[BK][BM+4];
    __shared__ float Bs[BK][BN+4];

    float acc[TM][TN];
#pragma unroll
    for (int i=0;i<TM;i++)
#pragma unroll
        for (int j=0;j<TN;j++) acc[i][j] = 0.f;

    for (int k0 = 0; k0 < K; k0 += BK) {
#pragma unroll
        for (int i = tid; i < BM*BK/4; i += NT) {
            int m  = i / (BK/4);
            int k4 = (i % (BK/4)) * 4;
            float4 v = *reinterpret_cast<const float4*>(&A[(long)(bm+m)*lda + k0 + k4]);
            As[k4+0][m] = v.x; As[k4+1][m] = v.y; As[k4+2][m] = v.z; As[k4+3][m] = v.w;
        }
#pragma unroll
        for (int i = tid; i < BN*BK/4; i += NT) {
            int n  = i / (BK/4);
            int k4 = (i % (BK/4)) * 4;
            float4 v = *reinterpret_cast<const float4*>(&Bm[(long)(bn+n)*ldb + k0 + k4]);
            Bs[k4+0][n] = v.x; Bs[k4+1][n] = v.y; Bs[k4+2][n] = v.z; Bs[k4+3][n] = v.w;
        }
        __syncthreads();
#pragma unroll
        for (int k = 0; k < BK; k++) {
            float af[TM], bf[TN];
#pragma unroll
            for (int i=0;i<TM;i+=4)
                *reinterpret_cast<float4*>(&af[i]) =
                    *reinterpret_cast<const float4*>(&As[k][ty*TM + i]);
#pragma unroll
            for (int j=0;j<TN;j+=4)
                *reinterpret_cast<float4*>(&bf[j]) =
                    *reinterpret_cast<const float4*>(&Bs[k][tx*TN + j]);
#pragma unroll
            for (int i=0;i<TM;i++)
#pragma unroll
                for (int j=0;j<TN;j++)
                    acc[i][j] = fmaf(af[i], bf[j], acc[i][j]);
        }
        __syncthreads();
    }

#pragma unroll
    for (int i=0;i<TM;i++) {
        const int m = bm + ty*TM + i;
        float* crow = &C[(long)m*ldc + bn + tx*TN];
#pragma unroll
        for (int j=0;j<TN;j+=4) {
            float4 v;
            v.x = acc[i][j+0]; v.y = acc[i][j+1]; v.z = acc[i][j+2]; v.w = acc[i][j+3];
            if (BIAS) {
                const float* bp = &bias[bn + tx*TN + j];
                v.x += bp[0]; v.y += bp[1]; v.z += bp[2]; v.w += bp[3];
            }
            *reinterpret_cast<float4*>(&crow[j]) = v;
        }
    }
}

// =====================================================================
// qk = scale * q_h @ Wk_h -> half.  Transposed smem: at[e][qq] so the
// 16 a-values per e are 4 broadcast LDS.128 (same addr across warp).
// =====================================================================
__global__ void qk_kernel(const float* __restrict__ q,
                          const float* __restrict__ Wk,
                          __half* __restrict__ qkh)
{
    const int bh = blockIdx.y;
    const int b = bh >> 4, h = bh & 15;
    const int col = blockIdx.x*128 + threadIdx.x;
    __shared__ __align__(16) float at[HDIM][LQ];   // [e][qq]
    for (int i = threadIdx.x; i < LQ*HDIM; i += 128) {
        int qq = i >> 6, e = i & 63;
        at[e][qq] = q[(b*LQ + qq)*HID + h*HDIM + e];
    }
    __syncthreads();
    float acc[LQ];
#pragma unroll
    for (int i = 0; i < LQ; i++) acc[i] = 0.f;
#pragma unroll 4
    for (int e = 0; e < HDIM; e++) {
        const float wv = Wk[(h*HDIM + e)*HID + col];
        float4 a0 = *reinterpret_cast<const float4*>(&at[e][0]);
        float4 a1 = *reinterpret_cast<const float4*>(&at[e][4]);
        float4 a2 = *reinterpret_cast<const float4*>(&at[e][8]);
        float4 a3 = *reinterpret_cast<const float4*>(&at[e][12]);
        acc[0]  = fmaf(a0.x, wv, acc[0]);  acc[1]  = fmaf(a0.y, wv, acc[1]);
        acc[2]  = fmaf(a0.z, wv, acc[2]);  acc[3]  = fmaf(a0.w, wv, acc[3]);
        acc[4]  = fmaf(a1.x, wv, acc[4]);  acc[5]  = fmaf(a1.y, wv, acc[5]);
        acc[6]  = fmaf(a1.z, wv, acc[6]);  acc[7]  = fmaf(a1.w, wv, acc[7]);
        acc[8]  = fmaf(a2.x, wv, acc[8]);  acc[9]  = fmaf(a2.y, wv, acc[9]);
        acc[10] = fmaf(a2.z, wv, acc[10]); acc[11] = fmaf(a2.w, wv, acc[11]);
        acc[12] = fmaf(a3.x, wv, acc[12]); acc[13] = fmaf(a3.y, wv, acc[13]);
        acc[14] = fmaf(a3.z, wv, acc[14]); acc[15] = fmaf(a3.w, wv, acc[15]);
    }
    const float scale = 0.125f;
#pragma unroll
    for (int qq = 0; qq < LQ; qq++)
        qkh[((long)b*RPB + h*LQ + qq)*HID + col] = __float2half_rn(acc[qq] * scale);
}

// =====================================================================
// softmax: fp32 logits in, half probs out
// =====================================================================
__global__ void softmax_kernel(const float* __restrict__ logits, __half* __restrict__ probs)
{
    const size_t row = blockIdx.x;
    const float* p = logits + row * (size_t)LK;
    __half2* o2 = reinterpret_cast<__half2*>(probs + row * (size_t)LK);
    __shared__ float buf[LK];
    __shared__ float red[8];
    const int tid = threadIdx.x;
    const int lane = tid & 31, warp = tid >> 5;
    float4*       b4 = reinterpret_cast<float4*>(buf);
    const float4* p4 = reinterpret_cast<const float4*>(p);

    float mx = -3.0e38f;
    for (int i = tid; i < LK/4; i += 256) {
        float4 v = p4[i]; b4[i] = v;
        mx = fmaxf(mx, fmaxf(fmaxf(v.x,v.y), fmaxf(v.z,v.w)));
    }
#pragma unroll
    for (int o=16;o;o>>=1) mx = fmaxf(mx, __shfl_xor_sync(0xffffffffu, mx, o));
    if (lane==0) red[warp] = mx;
    __syncthreads();
    mx = red[0];
#pragma unroll
    for (int w=1;w<8;w++) mx = fmaxf(mx, red[w]);

    float sum = 0.f;
    for (int i = tid; i < LK/4; i += 256) {
        float4 v = b4[i];
        v.x = expf(v.x - mx); v.y = expf(v.y - mx);
        v.z = expf(v.z - mx); v.w = expf(v.w - mx);
        b4[i] = v;
        sum += (v.x + v.y) + (v.z + v.w);
    }
#pragma unroll
    for (int o=16;o;o>>=1) sum += __shfl_xor_sync(0xffffffffu, sum, o);
    __syncthreads();
    if (lane==0) red[warp] = sum;
    __syncthreads();
    sum = 0.f;
#pragma unroll
    for (int w=0;w<8;w++) sum += red[w];
    const float inv = 1.f / sum;

    for (int i = tid; i < LK/4; i += 256) {
        float4 v = b4[i];
        o2[2*i]   = __floats2half2_rn(v.x*inv, v.y*inv);
        o2[2*i+1] = __floats2half2_rn(v.z*inv, v.w*inv);
    }
}

// =====================================================================
// attn = (sum of 4 ctx slabs) @ Wv_h^T + bv, per (b,h)
// =====================================================================
__global__ void attnv_kernel(const float* __restrict__ ctx,
                             const float* __restrict__ Wv,
                             const float* __restrict__ bv,
                             float* __restrict__ attn)
{
    const int bh = blockIdx.x;
    const int b = bh >> 4, h = bh & 15;
    const int t = threadIdx.x;
    const int d = t & 63, qg = t >> 6;
    __shared__ float cs[LQ][129];
    __shared__ float ws[HDIM][129];
    float acc[4] = {0.f,0.f,0.f,0.f};

    long row[4];
#pragma unroll
    for (int p = 0; p < 4; p++) row[p] = (long)(b*4 + p)*RPB + h*LQ;

    for (int e0 = 0; e0 < HID; e0 += 128) {
        __syncthreads();
        for (int i = t; i < LQ*128; i += 256) {
            int qq = i >> 7, e = i & 127;
            float v = 0.f;
#pragma unroll
            for (int p = 0; p < 4; p++) v += ctx[(row[p] + qq)*HID + e0 + e];
            cs[qq][e] = v;
        }
        for (int i = t; i < HDIM*128; i += 256) {
            int dd = i >> 7, e = i & 127;
            ws[dd][e] = Wv[(long)(h*HDIM + dd)*HID + e0 + e];
        }
        __syncthreads();
#pragma unroll 4
        for (int e = 0; e < 128; e++) {
            float wv = ws[d][e];
#pragma unroll
            for (int j = 0; j < 4; j++)
                acc[j] = fmaf(cs[qg*4 + j][e], wv, acc[j]);
        }
    }
    const float bvv = bv[h*HDIM + d];
#pragma unroll
    for (int j = 0; j < 4; j++)
        attn[(long)(b*LQ + qg*4 + j)*HID + h*HDIM + d] = acc[j] + bvv;
}

// =====================================================================
// launch  (K3 gemm_ha is the 4th launch -> gets profiled)
// =====================================================================
extern "C" void kernel_launch(void* const* d_in, const int* in_sizes, int n_in,
                              void* d_out, int out_size)
{
    const float* query = (const float*)d_in[0];
    const float* key   = (const float*)d_in[1];
    const float* value = (const float*)d_in[2];
    const float* Wq    = (const float*)d_in[3];
    const float* bq    = (const float*)d_in[4];
    const float* Wk    = (const float*)d_in[5];
    /* bk = d_in[6] : softmax-invariant, dropped */
    const float* Wv    = (const float*)d_in[7];
    const float* bv    = (const float*)d_in[8];
    const float* Wo    = (const float*)d_in[9];
    const float* bo    = (const float*)d_in[10];
    float* out = (float*)d_out;

    float *gq, *glog, *gctx, *gattn;
    __half *gqkh, *gph, *gkh, *gvth;
    cudaGetSymbolAddress((void**)&gq,    g_q);
    cudaGetSymbolAddress((void**)&gqkh,  g_qkh);
    cudaGetSymbolAddress((void**)&glog,  g_logits);
    cudaGetSymbolAddress((void**)&gph,   g_ph);
    cudaGetSymbolAddress((void**)&gkh,   g_kh);
    cudaGetSymbolAddress((void**)&gvth,  g_vth);
    cudaGetSymbolAddress((void**)&gctx,  g_ctx);
    cudaGetSymbolAddress((void**)&gattn, g_attn);

    cudaFuncSetAttribute(gemm_ha, cudaFuncAttributeMaxDynamicSharedMemorySize, GH_SMEM);

    // #1  K1: q = query @ Wq^T + bq (fp32)
    gemm_nt<64,64,16,4,4,true><<<dim3(HID/64, (BB*LQ)/64), 256>>>(
        query, Wq, bq, gq, HID, HID, HID, HID);

    // #2  K2: qk = scale * q_h @ Wk_h -> half
    qk_kernel<<<dim3(HID/128, BB*NHEAD), 128>>>(gq, Wk, gqkh);

    // #3  key -> half
    tohalf_kernel<<<1024, 256>>>((const float4*)key, (uint4*)gkh, BB*LK*HID/8);

    // #4  K3: logits = qkh @ kh^T  [256 x 8192] per batch, K=1024  (PROFILED)
    gemm_ha<<<dim3(LK/64, 1, BB), 256, GH_SMEM>>>(
        gqkh, gkh, glog, HID, HID, HID, LK,
        (long)RPB*HID, (long)LK*HID, (long)RPB*LK, 1);

    // #5  value -> half transposed [b][n][k]
    vtrans_kernel<<<dim3(LK/64, HID/64, BB), 256>>>(value, gvth);

    // #6  K4: softmax fp32 -> half probs
    softmax_kernel<<<BB*RPB, 256>>>(glog, gph);

    // #7  K5: ctx = ph @ vth^T  [256 x 1024] per batch, K=8192, split-K=4
    gemm_ha<<<dim3(HID/64, 1, BB*4), 256, GH_SMEM>>>(
        gph, gvth, gctx, LK/4, LK, LK, HID,
        (long)RPB*LK, (long)HID*LK, (long)RPB*HID, 4);

    // #8  K6: attn = ctx @ Wv_h^T + bv
    attnv_kernel<<<BB*NHEAD, 256>>>(gctx, Wv, bv, gattn);

    // #9  K7: out = attn @ Wo^T + bo
    gemm_nt<64,64,16,4,4,true><<<dim3(HID/64, (BB*LQ)/64), 256>>>(
        gattn, Wo, bo, out, HID, HID, HID, HID);
}

// round 8
// speedup vs baseline: 2.3576x; 1.0285x over previous
#include <cuda_runtime.h>
#include <cuda_fp16.h>
#include <cstdint>
#include <math.h>

#define HID   1024
#define NHEAD 16
#define HDIM  64
#define BB    8
#define LQ    16
#define LK    8192
#define RPB   (NHEAD*LQ)   /* 256 rows per batch */

// ---------------- scratch ----------------
__device__ float  g_q[BB*LQ*HID];
__device__ __half g_qkh[BB*RPB*HID];
__device__ __half g_logh[(size_t)BB*RPB*LK];
__device__ __half g_ph[(size_t)BB*RPB*LK];
__device__ __half g_kh[(size_t)BB*LK*HID];
__device__ __half g_vth[(size_t)BB*HID*LK];
__device__ float  g_ctx[2*BB*RPB*HID];
__device__ float  g_attn[BB*LQ*HID];

// =====================================================================
// asm helpers
// =====================================================================
__device__ __forceinline__ uint32_t smem_u32(const void* p) {
    uint32_t a;
    asm("{ .reg .u64 t; cvta.to.shared.u64 t, %1; cvt.u32.u64 %0, t; }" : "=r"(a) : "l"(p));
    return a;
}
#define CP_ASYNC16(dst, src) \
    asm volatile("cp.async.cg.shared.global [%0], [%1], 16;" :: "r"(dst), "l"(src) : "memory")
#define CP_COMMIT()  asm volatile("cp.async.commit_group;" ::: "memory")
#define CP_WAIT2()   asm volatile("cp.async.wait_group 2;" ::: "memory")
#define LDSM4(r, addr) \
    asm volatile("ldmatrix.sync.aligned.m8n8.x4.shared.b16 {%0,%1,%2,%3}, [%4];" \
        : "=r"((r)[0]), "=r"((r)[1]), "=r"((r)[2]), "=r"((r)[3]) : "r"(addr))

__device__ __forceinline__ void mma_f16(float c[4], const unsigned a[4], const unsigned b[2]) {
    asm("mma.sync.aligned.m16n8k16.row.col.f32.f16.f16.f32 "
        "{%0,%1,%2,%3}, {%4,%5,%6,%7}, {%8,%9}, {%0,%1,%2,%3};"
        : "+f"(c[0]), "+f"(c[1]), "+f"(c[2]), "+f"(c[3])
        : "r"(a[0]), "r"(a[1]), "r"(a[2]), "r"(a[3]), "r"(b[0]), "r"(b[1]));
}

// =====================================================================
// gemm_ha: half NT GEMM.  C[m][n] = sum_k A[m][k]*B[n][k]
// BM=256, BN=64, BK=32, 256 thr (8 warps = 4m x 2n, warp tile 64x32).
// 4-stage cp.async pipeline; ldmatrix fragment loads.
// CT = float (fp32 out) or __half (half out).
// =====================================================================
#define ST_BYTES 20480
#define B_OFF    16384
#define GH_SMEM  (4*ST_BYTES)

template<typename CT>
__global__ void __launch_bounds__(256, 2)
gemm_ha(const __half* __restrict__ A, const __half* __restrict__ B,
        CT* __restrict__ C, int Kpart, int lda, int ldb, int ldc,
        long sA, long sB, long sC, int ksplit)
{
    extern __shared__ __align__(16) char smem[];
    const uint32_t sb = smem_u32(smem);

    const int tid  = threadIdx.x;
    const int w    = tid >> 5;
    const int lane = tid & 31;
    const int g    = lane >> 2;
    const int tg   = lane & 3;
    const int wm   = (w >> 1) * 64;
    const int wn   = (w & 1) * 32;

    const int batch = blockIdx.z / ksplit;
    const int part  = blockIdx.z % ksplit;
    const int bn    = blockIdx.x * 64;
    A += (long)batch*sA + (long)part*Kpart;
    B += (long)batch*sB + (long)part*Kpart;
    C += (long)blockIdx.z*sC;

    // ---- cp.async coordinates ----
    const int kc = tid & 3;
    const int ar = tid >> 2;
    const __half* aP = A + (long)ar*lda + kc*8;
    const __half* bP = B + (long)(bn + ar)*ldb + kc*8;
    const long aStride64 = (long)64*lda;
    const uint32_t aDst0 = (uint32_t)(ar*64 + ((kc ^ ((ar>>1)&3)) << 4));
    const uint32_t bDst  = (uint32_t)(B_OFF + ar*64 + ((kc ^ ((ar>>1)&3)) << 4));

    // ---- ldmatrix offsets ----
    uint32_t aLd[2], bLd[2];
    {
        const int mrow = wm + (lane & 7) + ((lane >> 3) & 1) * 8;
        const int msel = (mrow >> 1) & 3;
#pragma unroll
        for (int s = 0; s < 2; s++) {
            const int kcc = 2*s + (lane >> 4);
            aLd[s] = (uint32_t)(mrow*64 + ((kcc ^ msel) << 4));
        }
        const int nrow = wn + (lane & 7) + ((lane >> 4) << 3);
        const int nsel = (nrow >> 1) & 3;
#pragma unroll
        for (int s = 0; s < 2; s++) {
            const int kcc = 2*s + ((lane >> 3) & 1);
            bLd[s] = (uint32_t)(B_OFF + nrow*64 + ((kcc ^ nsel) << 4));
        }
    }

    float acc[4][4][4];
#pragma unroll
    for (int i = 0; i < 4; i++)
#pragma unroll
        for (int j = 0; j < 4; j++)
#pragma unroll
            for (int r = 0; r < 4; r++) acc[i][j][r] = 0.f;

    const int chunks = Kpart / 32;

    auto issue = [&](int slot) {
        const uint32_t base = sb + slot*ST_BYTES;
#pragma unroll
        for (int i = 0; i < 4; i++)
            CP_ASYNC16(base + aDst0 + i*4096, aP + i*aStride64);
        CP_ASYNC16(base + bDst, bP);
        aP += 32; bP += 32;
    };

    issue(0); CP_COMMIT();
    issue(1); CP_COMMIT();
    issue(2); CP_COMMIT();

    for (int c = 0; c < chunks; c++) {
        CP_WAIT2();
        __syncthreads();
        if (c + 3 < chunks) issue((c + 3) & 3);
        CP_COMMIT();

        const uint32_t base = sb + (c & 3)*ST_BYTES;
#pragma unroll
        for (int s = 0; s < 2; s++) {
            unsigned af[4][4], bq[8];
#pragma unroll
            for (int mt = 0; mt < 4; mt++)
                LDSM4(af[mt], base + aLd[s] + mt*1024);
            LDSM4(bq + 0, base + bLd[s]);
            LDSM4(bq + 4, base + bLd[s] + 1024);
#pragma unroll
            for (int i = 0; i < 4; i++)
#pragma unroll
                for (int j = 0; j < 4; j++)
                    mma_f16(acc[i][j], af[i], &bq[j*2]);
        }
    }

    // epilogue
#pragma unroll
    for (int i = 0; i < 4; i++) {
        const int row0 = wm + i*16 + g;
#pragma unroll
        for (int j = 0; j < 4; j++) {
            const int col = bn + wn + j*8 + 2*tg;
            if (sizeof(CT) == 4) {
                *reinterpret_cast<float2*>(&((float*)C)[(long)row0*ldc + col]) =
                    make_float2(acc[i][j][0], acc[i][j][1]);
                *reinterpret_cast<float2*>(&((float*)C)[(long)(row0 + 8)*ldc + col]) =
                    make_float2(acc[i][j][2], acc[i][j][3]);
            } else {
                *reinterpret_cast<__half2*>(&((__half*)C)[(long)row0*ldc + col]) =
                    __floats2half2_rn(acc[i][j][0], acc[i][j][1]);
                *reinterpret_cast<__half2*>(&((__half*)C)[(long)(row0 + 8)*ldc + col]) =
                    __floats2half2_rn(acc[i][j][2], acc[i][j][3]);
            }
        }
    }
}

// =====================================================================
// key -> half (same layout), uint4 stores
// =====================================================================
__global__ void tohalf_kernel(const float4* __restrict__ src, uint4* __restrict__ dst, int n8)
{
    for (int i = blockIdx.x*blockDim.x + threadIdx.x; i < n8; i += gridDim.x*blockDim.x) {
        float4 v0 = src[2*i], v1 = src[2*i+1];
        __half2 a = __floats2half2_rn(v0.x, v0.y);
        __half2 b = __floats2half2_rn(v0.z, v0.w);
        __half2 c = __floats2half2_rn(v1.x, v1.y);
        __half2 d = __floats2half2_rn(v1.z, v1.w);
        uint4 o;
        o.x = *reinterpret_cast<unsigned*>(&a);
        o.y = *reinterpret_cast<unsigned*>(&b);
        o.z = *reinterpret_cast<unsigned*>(&c);
        o.w = *reinterpret_cast<unsigned*>(&d);
        dst[i] = o;
    }
}

// =====================================================================
// value [b][8192][1024] f32 -> g_vth [b][1024][8192] half (64x64 tiles)
// =====================================================================
__global__ void vtrans_kernel(const float* __restrict__ src, __half* __restrict__ dst)
{
    __shared__ float tile[64][65];
    const int b  = blockIdx.z;
    const int k0 = blockIdx.x * 64;
    const int n0 = blockIdx.y * 64;
    const float* s = src + (size_t)b * LK * HID;
    __half* d      = dst + (size_t)b * HID * LK;
    const int x = threadIdx.x & 15, y = threadIdx.x >> 4;

#pragma unroll
    for (int j = 0; j < 4; j++) {
        const int r = 16*j + y;
        float4 v = *reinterpret_cast<const float4*>(&s[(size_t)(k0 + r)*HID + n0 + 4*x]);
        tile[r][4*x+0] = v.x; tile[r][4*x+1] = v.y;
        tile[r][4*x+2] = v.z; tile[r][4*x+3] = v.w;
    }
    __syncthreads();
#pragma unroll
    for (int j = 0; j < 4; j++) {
        const int n = 16*j + y;
        __half2 h0 = __floats2half2_rn(tile[4*x+0][n], tile[4*x+1][n]);
        __half2 h1 = __floats2half2_rn(tile[4*x+2][n], tile[4*x+3][n]);
        uint2 o;
        o.x = *reinterpret_cast<unsigned*>(&h0);
        o.y = *reinterpret_cast<unsigned*>(&h1);
        *reinterpret_cast<uint2*>(&d[(size_t)(n0 + n)*LK + k0 + 4*x]) = o;
    }
}

// =====================================================================
// fp32 FFMA NT GEMM for small projections K1/K7
// =====================================================================
template<int BM,int BN,int BK,int TM,int TN,bool BIAS>
__global__ void __launch_bounds__((BM/TM)*(BN/TN))
gemm_nt(const float* __restrict__ A, const float* __restrict__ Bm,
        const float* __restrict__ bias, float* __restrict__ C,
        int K, int lda, int ldb, int ldc)
{
    constexpr int TX = BN/TN, TY = BM/TM, NT = TX*TY;
    const int tid = threadIdx.x;
    const int tx  = tid % TX, ty = tid / TX;
    const int bm  = blockIdx.y*BM, bn = blockIdx.x*BN;

    __shared__ float As[BK][BM+4];
    __shared__ float Bs[BK][BN+4];

    float acc[TM][TN];
#pragma unroll
    for (int i=0;i<TM;i++)
#pragma unroll
        for (int j=0;j<TN;j++) acc[i][j] = 0.f;

    for (int k0 = 0; k0 < K; k0 += BK) {
#pragma unroll
        for (int i = tid; i < BM*BK/4; i += NT) {
            int m  = i / (BK/4);
            int k4 = (i % (BK/4)) * 4;
            float4 v = *reinterpret_cast<const float4*>(&A[(long)(bm+m)*lda + k0 + k4]);
            As[k4+0][m] = v.x; As[k4+1][m] = v.y; As[k4+2][m] = v.z; As[k4+3][m] = v.w;
        }
#pragma unroll
        for (int i = tid; i < BN*BK/4; i += NT) {
            int n  = i / (BK/4);
            int k4 = (i % (BK/4)) * 4;
            float4 v = *reinterpret_cast<const float4*>(&Bm[(long)(bn+n)*ldb + k0 + k4]);
            Bs[k4+0][n] = v.x; Bs[k4+1][n] = v.y; Bs[k4+2][n] = v.z; Bs[k4+3][n] = v.w;
        }
        __syncthreads();
#pragma unroll
        for (int k = 0; k < BK; k++) {
            float af[TM], bf[TN];
#pragma unroll
            for (int i=0;i<TM;i+=4)
                *reinterpret_cast<float4*>(&af[i]) =
                    *reinterpret_cast<const float4*>(&As[k][ty*TM + i]);
#pragma unroll
            for (int j=0;j<TN;j+=4)
                *reinterpret_cast<float4*>(&bf[j]) =
                    *reinterpret_cast<const float4*>(&Bs[k][tx*TN + j]);
#pragma unroll
            for (int i=0;i<TM;i++)
#pragma unroll
                for (int j=0;j<TN;j++)
                    acc[i][j] = fmaf(af[i], bf[j], acc[i][j]);
        }
        __syncthreads();
    }

#pragma unroll
    for (int i=0;i<TM;i++) {
        const int m = bm + ty*TM + i;
        float* crow = &C[(long)m*ldc + bn + tx*TN];
#pragma unroll
        for (int j=0;j<TN;j+=4) {
            float4 v;
            v.x = acc[i][j+0]; v.y = acc[i][j+1]; v.z = acc[i][j+2]; v.w = acc[i][j+3];
            if (BIAS) {
                const float* bp = &bias[bn + tx*TN + j];
                v.x += bp[0]; v.y += bp[1]; v.z += bp[2]; v.w += bp[3];
            }
            *reinterpret_cast<float4*>(&crow[j]) = v;
        }
    }
}

// =====================================================================
// qk = scale * q_h @ Wk_h -> half (transposed smem, broadcast LDS.128)
// =====================================================================
__global__ void qk_kernel(const float* __restrict__ q,
                          const float* __restrict__ Wk,
                          __half* __restrict__ qkh)
{
    const int bh = blockIdx.y;
    const int b = bh >> 4, h = bh & 15;
    const int col = blockIdx.x*128 + threadIdx.x;
    __shared__ __align__(16) float at[HDIM][LQ];
    for (int i = threadIdx.x; i < LQ*HDIM; i += 128) {
        int qq = i >> 6, e = i & 63;
        at[e][qq] = q[(b*LQ + qq)*HID + h*HDIM + e];
    }
    __syncthreads();
    float acc[LQ];
#pragma unroll
    for (int i = 0; i < LQ; i++) acc[i] = 0.f;
#pragma unroll 4
    for (int e = 0; e < HDIM; e++) {
        const float wv = Wk[(h*HDIM + e)*HID + col];
        float4 a0 = *reinterpret_cast<const float4*>(&at[e][0]);
        float4 a1 = *reinterpret_cast<const float4*>(&at[e][4]);
        float4 a2 = *reinterpret_cast<const float4*>(&at[e][8]);
        float4 a3 = *reinterpret_cast<const float4*>(&at[e][12]);
        acc[0]  = fmaf(a0.x, wv, acc[0]);  acc[1]  = fmaf(a0.y, wv, acc[1]);
        acc[2]  = fmaf(a0.z, wv, acc[2]);  acc[3]  = fmaf(a0.w, wv, acc[3]);
        acc[4]  = fmaf(a1.x, wv, acc[4]);  acc[5]  = fmaf(a1.y, wv, acc[5]);
        acc[6]  = fmaf(a1.z, wv, acc[6]);  acc[7]  = fmaf(a1.w, wv, acc[7]);
        acc[8]  = fmaf(a2.x, wv, acc[8]);  acc[9]  = fmaf(a2.y, wv, acc[9]);
        acc[10] = fmaf(a2.z, wv, acc[10]); acc[11] = fmaf(a2.w, wv, acc[11]);
        acc[12] = fmaf(a3.x, wv, acc[12]); acc[13] = fmaf(a3.y, wv, acc[13]);
        acc[14] = fmaf(a3.z, wv, acc[14]); acc[15] = fmaf(a3.w, wv, acc[15]);
    }
    const float scale = 0.125f;
#pragma unroll
    for (int qq = 0; qq < LQ; qq++)
        qkh[((long)b*RPB + h*LQ + qq)*HID + col] = __float2half_rn(acc[qq] * scale);
}

// =====================================================================
// softmax: half logits in, half probs out (fp32 math via smem staging)
// =====================================================================
__global__ void softmax_kernel(const __half* __restrict__ logits, __half* __restrict__ probs)
{
    const size_t row = blockIdx.x;
    const uint4* p4 = reinterpret_cast<const uint4*>(logits + row * (size_t)LK);
    __half2*     o2 = reinterpret_cast<__half2*>(probs + row * (size_t)LK);
    __shared__ float buf[LK];
    __shared__ float red[8];
    const int tid = threadIdx.x;
    const int lane = tid & 31, warp = tid >> 5;
    float4* b4 = reinterpret_cast<float4*>(buf);

    float mx = -3.0e38f;
    for (int i = tid; i < LK/8; i += 256) {
        uint4 u = p4[i];
        float2 f0 = __half22float2(*reinterpret_cast<__half2*>(&u.x));
        float2 f1 = __half22float2(*reinterpret_cast<__half2*>(&u.y));
        float2 f2 = __half22float2(*reinterpret_cast<__half2*>(&u.z));
        float2 f3 = __half22float2(*reinterpret_cast<__half2*>(&u.w));
        b4[2*i]   = make_float4(f0.x, f0.y, f1.x, f1.y);
        b4[2*i+1] = make_float4(f2.x, f2.y, f3.x, f3.y);
        mx = fmaxf(mx, fmaxf(fmaxf(f0.x,f0.y), fmaxf(f1.x,f1.y)));
        mx = fmaxf(mx, fmaxf(fmaxf(f2.x,f2.y), fmaxf(f3.x,f3.y)));
    }
#pragma unroll
    for (int o=16;o;o>>=1) mx = fmaxf(mx, __shfl_xor_sync(0xffffffffu, mx, o));
    if (lane==0) red[warp] = mx;
    __syncthreads();
    mx = red[0];
#pragma unroll
    for (int w=1;w<8;w++) mx = fmaxf(mx, red[w]);

    float sum = 0.f;
    for (int i = tid; i < LK/4; i += 256) {
        float4 v = b4[i];
        v.x = expf(v.x - mx); v.y = expf(v.y - mx);
        v.z = expf(v.z - mx); v.w = expf(v.w - mx);
        b4[i] = v;
        sum += (v.x + v.y) + (v.z + v.w);
    }
#pragma unroll
    for (int o=16;o;o>>=1) sum += __shfl_xor_sync(0xffffffffu, sum, o);
    __syncthreads();
    if (lane==0) red[warp] = sum;
    __syncthreads();
    sum = 0.f;
#pragma unroll
    for (int w=0;w<8;w++) sum += red[w];
    const float inv = 1.f / sum;

    for (int i = tid; i < LK/4; i += 256) {
        float4 v = b4[i];
        o2[2*i]   = __floats2half2_rn(v.x*inv, v.y*inv);
        o2[2*i+1] = __floats2half2_rn(v.z*inv, v.w*inv);
    }
}

// =====================================================================
// attn = (ctx slab A + slab B) @ Wv_h^T + bv, per (b,h)
// =====================================================================
__global__ void attnv_kernel(const float* __restrict__ ctx,
                             const float* __restrict__ Wv,
                             const float* __restrict__ bv,
                             float* __restrict__ attn)
{
    const int bh = blockIdx.x;
    const int b = bh >> 4, h = bh & 15;
    const int t = threadIdx.x;
    const int d = t & 63, qg = t >> 6;
    __shared__ float cs[LQ][129];
    __shared__ float ws[HDIM][129];
    float acc[4] = {0.f,0.f,0.f,0.f};

    const long rowA = (long)(b*2    )*RPB + h*LQ;
    const long rowB = (long)(b*2 + 1)*RPB + h*LQ;

    for (int e0 = 0; e0 < HID; e0 += 128) {
        __syncthreads();
        for (int i = t; i < LQ*128; i += 256) {
            int qq = i >> 7, e = i & 127;
            cs[qq][e] = ctx[(rowA + qq)*HID + e0 + e] + ctx[(rowB + qq)*HID + e0 + e];
        }
        for (int i = t; i < HDIM*128; i += 256) {
            int dd = i >> 7, e = i & 127;
            ws[dd][e] = Wv[(long)(h*HDIM + dd)*HID + e0 + e];
        }
        __syncthreads();
#pragma unroll 4
        for (int e = 0; e < 128; e++) {
            float wv = ws[d][e];
#pragma unroll
            for (int j = 0; j < 4; j++)
                acc[j] = fmaf(cs[qg*4 + j][e], wv, acc[j]);
        }
    }
    const float bvv = bv[h*HDIM + d];
#pragma unroll
    for (int j = 0; j < 4; j++)
        attn[(long)(b*LQ + qg*4 + j)*HID + h*HDIM + d] = acc[j] + bvv;
}

// =====================================================================
// launch  (K3 gemm_ha stays the 4th launch -> profiled)
// =====================================================================
extern "C" void kernel_launch(void* const* d_in, const int* in_sizes, int n_in,
                              void* d_out, int out_size)
{
    const float* query = (const float*)d_in[0];
    const float* key   = (const float*)d_in[1];
    const float* value = (const float*)d_in[2];
    const float* Wq    = (const float*)d_in[3];
    const float* bq    = (const float*)d_in[4];
    const float* Wk    = (const float*)d_in[5];
    /* bk = d_in[6] : softmax-invariant, dropped */
    const float* Wv    = (const float*)d_in[7];
    const float* bv    = (const float*)d_in[8];
    const float* Wo    = (const float*)d_in[9];
    const float* bo    = (const float*)d_in[10];
    float* out = (float*)d_out;

    float *gq, *gctx, *gattn;
    __half *gqkh, *glogh, *gph, *gkh, *gvth;
    cudaGetSymbolAddress((void**)&gq,    g_q);
    cudaGetSymbolAddress((void**)&gqkh,  g_qkh);
    cudaGetSymbolAddress((void**)&glogh, g_logh);
    cudaGetSymbolAddress((void**)&gph,   g_ph);
    cudaGetSymbolAddress((void**)&gkh,   g_kh);
    cudaGetSymbolAddress((void**)&gvth,  g_vth);
    cudaGetSymbolAddress((void**)&gctx,  g_ctx);
    cudaGetSymbolAddress((void**)&gattn, g_attn);

    cudaFuncSetAttribute(gemm_ha<__half>, cudaFuncAttributeMaxDynamicSharedMemorySize, GH_SMEM);
    cudaFuncSetAttribute(gemm_ha<float>,  cudaFuncAttributeMaxDynamicSharedMemorySize, GH_SMEM);

    // #1  K1: q = query @ Wq^T + bq (fp32)
    gemm_nt<64,64,16,4,4,true><<<dim3(HID/64, (BB*LQ)/64), 256>>>(
        query, Wq, bq, gq, HID, HID, HID, HID);

    // #2  K2: qk = scale * q_h @ Wk_h -> half
    qk_kernel<<<dim3(HID/128, BB*NHEAD), 128>>>(gq, Wk, gqkh);

    // #3  key -> half
    tohalf_kernel<<<1024, 256>>>((const float4*)key, (uint4*)gkh, BB*LK*HID/8);

    // #4  K3: logits(half) = qkh @ kh^T  [256 x 8192] per batch, K=1024  (PROFILED)
    gemm_ha<__half><<<dim3(LK/64, 1, BB), 256, GH_SMEM>>>(
        gqkh, gkh, glogh, HID, HID, HID, LK,
        (long)RPB*HID, (long)LK*HID, (long)RPB*LK, 1);

    // #5  value -> half transposed [b][n][k]
    vtrans_kernel<<<dim3(LK/64, HID/64, BB), 256>>>(value, gvth);

    // #6  K4: softmax half -> half probs
    softmax_kernel<<<BB*RPB, 256>>>(glogh, gph);

    // #7  K5: ctx = ph @ vth^T  [256 x 1024] per batch, K=8192, split-K=2
    gemm_ha<float><<<dim3(HID/64, 1, BB*2), 256, GH_SMEM>>>(
        gph, gvth, gctx, LK/2, LK, LK, HID,
        (long)RPB*LK, (long)HID*LK, (long)RPB*HID, 2);

    // #8  K6: attn = ctx @ Wv_h^T + bv
    attnv_kernel<<<BB*NHEAD, 256>>>(gctx, Wv, bv, gattn);

    // #9  K7: out = attn @ Wo^T + bo
    gemm_nt<64,64,16,4,4,true><<<dim3(HID/64, (BB*LQ)/64), 256>>>(
        gattn, Wo, bo, out, HID, HID, HID, HID);
}

// round 9
// speedup vs baseline: 2.4427x; 1.0361x over previous
#include <cuda_runtime.h>
#include <cuda_fp16.h>
#include <cstdint>
#include <math.h>

#define HID   1024
#define NHEAD 16
#define HDIM  64
#define BB    8
#define LQ    16
#define LK    8192
#define RPB   (NHEAD*LQ)   /* 256 rows per batch */

// ---------------- scratch ----------------
__device__ float  g_q[BB*LQ*HID];
__device__ __half g_qkh[BB*RPB*HID];
__device__ __half g_logh[(size_t)BB*RPB*LK];
__device__ __half g_ph[(size_t)BB*RPB*LK];
__device__ __half g_kh[(size_t)BB*LK*HID];
__device__ __half g_vh[(size_t)BB*LK*HID];      // value in half, native [k][n]
__device__ float  g_ctx[2*BB*RPB*HID];
__device__ float  g_attn[BB*LQ*HID];

// =====================================================================
// asm helpers
// =====================================================================
__device__ __forceinline__ uint32_t smem_u32(const void* p) {
    uint32_t a;
    asm("{ .reg .u64 t; cvta.to.shared.u64 t, %1; cvt.u32.u64 %0, t; }" : "=r"(a) : "l"(p));
    return a;
}
#define CP_ASYNC16(dst, src) \
    asm volatile("cp.async.cg.shared.global [%0], [%1], 16;" :: "r"(dst), "l"(src) : "memory")
#define CP_COMMIT()  asm volatile("cp.async.commit_group;" ::: "memory")
#define CP_WAIT2()   asm volatile("cp.async.wait_group 2;" ::: "memory")
#define LDSM4(r, addr) \
    asm volatile("ldmatrix.sync.aligned.m8n8.x4.shared.b16 {%0,%1,%2,%3}, [%4];" \
        : "=r"((r)[0]), "=r"((r)[1]), "=r"((r)[2]), "=r"((r)[3]) : "r"(addr))
#define LDSM4_T(r, addr) \
    asm volatile("ldmatrix.sync.aligned.m8n8.x4.trans.shared.b16 {%0,%1,%2,%3}, [%4];" \
        : "=r"((r)[0]), "=r"((r)[1]), "=r"((r)[2]), "=r"((r)[3]) : "r"(addr))

__device__ __forceinline__ void mma_f16(float c[4], const unsigned a[4], const unsigned b[2]) {
    asm("mma.sync.aligned.m16n8k16.row.col.f32.f16.f16.f32 "
        "{%0,%1,%2,%3}, {%4,%5,%6,%7}, {%8,%9}, {%0,%1,%2,%3};"
        : "+f"(c[0]), "+f"(c[1]), "+f"(c[2]), "+f"(c[3])
        : "r"(a[0]), "r"(a[1]), "r"(a[2]), "r"(a[3]), "r"(b[0]), "r"(b[1]));
}

// =====================================================================
// gemm_ha: half GEMM.  C[m][n] = sum_k A[m][k] * B-op
// TRB=0: B[n*ldb + k] (NT);  TRB=1: B[k*ldb + n] (NN via ldmatrix.trans)
// BM=256, BN=64, BK=32, 256 thr (8 warps = 4m x 2n, warp tile 64x32).
// 4-stage cp.async pipeline; ldmatrix fragment loads.
// =====================================================================
#define ST_BYTES 20480
#define B_OFF    16384
#define GH_SMEM  (4*ST_BYTES)

template<typename CT, int TRB>
__global__ void __launch_bounds__(256, 2)
gemm_ha(const __half* __restrict__ A, const __half* __restrict__ B,
        CT* __restrict__ C, int Kpart, int lda, int ldb, int ldc,
        long sA, long sB, long sC, int ksplit)
{
    extern __shared__ __align__(16) char smem[];
    const uint32_t sb = smem_u32(smem);

    const int tid  = threadIdx.x;
    const int w    = tid >> 5;
    const int lane = tid & 31;
    const int g    = lane >> 2;
    const int tg   = lane & 3;
    const int wm   = (w >> 1) * 64;
    const int wn   = (w & 1) * 32;

    const int batch = blockIdx.z / ksplit;
    const int part  = blockIdx.z % ksplit;
    const int bn    = blockIdx.x * 64;
    A += (long)batch*sA + (long)part*Kpart;
    if (TRB == 0) B += (long)batch*sB + (long)part*Kpart;
    else          B += (long)batch*sB + (long)part*Kpart*ldb;
    C += (long)blockIdx.z*sC;

    // ---- cp.async coordinates ----
    const int kc = tid & 3;
    const int ar = tid >> 2;
    const __half* aP = A + (long)ar*lda + kc*8;
    const long aStride64 = (long)64*lda;
    const uint32_t aDst0 = (uint32_t)(ar*64 + ((kc ^ ((ar>>1)&3)) << 4));

    const __half* bP;
    uint32_t bDst;
    if (TRB == 0) {
        bP   = B + (long)(bn + ar)*ldb + kc*8;
        bDst = (uint32_t)(B_OFF + ar*64 + ((kc ^ ((ar>>1)&3)) << 4));
    } else {
        const int kr = tid >> 3;      // 0..31 k-row
        const int cc = tid & 7;       // 16B col chunk
        bP   = B + (long)kr*ldb + bn + cc*8;
        bDst = (uint32_t)(B_OFF + kr*128 + ((cc ^ (kr & 7)) << 4));
    }

    // ---- ldmatrix offsets ----
    uint32_t aLd[2], bLd[2][2];
    {
        const int mrow = wm + (lane & 7) + ((lane >> 3) & 1) * 8;
        const int msel = (mrow >> 1) & 3;
#pragma unroll
        for (int s = 0; s < 2; s++) {
            const int kcc = 2*s + (lane >> 4);
            aLd[s] = (uint32_t)(mrow*64 + ((kcc ^ msel) << 4));
        }
        if (TRB == 0) {
            const int nrow = wn + (lane & 7) + ((lane >> 4) << 3);
            const int nsel = (nrow >> 1) & 3;
#pragma unroll
            for (int s = 0; s < 2; s++) {
                const int kcc = 2*s + ((lane >> 3) & 1);
                bLd[s][0] = (uint32_t)(B_OFF + nrow*64 + ((kcc ^ nsel) << 4));
                bLd[s][1] = bLd[s][0] + 1024;   // n + 16 rows
            }
        } else {
            // trans: tiles per x4 call: t = lane>>3
            //   k = s*16 + ((lane>>3)&1)*8 + (lane&7), n8 = wn/8 + (lane>>4) + 2*c
#pragma unroll
            for (int s = 0; s < 2; s++) {
                const int krow = s*16 + ((lane >> 3) & 1)*8 + (lane & 7);
#pragma unroll
                for (int c = 0; c < 2; c++) {
                    const int n8 = (wn >> 3) + (lane >> 4) + 2*c;
                    bLd[s][c] = (uint32_t)(B_OFF + krow*128 + ((n8 ^ (krow & 7)) << 4));
                }
            }
        }
    }

    float acc[4][4][4];
#pragma unroll
    for (int i = 0; i < 4; i++)
#pragma unroll
        for (int j = 0; j < 4; j++)
#pragma unroll
            for (int r = 0; r < 4; r++) acc[i][j][r] = 0.f;

    const int chunks = Kpart / 32;

    auto issue = [&](int slot) {
        const uint32_t base = sb + slot*ST_BYTES;
#pragma unroll
        for (int i = 0; i < 4; i++)
            CP_ASYNC16(base + aDst0 + i*4096, aP + i*aStride64);
        CP_ASYNC16(base + bDst, bP);
        aP += 32;
        bP += (TRB == 0) ? 32 : (long)32*ldb;
    };

    issue(0); CP_COMMIT();
    issue(1); CP_COMMIT();
    issue(2); CP_COMMIT();

    for (int c = 0; c < chunks; c++) {
        CP_WAIT2();
        __syncthreads();
        if (c + 3 < chunks) issue((c + 3) & 3);
        CP_COMMIT();

        const uint32_t base = sb + (c & 3)*ST_BYTES;
#pragma unroll
        for (int s = 0; s < 2; s++) {
            unsigned af[4][4], bq[8];
#pragma unroll
            for (int mt = 0; mt < 4; mt++)
                LDSM4(af[mt], base + aLd[s] + mt*1024);
            if (TRB == 0) {
                LDSM4(bq + 0, base + bLd[s][0]);
                LDSM4(bq + 4, base + bLd[s][1]);
            } else {
                LDSM4_T(bq + 0, base + bLd[s][0]);
                LDSM4_T(bq + 4, base + bLd[s][1]);
            }
#pragma unroll
            for (int i = 0; i < 4; i++)
#pragma unroll
                for (int j = 0; j < 4; j++)
                    mma_f16(acc[i][j], af[i], &bq[j*2]);
        }
    }

    // epilogue
#pragma unroll
    for (int i = 0; i < 4; i++) {
        const int row0 = wm + i*16 + g;
#pragma unroll
        for (int j = 0; j < 4; j++) {
            const int col = bn + wn + j*8 + 2*tg;
            if (sizeof(CT) == 4) {
                *reinterpret_cast<float2*>(&((float*)C)[(long)row0*ldc + col]) =
                    make_float2(acc[i][j][0], acc[i][j][1]);
                *reinterpret_cast<float2*>(&((float*)C)[(long)(row0 + 8)*ldc + col]) =
                    make_float2(acc[i][j][2], acc[i][j][3]);
            } else {
                *reinterpret_cast<__half2*>(&((__half*)C)[(long)row0*ldc + col]) =
                    __floats2half2_rn(acc[i][j][0], acc[i][j][1]);
                *reinterpret_cast<__half2*>(&((__half*)C)[(long)(row0 + 8)*ldc + col]) =
                    __floats2half2_rn(acc[i][j][2], acc[i][j][3]);
            }
        }
    }
}

// =====================================================================
// f32 -> half (same layout), uint4 stores
// =====================================================================
__global__ void tohalf_kernel(const float4* __restrict__ src, uint4* __restrict__ dst, int n8)
{
    for (int i = blockIdx.x*blockDim.x + threadIdx.x; i < n8; i += gridDim.x*blockDim.x) {
        float4 v0 = src[2*i], v1 = src[2*i+1];
        __half2 a = __floats2half2_rn(v0.x, v0.y);
        __half2 b = __floats2half2_rn(v0.z, v0.w);
        __half2 c = __floats2half2_rn(v1.x, v1.y);
        __half2 d = __floats2half2_rn(v1.z, v1.w);
        uint4 o;
        o.x = *reinterpret_cast<unsigned*>(&a);
        o.y = *reinterpret_cast<unsigned*>(&b);
        o.z = *reinterpret_cast<unsigned*>(&c);
        o.w = *reinterpret_cast<unsigned*>(&d);
        dst[i] = o;
    }
}

// =====================================================================
// fp32 FFMA NT GEMM for small projections K1/K7
// =====================================================================
template<int BM,int BN,int BK,int TM,int TN,bool BIAS>
__global__ void __launch_bounds__((BM/TM)*(BN/TN))
gemm_nt(const float* __restrict__ A, const float* __restrict__ Bm,
        const float* __restrict__ bias, float* __restrict__ C,
        int K, int lda, int ldb, int ldc)
{
    constexpr int TX = BN/TN, TY = BM/TM, NT = TX*TY;
    const int tid = threadIdx.x;
    const int tx  = tid % TX, ty = tid / TX;
    const int bm  = blockIdx.y*BM, bn = blockIdx.x*BN;

    __shared__ float As[BK][BM+4];
    __shared__ float Bs[BK][BN+4];

    float acc[TM][TN];
#pragma unroll
    for (int i=0;i<TM;i++)
#pragma unroll
        for (int j=0;j<TN;j++) acc[i][j] = 0.f;

    for (int k0 = 0; k0 < K; k0 += BK) {
#pragma unroll
        for (int i = tid; i < BM*BK/4; i += NT) {
            int m  = i / (BK/4);
            int k4 = (i % (BK/4)) * 4;
            float4 v = *reinterpret_cast<const float4*>(&A[(long)(bm+m)*lda + k0 + k4]);
            As[k4+0][m] = v.x; As[k4+1][m] = v.y; As[k4+2][m] = v.z; As[k4+3][m] = v.w;
        }
#pragma unroll
        for (int i = tid; i < BN*BK/4; i += NT) {
            int n  = i / (BK/4);
            int k4 = (i % (BK/4)) * 4;
            float4 v = *reinterpret_cast<const float4*>(&Bm[(long)(bn+n)*ldb + k0 + k4]);
            Bs[k4+0][n] = v.x; Bs[k4+1][n] = v.y; Bs[k4+2][n] = v.z; Bs[k4+3][n] = v.w;
        }
        __syncthreads();
#pragma unroll
        for (int k = 0; k < BK; k++) {
            float af[TM], bf[TN];
#pragma unroll
            for (int i=0;i<TM;i+=4)
                *reinterpret_cast<float4*>(&af[i]) =
                    *reinterpret_cast<const float4*>(&As[k][ty*TM + i]);
#pragma unroll
            for (int j=0;j<TN;j+=4)
                *reinterpret_cast<float4*>(&bf[j]) =
                    *reinterpret_cast<const float4*>(&Bs[k][tx*TN + j]);
#pragma unroll
            for (int i=0;i<TM;i++)
#pragma unroll
                for (int j=0;j<TN;j++)
                    acc[i][j] = fmaf(af[i], bf[j], acc[i][j]);
        }
        __syncthreads();
    }

#pragma unroll
    for (int i=0;i<TM;i++) {
        const int m = bm + ty*TM + i;
        float* crow = &C[(long)m*ldc + bn + tx*TN];
#pragma unroll
        for (int j=0;j<TN;j+=4) {
            float4 v;
            v.x = acc[i][j+0]; v.y = acc[i][j+1]; v.z = acc[i][j+2]; v.w = acc[i][j+3];
            if (BIAS) {
                const float* bp = &bias[bn + tx*TN + j];
                v.x += bp[0]; v.y += bp[1]; v.z += bp[2]; v.w += bp[3];
            }
            *reinterpret_cast<float4*>(&crow[j]) = v;
        }
    }
}

// =====================================================================
// qk = scale * q_h @ Wk_h -> half (transposed smem, broadcast LDS.128)
// =====================================================================
__global__ void qk_kernel(const float* __restrict__ q,
                          const float* __restrict__ Wk,
                          __half* __restrict__ qkh)
{
    const int bh = blockIdx.y;
    const int b = bh >> 4, h = bh & 15;
    const int col = blockIdx.x*128 + threadIdx.x;
    __shared__ __align__(16) float at[HDIM][LQ];
    for (int i = threadIdx.x; i < LQ*HDIM; i += 128) {
        int qq = i >> 6, e = i & 63;
        at[e][qq] = q[(b*LQ + qq)*HID + h*HDIM + e];
    }
    __syncthreads();
    float acc[LQ];
#pragma unroll
    for (int i = 0; i < LQ; i++) acc[i] = 0.f;
#pragma unroll 4
    for (int e = 0; e < HDIM; e++) {
        const float wv = Wk[(h*HDIM + e)*HID + col];
        float4 a0 = *reinterpret_cast<const float4*>(&at[e][0]);
        float4 a1 = *reinterpret_cast<const float4*>(&at[e][4]);
        float4 a2 = *reinterpret_cast<const float4*>(&at[e][8]);
        float4 a3 = *reinterpret_cast<const float4*>(&at[e][12]);
        acc[0]  = fmaf(a0.x, wv, acc[0]);  acc[1]  = fmaf(a0.y, wv, acc[1]);
        acc[2]  = fmaf(a0.z, wv, acc[2]);  acc[3]  = fmaf(a0.w, wv, acc[3]);
        acc[4]  = fmaf(a1.x, wv, acc[4]);  acc[5]  = fmaf(a1.y, wv, acc[5]);
        acc[6]  = fmaf(a1.z, wv, acc[6]);  acc[7]  = fmaf(a1.w, wv, acc[7]);
        acc[8]  = fmaf(a2.x, wv, acc[8]);  acc[9]  = fmaf(a2.y, wv, acc[9]);
        acc[10] = fmaf(a2.z, wv, acc[10]); acc[11] = fmaf(a2.w, wv, acc[11]);
        acc[12] = fmaf(a3.x, wv, acc[12]); acc[13] = fmaf(a3.y, wv, acc[13]);
        acc[14] = fmaf(a3.z, wv, acc[14]); acc[15] = fmaf(a3.w, wv, acc[15]);
    }
    const float scale = 0.125f;
#pragma unroll
    for (int qq = 0; qq < LQ; qq++)
        qkh[((long)b*RPB + h*LQ + qq)*HID + col] = __float2half_rn(acc[qq] * scale);
}

// =====================================================================
// softmax: half logits in, half probs out (fp32 math via smem staging)
// =====================================================================
__global__ void softmax_kernel(const __half* __restrict__ logits, __half* __restrict__ probs)
{
    const size_t row = blockIdx.x;
    const uint4* p4 = reinterpret_cast<const uint4*>(logits + row * (size_t)LK);
    __half2*     o2 = reinterpret_cast<__half2*>(probs + row * (size_t)LK);
    __shared__ float buf[LK];
    __shared__ float red[8];
    const int tid = threadIdx.x;
    const int lane = tid & 31, warp = tid >> 5;
    float4* b4 = reinterpret_cast<float4*>(buf);

    float mx = -3.0e38f;
    for (int i = tid; i < LK/8; i += 256) {
        uint4 u = p4[i];
        float2 f0 = __half22float2(*reinterpret_cast<__half2*>(&u.x));
        float2 f1 = __half22float2(*reinterpret_cast<__half2*>(&u.y));
        float2 f2 = __half22float2(*reinterpret_cast<__half2*>(&u.z));
        float2 f3 = __half22float2(*reinterpret_cast<__half2*>(&u.w));
        b4[2*i]   = make_float4(f0.x, f0.y, f1.x, f1.y);
        b4[2*i+1] = make_float4(f2.x, f2.y, f3.x, f3.y);
        mx = fmaxf(mx, fmaxf(fmaxf(f0.x,f0.y), fmaxf(f1.x,f1.y)));
        mx = fmaxf(mx, fmaxf(fmaxf(f2.x,f2.y), fmaxf(f3.x,f3.y)));
    }
#pragma unroll
    for (int o=16;o;o>>=1) mx = fmaxf(mx, __shfl_xor_sync(0xffffffffu, mx, o));
    if (lane==0) red[warp] = mx;
    __syncthreads();
    mx = red[0];
#pragma unroll
    for (int w=1;w<8;w++) mx = fmaxf(mx, red[w]);

    float sum = 0.f;
    for (int i = tid; i < LK/4; i += 256) {
        float4 v = b4[i];
        v.x = expf(v.x - mx); v.y = expf(v.y - mx);
        v.z = expf(v.z - mx); v.w = expf(v.w - mx);
        b4[i] = v;
        sum += (v.x + v.y) + (v.z + v.w);
    }
#pragma unroll
    for (int o=16;o;o>>=1) sum += __shfl_xor_sync(0xffffffffu, sum, o);
    __syncthreads();
    if (lane==0) red[warp] = sum;
    __syncthreads();
    sum = 0.f;
#pragma unroll
    for (int w=0;w<8;w++) sum += red[w];
    const float inv = 1.f / sum;

    for (int i = tid; i < LK/4; i += 256) {
        float4 v = b4[i];
        o2[2*i]   = __floats2half2_rn(v.x*inv, v.y*inv);
        o2[2*i+1] = __floats2half2_rn(v.z*inv, v.w*inv);
    }
}

// =====================================================================
// attn = (ctx slab A + slab B) @ Wv_h^T + bv, per (b,h)
// =====================================================================
__global__ void attnv_kernel(const float* __restrict__ ctx,
                             const float* __restrict__ Wv,
                             const float* __restrict__ bv,
                             float* __restrict__ attn)
{
    const int bh = blockIdx.x;
    const int b = bh >> 4, h = bh & 15;
    const int t = threadIdx.x;
    const int d = t & 63, qg = t >> 6;
    __shared__ float cs[LQ][129];
    __shared__ float ws[HDIM][129];
    float acc[4] = {0.f,0.f,0.f,0.f};

    const long rowA = (long)(b*2    )*RPB + h*LQ;
    const long rowB = (long)(b*2 + 1)*RPB + h*LQ;

    for (int e0 = 0; e0 < HID; e0 += 128) {
        __syncthreads();
        for (int i = t; i < LQ*128; i += 256) {
            int qq = i >> 7, e = i & 127;
            cs[qq][e] = ctx[(rowA + qq)*HID + e0 + e] + ctx[(rowB + qq)*HID + e0 + e];
        }
        for (int i = t; i < HDIM*128; i += 256) {
            int dd = i >> 7, e = i & 127;
            ws[dd][e] = Wv[(long)(h*HDIM + dd)*HID + e0 + e];
        }
        __syncthreads();
#pragma unroll 4
        for (int e = 0; e < 128; e++) {
            float wv = ws[d][e];
#pragma unroll
            for (int j = 0; j < 4; j++)
                acc[j] = fmaf(cs[qg*4 + j][e], wv, acc[j]);
        }
    }
    const float bvv = bv[h*HDIM + d];
#pragma unroll
    for (int j = 0; j < 4; j++)
        attn[(long)(b*LQ + qg*4 + j)*HID + h*HDIM + d] = acc[j] + bvv;
}

// =====================================================================
// launch  (K3 gemm_ha stays the 4th launch -> profiled)
// =====================================================================
extern "C" void kernel_launch(void* const* d_in, const int* in_sizes, int n_in,
                              void* d_out, int out_size)
{
    const float* query = (const float*)d_in[0];
    const float* key   = (const float*)d_in[1];
    const float* value = (const float*)d_in[2];
    const float* Wq    = (const float*)d_in[3];
    const float* bq    = (const float*)d_in[4];
    const float* Wk    = (const float*)d_in[5];
    /* bk = d_in[6] : softmax-invariant, dropped */
    const float* Wv    = (const float*)d_in[7];
    const float* bv    = (const float*)d_in[8];
    const float* Wo    = (const float*)d_in[9];
    const float* bo    = (const float*)d_in[10];
    float* out = (float*)d_out;

    float *gq, *gctx, *gattn;
    __half *gqkh, *glogh, *gph, *gkh, *gvh;
    cudaGetSymbolAddress((void**)&gq,    g_q);
    cudaGetSymbolAddress((void**)&gqkh,  g_qkh);
    cudaGetSymbolAddress((void**)&glogh, g_logh);
    cudaGetSymbolAddress((void**)&gph,   g_ph);
    cudaGetSymbolAddress((void**)&gkh,   g_kh);
    cudaGetSymbolAddress((void**)&gvh,   g_vh);
    cudaGetSymbolAddress((void**)&gctx,  g_ctx);
    cudaGetSymbolAddress((void**)&gattn, g_attn);

    cudaFuncSetAttribute((const void*)gemm_ha<__half,0>, cudaFuncAttributeMaxDynamicSharedMemorySize, GH_SMEM);
    cudaFuncSetAttribute((const void*)gemm_ha<float,1>,  cudaFuncAttributeMaxDynamicSharedMemorySize, GH_SMEM);

    // #1  K1: q = query @ Wq^T + bq (fp32)
    gemm_nt<64,64,16,4,4,true><<<dim3(HID/64, (BB*LQ)/64), 256>>>(
        query, Wq, bq, gq, HID, HID, HID, HID);

    // #2  K2: qk = scale * q_h @ Wk_h -> half
    qk_kernel<<<dim3(HID/128, BB*NHEAD), 128>>>(gq, Wk, gqkh);

    // #3  key -> half
    tohalf_kernel<<<1024, 256>>>((const float4*)key, (uint4*)gkh, BB*LK*HID/8);

    // #4  K3: logits(half) = qkh @ kh^T  [256 x 8192] per batch, K=1024  (PROFILED)
    gemm_ha<__half,0><<<dim3(LK/64, 1, BB), 256, GH_SMEM>>>(
        gqkh, gkh, glogh, HID, HID, HID, LK,
        (long)RPB*HID, (long)LK*HID, (long)RPB*LK, 1);

    // #5  value -> half (native [k][n] layout)
    tohalf_kernel<<<1024, 256>>>((const float4*)value, (uint4*)gvh, BB*LK*HID/8);

    // #6  K4: softmax half -> half probs
    softmax_kernel<<<BB*RPB, 256>>>(glogh, gph);

    // #7  K5: ctx = ph @ vh (NN via ldmatrix.trans)  [256 x 1024] per batch, K=8192, split-K=2
    gemm_ha<float,1><<<dim3(HID/64, 1, BB*2), 256, GH_SMEM>>>(
        gph, gvh, gctx, LK/2, LK, HID, HID,
        (long)RPB*LK, (long)LK*HID, (long)RPB*HID, 2);

    // #8  K6: attn = ctx @ Wv_h^T + bv
    attnv_kernel<<<BB*NHEAD, 256>>>(gctx, Wv, bv, gattn);

    // #9  K7: out = attn @ Wo^T + bo
    gemm_nt<64,64,16,4,4,true><<<dim3(HID/64, (BB*LQ)/64), 256>>>(
        gattn, Wo, bo, out, HID, HID, HID, HID);
}

// round 10
// speedup vs baseline: 2.4778x; 1.0144x over previous
#include <cuda_runtime.h>
#include <cuda_fp16.h>
#include <cstdint>
#include <math.h>

#define HID   1024
#define NHEAD 16
#define HDIM  64
#define BB    8
#define LQ    16
#define LK    8192
#define RPB   (NHEAD*LQ)   /* 256 rows per batch */

// ---------------- scratch ----------------
__device__ float  g_q[BB*LQ*HID];
__device__ __half g_qkh[BB*RPB*HID];
__device__ __half g_eh[(size_t)BB*RPB*LK];      // exp(logits), unnormalized
__device__ float  g_rowsum[BB*RPB];             // per-row sum of exp
__device__ __half g_kh[(size_t)BB*LK*HID];
__device__ __half g_vh[(size_t)BB*LK*HID];      // value half, native [k][n]
__device__ float  g_ctx[2*BB*RPB*HID];
__device__ float  g_attn[BB*LQ*HID];

// =====================================================================
// asm helpers
// =====================================================================
__device__ __forceinline__ uint32_t smem_u32(const void* p) {
    uint32_t a;
    asm("{ .reg .u64 t; cvta.to.shared.u64 t, %1; cvt.u32.u64 %0, t; }" : "=r"(a) : "l"(p));
    return a;
}
#define CP_ASYNC16(dst, src) \
    asm volatile("cp.async.cg.shared.global [%0], [%1], 16;" :: "r"(dst), "l"(src) : "memory")
#define CP_COMMIT()  asm volatile("cp.async.commit_group;" ::: "memory")
#define CP_WAIT2()   asm volatile("cp.async.wait_group 2;" ::: "memory")
#define LDSM4(r, addr) \
    asm volatile("ldmatrix.sync.aligned.m8n8.x4.shared.b16 {%0,%1,%2,%3}, [%4];" \
        : "=r"((r)[0]), "=r"((r)[1]), "=r"((r)[2]), "=r"((r)[3]) : "r"(addr))
#define LDSM4_T(r, addr) \
    asm volatile("ldmatrix.sync.aligned.m8n8.x4.trans.shared.b16 {%0,%1,%2,%3}, [%4];" \
        : "=r"((r)[0]), "=r"((r)[1]), "=r"((r)[2]), "=r"((r)[3]) : "r"(addr))

__device__ __forceinline__ void mma_f16(float c[4], const unsigned a[4], const unsigned b[2]) {
    asm("mma.sync.aligned.m16n8k16.row.col.f32.f16.f16.f32 "
        "{%0,%1,%2,%3}, {%4,%5,%6,%7}, {%8,%9}, {%0,%1,%2,%3};"
        : "+f"(c[0]), "+f"(c[1]), "+f"(c[2]), "+f"(c[3])
        : "r"(a[0]), "r"(a[1]), "r"(a[2]), "r"(a[3]), "r"(b[0]), "r"(b[1]));
}

// =====================================================================
// gemm_ha: half GEMM.  C[m][n] = sum_k A[m][k] * B-op
// TRB=0: B[n*ldb + k] (NT);  TRB=1: B[k*ldb + n] (NN via ldmatrix.trans)
// DOEXP=1: C = exp(acc) (half out) + per-row atomicAdd of exp-sums into
//          rowsum[blockIdx.z*RPB + row]  (fused softmax numerator).
// BM=256, BN=64, BK=32, 256 thr (8 warps = 4m x 2n, warp tile 64x32).
// 4-stage cp.async pipeline; ldmatrix fragment loads.
// =====================================================================
#define ST_BYTES 20480
#define B_OFF    16384
#define GH_SMEM  (4*ST_BYTES)

template<typename CT, int TRB, int DOEXP>
__global__ void __launch_bounds__(256, 2)
gemm_ha(const __half* __restrict__ A, const __half* __restrict__ B,
        CT* __restrict__ C, float* __restrict__ rowsum,
        int Kpart, int lda, int ldb, int ldc,
        long sA, long sB, long sC, int ksplit)
{
    extern __shared__ __align__(16) char smem[];
    const uint32_t sb = smem_u32(smem);

    const int tid  = threadIdx.x;
    const int w    = tid >> 5;
    const int lane = tid & 31;
    const int g    = lane >> 2;
    const int tg   = lane & 3;
    const int wm   = (w >> 1) * 64;
    const int wn   = (w & 1) * 32;

    const int batch = blockIdx.z / ksplit;
    const int part  = blockIdx.z % ksplit;
    const int bn    = blockIdx.x * 64;
    A += (long)batch*sA + (long)part*Kpart;
    if (TRB == 0) B += (long)batch*sB + (long)part*Kpart;
    else          B += (long)batch*sB + (long)part*Kpart*ldb;
    C += (long)blockIdx.z*sC;

    // ---- cp.async coordinates ----
    const int kc = tid & 3;
    const int ar = tid >> 2;
    const __half* aP = A + (long)ar*lda + kc*8;
    const long aStride64 = (long)64*lda;
    const uint32_t aDst0 = (uint32_t)(ar*64 + ((kc ^ ((ar>>1)&3)) << 4));

    const __half* bP;
    uint32_t bDst;
    if (TRB == 0) {
        bP   = B + (long)(bn + ar)*ldb + kc*8;
        bDst = (uint32_t)(B_OFF + ar*64 + ((kc ^ ((ar>>1)&3)) << 4));
    } else {
        const int kr = tid >> 3;
        const int cc = tid & 7;
        bP   = B + (long)kr*ldb + bn + cc*8;
        bDst = (uint32_t)(B_OFF + kr*128 + ((cc ^ (kr & 7)) << 4));
    }

    // ---- ldmatrix offsets ----
    uint32_t aLd[2], bLd[2][2];
    {
        const int mrow = wm + (lane & 7) + ((lane >> 3) & 1) * 8;
        const int msel = (mrow >> 1) & 3;
#pragma unroll
        for (int s = 0; s < 2; s++) {
            const int kcc = 2*s + (lane >> 4);
            aLd[s] = (uint32_t)(mrow*64 + ((kcc ^ msel) << 4));
        }
        if (TRB == 0) {
            const int nrow = wn + (lane & 7) + ((lane >> 4) << 3);
            const int nsel = (nrow >> 1) & 3;
#pragma unroll
            for (int s = 0; s < 2; s++) {
                const int kcc = 2*s + ((lane >> 3) & 1);
                bLd[s][0] = (uint32_t)(B_OFF + nrow*64 + ((kcc ^ nsel) << 4));
                bLd[s][1] = bLd[s][0] + 1024;
            }
        } else {
#pragma unroll
            for (int s = 0; s < 2; s++) {
                const int krow = s*16 + ((lane >> 3) & 1)*8 + (lane & 7);
#pragma unroll
                for (int c = 0; c < 2; c++) {
                    const int n8 = (wn >> 3) + (lane >> 4) + 2*c;
                    bLd[s][c] = (uint32_t)(B_OFF + krow*128 + ((n8 ^ (krow & 7)) << 4));
                }
            }
        }
    }

    float acc[4][4][4];
#pragma unroll
    for (int i = 0; i < 4; i++)
#pragma unroll
        for (int j = 0; j < 4; j++)
#pragma unroll
            for (int r = 0; r < 4; r++) acc[i][j][r] = 0.f;

    const int chunks = Kpart / 32;

    auto issue = [&](int slot) {
        const uint32_t base = sb + slot*ST_BYTES;
#pragma unroll
        for (int i = 0; i < 4; i++)
            CP_ASYNC16(base + aDst0 + i*4096, aP + i*aStride64);
        CP_ASYNC16(base + bDst, bP);
        aP += 32;
        bP += (TRB == 0) ? 32 : (long)32*ldb;
    };

    issue(0); CP_COMMIT();
    issue(1); CP_COMMIT();
    issue(2); CP_COMMIT();

    for (int c = 0; c < chunks; c++) {
        CP_WAIT2();
        __syncthreads();
        if (c + 3 < chunks) issue((c + 3) & 3);
        CP_COMMIT();

        const uint32_t base = sb + (c & 3)*ST_BYTES;
#pragma unroll
        for (int s = 0; s < 2; s++) {
            unsigned af[4][4], bq[8];
#pragma unroll
            for (int mt = 0; mt < 4; mt++)
                LDSM4(af[mt], base + aLd[s] + mt*1024);
            if (TRB == 0) {
                LDSM4(bq + 0, base + bLd[s][0]);
                LDSM4(bq + 4, base + bLd[s][1]);
            } else {
                LDSM4_T(bq + 0, base + bLd[s][0]);
                LDSM4_T(bq + 4, base + bLd[s][1]);
            }
#pragma unroll
            for (int i = 0; i < 4; i++)
#pragma unroll
                for (int j = 0; j < 4; j++)
                    mma_f16(acc[i][j], af[i], &bq[j*2]);
        }
    }

    // ---- epilogue ----
#pragma unroll
    for (int i = 0; i < 4; i++) {
        const int row0 = wm + i*16 + g;
        float s0 = 0.f, s1 = 0.f;
#pragma unroll
        for (int j = 0; j < 4; j++) {
            const int col = bn + wn + j*8 + 2*tg;
            if (DOEXP) {
                float e0 = expf(acc[i][j][0]);
                float e1 = expf(acc[i][j][1]);
                float e2 = expf(acc[i][j][2]);
                float e3 = expf(acc[i][j][3]);
                s0 += e0 + e1;  s1 += e2 + e3;
                *reinterpret_cast<__half2*>(&((__half*)C)[(long)row0*ldc + col]) =
                    __floats2half2_rn(e0, e1);
                *reinterpret_cast<__half2*>(&((__half*)C)[(long)(row0 + 8)*ldc + col]) =
                    __floats2half2_rn(e2, e3);
            } else if (sizeof(CT) == 4) {
                *reinterpret_cast<float2*>(&((float*)C)[(long)row0*ldc + col]) =
                    make_float2(acc[i][j][0], acc[i][j][1]);
                *reinterpret_cast<float2*>(&((float*)C)[(long)(row0 + 8)*ldc + col]) =
                    make_float2(acc[i][j][2], acc[i][j][3]);
            } else {
                *reinterpret_cast<__half2*>(&((__half*)C)[(long)row0*ldc + col]) =
                    __floats2half2_rn(acc[i][j][0], acc[i][j][1]);
                *reinterpret_cast<__half2*>(&((__half*)C)[(long)(row0 + 8)*ldc + col]) =
                    __floats2half2_rn(acc[i][j][2], acc[i][j][3]);
            }
        }
        if (DOEXP) {
            // reduce across the quad (lanes 4g..4g+3 share rows row0/row0+8)
            s0 += __shfl_xor_sync(0xffffffffu, s0, 1);
            s0 += __shfl_xor_sync(0xffffffffu, s0, 2);
            s1 += __shfl_xor_sync(0xffffffffu, s1, 1);
            s1 += __shfl_xor_sync(0xffffffffu, s1, 2);
            if (tg == 0) {
                float* rs = rowsum + (long)blockIdx.z * RPB;
                atomicAdd(&rs[row0],     s0);
                atomicAdd(&rs[row0 + 8], s1);
            }
        }
    }
}

// =====================================================================
// key & value f32 -> half (same layouts), one kernel, uint4 stores
// =====================================================================
__global__ void tohalf2_kernel(const float4* __restrict__ s1, uint4* __restrict__ d1,
                               const float4* __restrict__ s2, uint4* __restrict__ d2,
                               int n8)
{
    for (int i = blockIdx.x*blockDim.x + threadIdx.x; i < n8; i += gridDim.x*blockDim.x) {
        float4 v0 = s1[2*i], v1 = s1[2*i+1];
        __half2 a = __floats2half2_rn(v0.x, v0.y);
        __half2 b = __floats2half2_rn(v0.z, v0.w);
        __half2 c = __floats2half2_rn(v1.x, v1.y);
        __half2 d = __floats2half2_rn(v1.z, v1.w);
        uint4 o;
        o.x = *reinterpret_cast<unsigned*>(&a);
        o.y = *reinterpret_cast<unsigned*>(&b);
        o.z = *reinterpret_cast<unsigned*>(&c);
        o.w = *reinterpret_cast<unsigned*>(&d);
        d1[i] = o;
        v0 = s2[2*i]; v1 = s2[2*i+1];
        a = __floats2half2_rn(v0.x, v0.y);
        b = __floats2half2_rn(v0.z, v0.w);
        c = __floats2half2_rn(v1.x, v1.y);
        d = __floats2half2_rn(v1.z, v1.w);
        o.x = *reinterpret_cast<unsigned*>(&a);
        o.y = *reinterpret_cast<unsigned*>(&b);
        o.z = *reinterpret_cast<unsigned*>(&c);
        o.w = *reinterpret_cast<unsigned*>(&d);
        d2[i] = o;
    }
}

// =====================================================================
// fp32 FFMA NT GEMM for small projections K1/K7
// =====================================================================
template<int BM,int BN,int BK,int TM,int TN,bool BIAS>
__global__ void __launch_bounds__((BM/TM)*(BN/TN))
gemm_nt(const float* __restrict__ A, const float* __restrict__ Bm,
        const float* __restrict__ bias, float* __restrict__ C,
        int K, int lda, int ldb, int ldc)
{
    constexpr int TX = BN/TN, TY = BM/TM, NT = TX*TY;
    const int tid = threadIdx.x;
    const int tx  = tid % TX, ty = tid / TX;
    const int bm  = blockIdx.y*BM, bn = blockIdx.x*BN;

    __shared__ float As[BK][BM+4];
    __shared__ float Bs[BK][BN+4];

    float acc[TM][TN];
#pragma unroll
    for (int i=0;i<TM;i++)
#pragma unroll
        for (int j=0;j<TN;j++) acc[i][j] = 0.f;

    for (int k0 = 0; k0 < K; k0 += BK) {
#pragma unroll
        for (int i = tid; i < BM*BK/4; i += NT) {
            int m  = i / (BK/4);
            int k4 = (i % (BK/4)) * 4;
            float4 v = *reinterpret_cast<const float4*>(&A[(long)(bm+m)*lda + k0 + k4]);
            As[k4+0][m] = v.x; As[k4+1][m] = v.y; As[k4+2][m] = v.z; As[k4+3][m] = v.w;
        }
#pragma unroll
        for (int i = tid; i < BN*BK/4; i += NT) {
            int n  = i / (BK/4);
            int k4 = (i % (BK/4)) * 4;
            float4 v = *reinterpret_cast<const float4*>(&Bm[(long)(bn+n)*ldb + k0 + k4]);
            Bs[k4+0][n] = v.x; Bs[k4+1][n] = v.y; Bs[k4+2][n] = v.z; Bs[k4+3][n] = v.w;
        }
        __syncthreads();
#pragma unroll
        for (int k = 0; k < BK; k++) {
            float af[TM], bf[TN];
#pragma unroll
            for (int i=0;i<TM;i+=4)
                *reinterpret_cast<float4*>(&af[i]) =
                    *reinterpret_cast<const float4*>(&As[k][ty*TM + i]);
#pragma unroll
            for (int j=0;j<TN;j+=4)
                *reinterpret_cast<float4*>(&bf[j]) =
                    *reinterpret_cast<const float4*>(&Bs[k][tx*TN + j]);
#pragma unroll
            for (int i=0;i<TM;i++)
#pragma unroll
                for (int j=0;j<TN;j++)
                    acc[i][j] = fmaf(af[i], bf[j], acc[i][j]);
        }
        __syncthreads();
    }

#pragma unroll
    for (int i=0;i<TM;i++) {
        const int m = bm + ty*TM + i;
        float* crow = &C[(long)m*ldc + bn + tx*TN];
#pragma unroll
        for (int j=0;j<TN;j+=4) {
            float4 v;
            v.x = acc[i][j+0]; v.y = acc[i][j+1]; v.z = acc[i][j+2]; v.w = acc[i][j+3];
            if (BIAS) {
                const float* bp = &bias[bn + tx*TN + j];
                v.x += bp[0]; v.y += bp[1]; v.z += bp[2]; v.w += bp[3];
            }
            *reinterpret_cast<float4*>(&crow[j]) = v;
        }
    }
}

// =====================================================================
// qk = scale * q_h @ Wk_h -> half; also zeroes g_rowsum (runs before K3)
// =====================================================================
__global__ void qk_kernel(const float* __restrict__ q,
                          const float* __restrict__ Wk,
                          __half* __restrict__ qkh,
                          float* __restrict__ rowsum)
{
    const int bh = blockIdx.y;
    const int b = bh >> 4, h = bh & 15;
    const int col = blockIdx.x*128 + threadIdx.x;
    if (blockIdx.x == 0 && bh == 0) {
#pragma unroll
        for (int r = 0; r < BB*RPB/128; r++)
            rowsum[r*128 + threadIdx.x] = 0.f;
    }
    __shared__ __align__(16) float at[HDIM][LQ];
    for (int i = threadIdx.x; i < LQ*HDIM; i += 128) {
        int qq = i >> 6, e = i & 63;
        at[e][qq] = q[(b*LQ + qq)*HID + h*HDIM + e];
    }
    __syncthreads();
    float acc[LQ];
#pragma unroll
    for (int i = 0; i < LQ; i++) acc[i] = 0.f;
#pragma unroll 4
    for (int e = 0; e < HDIM; e++) {
        const float wv = Wk[(h*HDIM + e)*HID + col];
        float4 a0 = *reinterpret_cast<const float4*>(&at[e][0]);
        float4 a1 = *reinterpret_cast<const float4*>(&at[e][4]);
        float4 a2 = *reinterpret_cast<const float4*>(&at[e][8]);
        float4 a3 = *reinterpret_cast<const float4*>(&at[e][12]);
        acc[0]  = fmaf(a0.x, wv, acc[0]);  acc[1]  = fmaf(a0.y, wv, acc[1]);
        acc[2]  = fmaf(a0.z, wv, acc[2]);  acc[3]  = fmaf(a0.w, wv, acc[3]);
        acc[4]  = fmaf(a1.x, wv, acc[4]);  acc[5]  = fmaf(a1.y, wv, acc[5]);
        acc[6]  = fmaf(a1.z, wv, acc[6]);  acc[7]  = fmaf(a1.w, wv, acc[7]);
        acc[8]  = fmaf(a2.x, wv, acc[8]);  acc[9]  = fmaf(a2.y, wv, acc[9]);
        acc[10] = fmaf(a2.z, wv, acc[10]); acc[11] = fmaf(a2.w, wv, acc[11]);
        acc[12] = fmaf(a3.x, wv, acc[12]); acc[13] = fmaf(a3.y, wv, acc[13]);
        acc[14] = fmaf(a3.z, wv, acc[14]); acc[15] = fmaf(a3.w, wv, acc[15]);
    }
    const float scale = 0.125f;
#pragma unroll
    for (int qq = 0; qq < LQ; qq++)
        qkh[((long)b*RPB + h*LQ + qq)*HID + col] = __float2half_rn(acc[qq] * scale);
}

// =====================================================================
// attn = inv_rowsum * (ctx slab A + slab B) @ Wv_h^T + bv, per (b,h)
// =====================================================================
__global__ void attnv_kernel(const float* __restrict__ ctx,
                             const float* __restrict__ rowsum,
                             const float* __restrict__ Wv,
                             const float* __restrict__ bv,
                             float* __restrict__ attn)
{
    const int bh = blockIdx.x;
    const int b = bh >> 4, h = bh & 15;
    const int t = threadIdx.x;
    const int d = t & 63, qg = t >> 6;
    __shared__ float cs[LQ][129];
    __shared__ float ws[HDIM][129];
    __shared__ float inv[LQ];
    float acc[4] = {0.f,0.f,0.f,0.f};

    if (t < LQ) inv[t] = 1.f / rowsum[b*RPB + h*LQ + t];

    const long rowA = (long)(b*2    )*RPB + h*LQ;
    const long rowB = (long)(b*2 + 1)*RPB + h*LQ;

    for (int e0 = 0; e0 < HID; e0 += 128) {
        __syncthreads();
        for (int i = t; i < LQ*128; i += 256) {
            int qq = i >> 7, e = i & 127;
            cs[qq][e] = (ctx[(rowA + qq)*HID + e0 + e] + ctx[(rowB + qq)*HID + e0 + e]) * inv[qq];
        }
        for (int i = t; i < HDIM*128; i += 256) {
            int dd = i >> 7, e = i & 127;
            ws[dd][e] = Wv[(long)(h*HDIM + dd)*HID + e0 + e];
        }
        __syncthreads();
#pragma unroll 4
        for (int e = 0; e < 128; e++) {
            float wv = ws[d][e];
#pragma unroll
            for (int j = 0; j < 4; j++)
                acc[j] = fmaf(cs[qg*4 + j][e], wv, acc[j]);
        }
    }
    const float bvv = bv[h*HDIM + d];
#pragma unroll
    for (int j = 0; j < 4; j++)
        attn[(long)(b*LQ + qg*4 + j)*HID + h*HDIM + d] = acc[j] + bvv;
}

// =====================================================================
// launch  (K3 gemm_ha stays the 4th launch -> profiled)
// =====================================================================
extern "C" void kernel_launch(void* const* d_in, const int* in_sizes, int n_in,
                              void* d_out, int out_size)
{
    const float* query = (const float*)d_in[0];
    const float* key   = (const float*)d_in[1];
    const float* value = (const float*)d_in[2];
    const float* Wq    = (const float*)d_in[3];
    const float* bq    = (const float*)d_in[4];
    const float* Wk    = (const float*)d_in[5];
    /* bk = d_in[6] : softmax-invariant, dropped */
    const float* Wv    = (const float*)d_in[7];
    const float* bv    = (const float*)d_in[8];
    const float* Wo    = (const float*)d_in[9];
    const float* bo    = (const float*)d_in[10];
    float* out = (float*)d_out;

    float *gq, *gctx, *gattn, *grs;
    __half *gqkh, *geh, *gkh, *gvh;
    cudaGetSymbolAddress((void**)&gq,    g_q);
    cudaGetSymbolAddress((void**)&gqkh,  g_qkh);
    cudaGetSymbolAddress((void**)&geh,   g_eh);
    cudaGetSymbolAddress((void**)&grs,   g_rowsum);
    cudaGetSymbolAddress((void**)&gkh,   g_kh);
    cudaGetSymbolAddress((void**)&gvh,   g_vh);
    cudaGetSymbolAddress((void**)&gctx,  g_ctx);
    cudaGetSymbolAddress((void**)&gattn, g_attn);

    cudaFuncSetAttribute((const void*)gemm_ha<__half,0,1>, cudaFuncAttributeMaxDynamicSharedMemorySize, GH_SMEM);
    cudaFuncSetAttribute((const void*)gemm_ha<float,1,0>,  cudaFuncAttributeMaxDynamicSharedMemorySize, GH_SMEM);

    // #1  K1: q = query @ Wq^T + bq (fp32)
    gemm_nt<64,64,16,4,4,true><<<dim3(HID/64, (BB*LQ)/64), 256>>>(
        query, Wq, bq, gq, HID, HID, HID, HID);

    // #2  K2: qk = scale * q_h @ Wk_h -> half  (also zeroes rowsum)
    qk_kernel<<<dim3(HID/128, BB*NHEAD), 128>>>(gq, Wk, gqkh, grs);

    // #3  key & value -> half
    tohalf2_kernel<<<1024, 256>>>((const float4*)key, (uint4*)gkh,
                                  (const float4*)value, (uint4*)gvh, BB*LK*HID/8);

    // #4  K3: e = exp(qkh @ kh^T) + row sums  [256 x 8192] per batch  (PROFILED)
    gemm_ha<__half,0,1><<<dim3(LK/64, 1, BB), 256, GH_SMEM>>>(
        gqkh, gkh, geh, grs, HID, HID, HID, LK,
        (long)RPB*HID, (long)LK*HID, (long)RPB*LK, 1);

    // #5  K5: ctx = e @ vh (NN via ldmatrix.trans), K=8192, split-K=2
    gemm_ha<float,1,0><<<dim3(HID/64, 1, BB*2), 256, GH_SMEM>>>(
        geh, gvh, gctx, nullptr, LK/2, LK, HID, HID,
        (long)RPB*LK, (long)LK*HID, (long)RPB*HID, 2);

    // #6  K6: attn = inv_rowsum * ctx @ Wv_h^T + bv
    attnv_kernel<<<BB*NHEAD, 256>>>(gctx, grs, Wv, bv, gattn);

    // #7  K7: out = attn @ Wo^T + bo
    gemm_nt<64,64,16,4,4,true><<<dim3(HID/64, (BB*LQ)/64), 256>>>(
        gattn, Wo, bo, out, HID, HID, HID, HID);
}

// round 11
// speedup vs baseline: 2.5286x; 1.0205x over previous
#include <cuda_runtime.h>
#include <cuda_fp16.h>
#include <cstdint>
#include <math.h>

#define HID   1024
#define NHEAD 16
#define HDIM  64
#define BB    8
#define LQ    16
#define LK    8192
#define RPB   (NHEAD*LQ)   /* 256 rows per batch */

// ---------------- scratch ----------------
__device__ float  g_q[BB*LQ*HID];
__device__ __half g_qkh[BB*RPB*HID];
__device__ __half g_eh[(size_t)BB*RPB*LK];      // exp(logits), unnormalized
__device__ float  g_rowsum[BB*RPB];             // per-row sum of exp
__device__ float  g_ctx[2*BB*RPB*HID];
__device__ float  g_attn[BB*LQ*HID];

// =====================================================================
// asm helpers
// =====================================================================
__device__ __forceinline__ uint32_t smem_u32(const void* p) {
    uint32_t a;
    asm("{ .reg .u64 t; cvta.to.shared.u64 t, %1; cvt.u32.u64 %0, t; }" : "=r"(a) : "l"(p));
    return a;
}
#define CP_ASYNC16(dst, src) \
    asm volatile("cp.async.cg.shared.global [%0], [%1], 16;" :: "r"(dst), "l"(src) : "memory")
#define CP_COMMIT()  asm volatile("cp.async.commit_group;" ::: "memory")
#define CP_WAIT2()   asm volatile("cp.async.wait_group 2;" ::: "memory")
#define LDSM4(r, addr) \
    asm volatile("ldmatrix.sync.aligned.m8n8.x4.shared.b16 {%0,%1,%2,%3}, [%4];" \
        : "=r"((r)[0]), "=r"((r)[1]), "=r"((r)[2]), "=r"((r)[3]) : "r"(addr))
#define LDSM4_T(r, addr) \
    asm volatile("ldmatrix.sync.aligned.m8n8.x4.trans.shared.b16 {%0,%1,%2,%3}, [%4];" \
        : "=r"((r)[0]), "=r"((r)[1]), "=r"((r)[2]), "=r"((r)[3]) : "r"(addr))

__device__ __forceinline__ void mma_f16(float c[4], const unsigned a[4], const unsigned b[2]) {
    asm("mma.sync.aligned.m16n8k16.row.col.f32.f16.f16.f32 "
        "{%0,%1,%2,%3}, {%4,%5,%6,%7}, {%8,%9}, {%0,%1,%2,%3};"
        : "+f"(c[0]), "+f"(c[1]), "+f"(c[2]), "+f"(c[3])
        : "r"(a[0]), "r"(a[1]), "r"(a[2]), "r"(a[3]), "r"(b[0]), "r"(b[1]));
}

// =====================================================================
// gemm_hf: A half [m][k]; B fp32 converted to half in-kernel.
// TRB=0: B[n*ldb + k] (NT);  TRB=1: B[k*ldb + n] (NN via ldmatrix.trans)
// DOEXP=1: C = exp(acc) half + per-row atomicAdd exp-sums into rowsum.
// BM=256, BN=64, BK=32, 256 thr (8 warps = 4m x 2n, warp tile 64x32).
// 4-stage cp.async (A half + B fp32 in two 4KB planes); per-chunk the
// B fp32 tile is converted into ONE swizzled half buffer (sync-guarded).
// =====================================================================
#define ST_BYTES 24576           /* per stage: A 16KB + B32 8KB */
#define B32_OFF  16384
#define BH_OFF   98304           /* single 4KB half-B buffer after 4 stages */
#define GH_SMEM  (4*ST_BYTES + 4096)

template<typename CT, int TRB, int DOEXP>
__global__ void __launch_bounds__(256, 2)
gemm_hf(const __half* __restrict__ A, const float* __restrict__ B,
        CT* __restrict__ C, float* __restrict__ rowsum,
        int Kpart, int lda, int ldb, int ldc,
        long sA, long sB, long sC, int ksplit)
{
    extern __shared__ __align__(16) char smem[];
    const uint32_t sb = smem_u32(smem);

    const int tid  = threadIdx.x;
    const int w    = tid >> 5;
    const int lane = tid & 31;
    const int g    = lane >> 2;
    const int tg   = lane & 3;
    const int wm   = (w >> 1) * 64;
    const int wn   = (w & 1) * 32;

    const int batch = blockIdx.z / ksplit;
    const int part  = blockIdx.z % ksplit;
    const int bn    = blockIdx.x * 64;
    A += (long)batch*sA + (long)part*Kpart;
    if (TRB == 0) B += (long)batch*sB + (long)part*Kpart;
    else          B += (long)batch*sB + (long)part*Kpart*ldb;
    C += (long)blockIdx.z*sC;

    // ---- cp.async coordinates ----
    const int kc = tid & 3;
    const int ar = tid >> 2;
    const __half* aP = A + (long)ar*lda + kc*8;
    const long aStride64 = (long)64*lda;
    const uint32_t aDst0 = (uint32_t)(ar*64 + ((kc ^ ((ar>>1)&3)) << 4));

    // B fp32: each thread owns one 8-float "group" per chunk, split in 2 planes.
    const float* bP;
    if (TRB == 0) bP = B + (long)(bn + (tid >> 2))*ldb + (tid & 3)*8;
    else          bP = B + (long)(tid >> 3)*ldb + bn + (tid & 7)*8;
    const uint32_t b32d0 = (uint32_t)(B32_OFF + tid*16);
    const uint32_t b32d1 = (uint32_t)(B32_OFF + 4096 + tid*16);

    // half-B destination (swizzled fragment layout)
    uint32_t bhDst;
    if (TRB == 0) {
        const int row = tid >> 2, kcc = tid & 3;
        bhDst = (uint32_t)(BH_OFF + row*64 + ((kcc ^ ((row>>1)&3)) << 4));
    } else {
        const int kr = tid >> 3, g8 = tid & 7;
        bhDst = (uint32_t)(BH_OFF + kr*128 + ((g8 ^ (kr & 7)) << 4));
    }

    // ---- ldmatrix offsets ----
    uint32_t aLd[2], bLd[2][2];
    {
        const int mrow = wm + (lane & 7) + ((lane >> 3) & 1) * 8;
        const int msel = (mrow >> 1) & 3;
#pragma unroll
        for (int s = 0; s < 2; s++) {
            const int kcc = 2*s + (lane >> 4);
            aLd[s] = (uint32_t)(mrow*64 + ((kcc ^ msel) << 4));
        }
        if (TRB == 0) {
            const int nrow = wn + (lane & 7) + ((lane >> 4) << 3);
            const int nsel = (nrow >> 1) & 3;
#pragma unroll
            for (int s = 0; s < 2; s++) {
                const int kcc = 2*s + ((lane >> 3) & 1);
                bLd[s][0] = (uint32_t)(BH_OFF + nrow*64 + ((kcc ^ nsel) << 4));
                bLd[s][1] = bLd[s][0] + 1024;
            }
        } else {
#pragma unroll
            for (int s = 0; s < 2; s++) {
                const int krow = s*16 + ((lane >> 3) & 1)*8 + (lane & 7);
#pragma unroll
                for (int c = 0; c < 2; c++) {
                    const int n8 = (wn >> 3) + (lane >> 4) + 2*c;
                    bLd[s][c] = (uint32_t)(BH_OFF + krow*128 + ((n8 ^ (krow & 7)) << 4));
                }
            }
        }
    }

    float acc[4][4][4];
#pragma unroll
    for (int i = 0; i < 4; i++)
#pragma unroll
        for (int j = 0; j < 4; j++)
#pragma unroll
            for (int r = 0; r < 4; r++) acc[i][j][r] = 0.f;

    const int chunks = Kpart / 32;

    auto issue = [&](int slot) {
        const uint32_t base = sb + slot*ST_BYTES;
#pragma unroll
        for (int i = 0; i < 4; i++)
            CP_ASYNC16(base + aDst0 + i*4096, aP + i*aStride64);
        CP_ASYNC16(base + b32d0, bP);
        CP_ASYNC16(base + b32d1, bP + 4);
        aP += 32;
        bP += (TRB == 0) ? 32 : (long)32*ldb;
    };

    issue(0); CP_COMMIT();
    issue(1); CP_COMMIT();
    issue(2); CP_COMMIT();

    for (int c = 0; c < chunks; c++) {
        CP_WAIT2();
        __syncthreads();
        if (c + 3 < chunks) issue((c + 3) & 3);
        CP_COMMIT();

        const uint32_t base = sb + (c & 3)*ST_BYTES;
        // convert this chunk's fp32 B tile -> half fragment buffer
        {
            float4 f0, f1;
            asm volatile("ld.shared.v4.f32 {%0,%1,%2,%3}, [%4];"
                : "=f"(f0.x), "=f"(f0.y), "=f"(f0.z), "=f"(f0.w) : "r"(base + b32d0));
            asm volatile("ld.shared.v4.f32 {%0,%1,%2,%3}, [%4];"
                : "=f"(f1.x), "=f"(f1.y), "=f"(f1.z), "=f"(f1.w) : "r"(base + b32d1));
            __half2 h0 = __floats2half2_rn(f0.x, f0.y);
            __half2 h1 = __floats2half2_rn(f0.z, f0.w);
            __half2 h2 = __floats2half2_rn(f1.x, f1.y);
            __half2 h3 = __floats2half2_rn(f1.z, f1.w);
            asm volatile("st.shared.v4.b32 [%0], {%1,%2,%3,%4};"
                :: "r"(sb + bhDst),
                   "r"(*reinterpret_cast<unsigned*>(&h0)),
                   "r"(*reinterpret_cast<unsigned*>(&h1)),
                   "r"(*reinterpret_cast<unsigned*>(&h2)),
                   "r"(*reinterpret_cast<unsigned*>(&h3)) : "memory");
        }
        __syncthreads();

#pragma unroll
        for (int s = 0; s < 2; s++) {
            unsigned af[4][4], bq[8];
#pragma unroll
            for (int mt = 0; mt < 4; mt++)
                LDSM4(af[mt], base + aLd[s] + mt*1024);
            if (TRB == 0) {
                LDSM4(bq + 0, sb + bLd[s][0]);
                LDSM4(bq + 4, sb + bLd[s][1]);
            } else {
                LDSM4_T(bq + 0, sb + bLd[s][0]);
                LDSM4_T(bq + 4, sb + bLd[s][1]);
            }
#pragma unroll
            for (int i = 0; i < 4; i++)
#pragma unroll
                for (int j = 0; j < 4; j++)
                    mma_f16(acc[i][j], af[i], &bq[j*2]);
        }
    }

    // ---- epilogue ----
#pragma unroll
    for (int i = 0; i < 4; i++) {
        const int row0 = wm + i*16 + g;
        float s0 = 0.f, s1 = 0.f;
#pragma unroll
        for (int j = 0; j < 4; j++) {
            const int col = bn + wn + j*8 + 2*tg;
            if (DOEXP) {
                float e0 = expf(acc[i][j][0]);
                float e1 = expf(acc[i][j][1]);
                float e2 = expf(acc[i][j][2]);
                float e3 = expf(acc[i][j][3]);
                s0 += e0 + e1;  s1 += e2 + e3;
                *reinterpret_cast<__half2*>(&((__half*)C)[(long)row0*ldc + col]) =
                    __floats2half2_rn(e0, e1);
                *reinterpret_cast<__half2*>(&((__half*)C)[(long)(row0 + 8)*ldc + col]) =
                    __floats2half2_rn(e2, e3);
            } else if (sizeof(CT) == 4) {
                *reinterpret_cast<float2*>(&((float*)C)[(long)row0*ldc + col]) =
                    make_float2(acc[i][j][0], acc[i][j][1]);
                *reinterpret_cast<float2*>(&((float*)C)[(long)(row0 + 8)*ldc + col]) =
                    make_float2(acc[i][j][2], acc[i][j][3]);
            } else {
                *reinterpret_cast<__half2*>(&((__half*)C)[(long)row0*ldc + col]) =
                    __floats2half2_rn(acc[i][j][0], acc[i][j][1]);
                *reinterpret_cast<__half2*>(&((__half*)C)[(long)(row0 + 8)*ldc + col]) =
                    __floats2half2_rn(acc[i][j][2], acc[i][j][3]);
            }
        }
        if (DOEXP) {
            s0 += __shfl_xor_sync(0xffffffffu, s0, 1);
            s0 += __shfl_xor_sync(0xffffffffu, s0, 2);
            s1 += __shfl_xor_sync(0xffffffffu, s1, 1);
            s1 += __shfl_xor_sync(0xffffffffu, s1, 2);
            if (tg == 0) {
                float* rs = rowsum + (long)blockIdx.z * RPB;
                atomicAdd(&rs[row0],     s0);
                atomicAdd(&rs[row0 + 8], s1);
            }
        }
    }
}

// =====================================================================
// fp32 FFMA NT GEMM for small projections K1/K7
// =====================================================================
template<int BM,int BN,int BK,int TM,int TN,bool BIAS>
__global__ void __launch_bounds__((BM/TM)*(BN/TN))
gemm_nt(const float* __restrict__ A, const float* __restrict__ Bm,
        const float* __restrict__ bias, float* __restrict__ C,
        int K, int lda, int ldb, int ldc)
{
    constexpr int TX = BN/TN, TY = BM/TM, NT = TX*TY;
    const int tid = threadIdx.x;
    const int tx  = tid % TX, ty = tid / TX;
    const int bm  = blockIdx.y*BM, bn = blockIdx.x*BN;

    __shared__ float As[BK][BM+4];
    __shared__ float Bs[BK][BN+4];

    float acc[TM][TN];
#pragma unroll
    for (int i=0;i<TM;i++)
#pragma unroll
        for (int j=0;j<TN;j++) acc[i][j] = 0.f;

    for (int k0 = 0; k0 < K; k0 += BK) {
#pragma unroll
        for (int i = tid; i < BM*BK/4; i += NT) {
            int m  = i / (BK/4);
            int k4 = (i % (BK/4)) * 4;
            float4 v = *reinterpret_cast<const float4*>(&A[(long)(bm+m)*lda + k0 + k4]);
            As[k4+0][m] = v.x; As[k4+1][m] = v.y; As[k4+2][m] = v.z; As[k4+3][m] = v.w;
        }
#pragma unroll
        for (int i = tid; i < BN*BK/4; i += NT) {
            int n  = i / (BK/4);
            int k4 = (i % (BK/4)) * 4;
            float4 v = *reinterpret_cast<const float4*>(&Bm[(long)(bn+n)*ldb + k0 + k4]);
            Bs[k4+0][n] = v.x; Bs[k4+1][n] = v.y; Bs[k4+2][n] = v.z; Bs[k4+3][n] = v.w;
        }
        __syncthreads();
#pragma unroll
        for (int k = 0; k < BK; k++) {
            float af[TM], bf[TN];
#pragma unroll
            for (int i=0;i<TM;i+=4)
                *reinterpret_cast<float4*>(&af[i]) =
                    *reinterpret_cast<const float4*>(&As[k][ty*TM + i]);
#pragma unroll
            for (int j=0;j<TN;j+=4)
                *reinterpret_cast<float4*>(&bf[j]) =
                    *reinterpret_cast<const float4*>(&Bs[k][tx*TN + j]);
#pragma unroll
            for (int i=0;i<TM;i++)
#pragma unroll
                for (int j=0;j<TN;j++)
                    acc[i][j] = fmaf(af[i], bf[j], acc[i][j]);
        }
        __syncthreads();
    }

#pragma unroll
    for (int i=0;i<TM;i++) {
        const int m = bm + ty*TM + i;
        float* crow = &C[(long)m*ldc + bn + tx*TN];
#pragma unroll
        for (int j=0;j<TN;j+=4) {
            float4 v;
            v.x = acc[i][j+0]; v.y = acc[i][j+1]; v.z = acc[i][j+2]; v.w = acc[i][j+3];
            if (BIAS) {
                const float* bp = &bias[bn + tx*TN + j];
                v.x += bp[0]; v.y += bp[1]; v.z += bp[2]; v.w += bp[3];
            }
            *reinterpret_cast<float4*>(&crow[j]) = v;
        }
    }
}

// =====================================================================
// qk = scale * q_h @ Wk_h -> half; also zeroes g_rowsum (runs before K3)
// =====================================================================
__global__ void qk_kernel(const float* __restrict__ q,
                          const float* __restrict__ Wk,
                          __half* __restrict__ qkh,
                          float* __restrict__ rowsum)
{
    const int bh = blockIdx.y;
    const int b = bh >> 4, h = bh & 15;
    const int col = blockIdx.x*128 + threadIdx.x;
    if (blockIdx.x == 0 && bh == 0) {
#pragma unroll
        for (int r = 0; r < BB*RPB/128; r++)
            rowsum[r*128 + threadIdx.x] = 0.f;
    }
    __shared__ __align__(16) float at[HDIM][LQ];
    for (int i = threadIdx.x; i < LQ*HDIM; i += 128) {
        int qq = i >> 6, e = i & 63;
        at[e][qq] = q[(b*LQ + qq)*HID + h*HDIM + e];
    }
    __syncthreads();
    float acc[LQ];
#pragma unroll
    for (int i = 0; i < LQ; i++) acc[i] = 0.f;
#pragma unroll 4
    for (int e = 0; e < HDIM; e++) {
        const float wv = Wk[(h*HDIM + e)*HID + col];
        float4 a0 = *reinterpret_cast<const float4*>(&at[e][0]);
        float4 a1 = *reinterpret_cast<const float4*>(&at[e][4]);
        float4 a2 = *reinterpret_cast<const float4*>(&at[e][8]);
        float4 a3 = *reinterpret_cast<const float4*>(&at[e][12]);
        acc[0]  = fmaf(a0.x, wv, acc[0]);  acc[1]  = fmaf(a0.y, wv, acc[1]);
        acc[2]  = fmaf(a0.z, wv, acc[2]);  acc[3]  = fmaf(a0.w, wv, acc[3]);
        acc[4]  = fmaf(a1.x, wv, acc[4]);  acc[5]  = fmaf(a1.y, wv, acc[5]);
        acc[6]  = fmaf(a1.z, wv, acc[6]);  acc[7]  = fmaf(a1.w, wv, acc[7]);
        acc[8]  = fmaf(a2.x, wv, acc[8]);  acc[9]  = fmaf(a2.y, wv, acc[9]);
        acc[10] = fmaf(a2.z, wv, acc[10]); acc[11] = fmaf(a2.w, wv, acc[11]);
        acc[12] = fmaf(a3.x, wv, acc[12]); acc[13] = fmaf(a3.y, wv, acc[13]);
        acc[14] = fmaf(a3.z, wv, acc[14]); acc[15] = fmaf(a3.w, wv, acc[15]);
    }
    const float scale = 0.125f;
#pragma unroll
    for (int qq = 0; qq < LQ; qq++)
        qkh[((long)b*RPB + h*LQ + qq)*HID + col] = __float2half_rn(acc[qq] * scale);
}

// =====================================================================
// attn = inv_rowsum * (ctx slab A + slab B) @ Wv_h^T + bv, per (b,h)
// =====================================================================
__global__ void attnv_kernel(const float* __restrict__ ctx,
                             const float* __restrict__ rowsum,
                             const float* __restrict__ Wv,
                             const float* __restrict__ bv,
                             float* __restrict__ attn)
{
    const int bh = blockIdx.x;
    const int b = bh >> 4, h = bh & 15;
    const int t = threadIdx.x;
    const int d = t & 63, qg = t >> 6;
    __shared__ float cs[LQ][129];
    __shared__ float ws[HDIM][129];
    __shared__ float inv[LQ];
    float acc[4] = {0.f,0.f,0.f,0.f};

    if (t < LQ) inv[t] = 1.f / rowsum[b*RPB + h*LQ + t];

    const long rowA = (long)(b*2    )*RPB + h*LQ;
    const long rowB = (long)(b*2 + 1)*RPB + h*LQ;

    for (int e0 = 0; e0 < HID; e0 += 128) {
        __syncthreads();
        for (int i = t; i < LQ*128; i += 256) {
            int qq = i >> 7, e = i & 127;
            cs[qq][e] = (ctx[(rowA + qq)*HID + e0 + e] + ctx[(rowB + qq)*HID + e0 + e]) * inv[qq];
        }
        for (int i = t; i < HDIM*128; i += 256) {
            int dd = i >> 7, e = i & 127;
            ws[dd][e] = Wv[(long)(h*HDIM + dd)*HID + e0 + e];
        }
        __syncthreads();
#pragma unroll 4
        for (int e = 0; e < 128; e++) {
            float wv = ws[d][e];
#pragma unroll
            for (int j = 0; j < 4; j++)
                acc[j] = fmaf(cs[qg*4 + j][e], wv, acc[j]);
        }
    }
    const float bvv = bv[h*HDIM + d];
#pragma unroll
    for (int j = 0; j < 4; j++)
        attn[(long)(b*LQ + qg*4 + j)*HID + h*HDIM + d] = acc[j] + bvv;
}

// =====================================================================
// launch  (K5 is now the 4th launch -> profiled for the first time)
// =====================================================================
extern "C" void kernel_launch(void* const* d_in, const int* in_sizes, int n_in,
                              void* d_out, int out_size)
{
    const float* query = (const float*)d_in[0];
    const float* key   = (const float*)d_in[1];
    const float* value = (const float*)d_in[2];
    const float* Wq    = (const float*)d_in[3];
    const float* bq    = (const float*)d_in[4];
    const float* Wk    = (const float*)d_in[5];
    /* bk = d_in[6] : softmax-invariant, dropped */
    const float* Wv    = (const float*)d_in[7];
    const float* bv    = (const float*)d_in[8];
    const float* Wo    = (const float*)d_in[9];
    const float* bo    = (const float*)d_in[10];
    float* out = (float*)d_out;

    float *gq, *gctx, *gattn, *grs;
    __half *gqkh, *geh;
    cudaGetSymbolAddress((void**)&gq,    g_q);
    cudaGetSymbolAddress((void**)&gqkh,  g_qkh);
    cudaGetSymbolAddress((void**)&geh,   g_eh);
    cudaGetSymbolAddress((void**)&grs,   g_rowsum);
    cudaGetSymbolAddress((void**)&gctx,  g_ctx);
    cudaGetSymbolAddress((void**)&gattn, g_attn);

    cudaFuncSetAttribute((const void*)gemm_hf<__half,0,1>, cudaFuncAttributeMaxDynamicSharedMemorySize, GH_SMEM);
    cudaFuncSetAttribute((const void*)gemm_hf<float,1,0>,  cudaFuncAttributeMaxDynamicSharedMemorySize, GH_SMEM);

    // #1  K1: q = query @ Wq^T + bq (fp32)
    gemm_nt<64,64,16,4,4,true><<<dim3(HID/64, (BB*LQ)/64), 256>>>(
        query, Wq, bq, gq, HID, HID, HID, HID);

    // #2  K2: qk = scale * q_h @ Wk_h -> half  (also zeroes rowsum)
    qk_kernel<<<dim3(HID/128, BB*NHEAD), 128>>>(gq, Wk, gqkh, grs);

    // #3  K3: e = exp(qkh @ key^T) + row sums  [256 x 8192] per batch (B fp32 in-kernel cvt)
    gemm_hf<__half,0,1><<<dim3(LK/64, 1, BB), 256, GH_SMEM>>>(
        gqkh, key, geh, grs, HID, HID, HID, LK,
        (long)RPB*HID, (long)LK*HID, (long)RPB*LK, 1);

    // #4  K5: ctx = e @ value (NN via ldmatrix.trans, B fp32 in-kernel cvt)  (PROFILED)
    gemm_hf<float,1,0><<<dim3(HID/64, 1, BB*2), 256, GH_SMEM>>>(
        geh, value, gctx, nullptr, LK/2, LK, HID, HID,
        (long)RPB*LK, (long)LK*HID, (long)RPB*HID, 2);

    // #5  K6: attn = inv_rowsum * ctx @ Wv_h^T + bv
    attnv_kernel<<<BB*NHEAD, 256>>>(gctx, grs, Wv, bv, gattn);

    // #6  K7: out = attn @ Wo^T + bo
    gemm_nt<64,64,16,4,4,true><<<dim3(HID/64, (BB*LQ)/64), 256>>>(
        gattn, Wo, bo, out, HID, HID, HID, HID);
}

// round 12
// speedup vs baseline: 2.5287x; 1.0001x over previous
#include <cuda_runtime.h>
#include <cuda_fp16.h>
#include <cstdint>
#include <math.h>

#define HID   1024
#define NHEAD 16
#define HDIM  64
#define BB    8
#define LQ    16
#define LK    8192
#define RPB   (NHEAD*LQ)   /* 256 rows per batch */

// ---------------- scratch ----------------
__device__ float  g_q[BB*LQ*HID];
__device__ __half g_qkh[BB*RPB*HID];
__device__ __half g_eh[(size_t)BB*RPB*LK];      // exp(logits), unnormalized
__device__ float  g_rowsum[BB*RPB];             // per-row sum of exp
__device__ float  g_ctx[2*BB*RPB*HID];
__device__ float  g_attn[BB*LQ*HID];

// =====================================================================
// asm helpers
// =====================================================================
__device__ __forceinline__ uint32_t smem_u32(const void* p) {
    uint32_t a;
    asm("{ .reg .u64 t; cvta.to.shared.u64 t, %1; cvt.u32.u64 %0, t; }" : "=r"(a) : "l"(p));
    return a;
}
#define CP_ASYNC16(dst, src) \
    asm volatile("cp.async.cg.shared.global [%0], [%1], 16;" :: "r"(dst), "l"(src) : "memory")
#define CP_COMMIT()  asm volatile("cp.async.commit_group;" ::: "memory")
#define CP_WAIT2()   asm volatile("cp.async.wait_group 2;" ::: "memory")
#define LDSM4(r, addr) \
    asm volatile("ldmatrix.sync.aligned.m8n8.x4.shared.b16 {%0,%1,%2,%3}, [%4];" \
        : "=r"((r)[0]), "=r"((r)[1]), "=r"((r)[2]), "=r"((r)[3]) : "r"(addr))
#define LDSM4_T(r, addr) \
    asm volatile("ldmatrix.sync.aligned.m8n8.x4.trans.shared.b16 {%0,%1,%2,%3}, [%4];" \
        : "=r"((r)[0]), "=r"((r)[1]), "=r"((r)[2]), "=r"((r)[3]) : "r"(addr))

__device__ __forceinline__ void mma_f16(float c[4], const unsigned a[4], const unsigned b[2]) {
    asm("mma.sync.aligned.m16n8k16.row.col.f32.f16.f16.f32 "
        "{%0,%1,%2,%3}, {%4,%5,%6,%7}, {%8,%9}, {%0,%1,%2,%3};"
        : "+f"(c[0]), "+f"(c[1]), "+f"(c[2]), "+f"(c[3])
        : "r"(a[0]), "r"(a[1]), "r"(a[2]), "r"(a[3]), "r"(b[0]), "r"(b[1]));
}

// =====================================================================
// gemm_hf: A half [m][k]; B fp32 converted to half in-kernel.
// TRB=0: B[n*ldb + k] (NT);  TRB=1: B[k*ldb + n] (NN via ldmatrix.trans)
// DOEXP=1: C = exp(acc) half + per-row atomicAdd exp-sums into rowsum.
// BM=256, BN=64, BK=32, 256 thr (8 warps = 4m x 2n, warp tile 64x32).
// 4-stage cp.async (A half + B fp32 in two 4KB planes); per-chunk the
// B fp32 tile is converted into ONE swizzled half buffer (sync-guarded).
// =====================================================================
#define ST_BYTES 24576           /* per stage: A 16KB + B32 8KB */
#define B32_OFF  16384
#define BH_OFF   98304           /* single 4KB half-B buffer after 4 stages */
#define GH_SMEM  (4*ST_BYTES + 4096)

template<typename CT, int TRB, int DOEXP>
__global__ void __launch_bounds__(256, 2)
gemm_hf(const __half* __restrict__ A, const float* __restrict__ B,
        CT* __restrict__ C, float* __restrict__ rowsum,
        int Kpart, int lda, int ldb, int ldc,
        long sA, long sB, long sC, int ksplit)
{
    extern __shared__ __align__(16) char smem[];
    const uint32_t sb = smem_u32(smem);

    const int tid  = threadIdx.x;
    const int w    = tid >> 5;
    const int lane = tid & 31;
    const int g    = lane >> 2;
    const int tg   = lane & 3;
    const int wm   = (w >> 1) * 64;
    const int wn   = (w & 1) * 32;

    const int batch = blockIdx.z / ksplit;
    const int part  = blockIdx.z % ksplit;
    const int bn    = blockIdx.x * 64;
    A += (long)batch*sA + (long)part*Kpart;
    if (TRB == 0) B += (long)batch*sB + (long)part*Kpart;
    else          B += (long)batch*sB + (long)part*Kpart*ldb;
    C += (long)blockIdx.z*sC;

    // ---- cp.async coordinates ----
    const int kc = tid & 3;
    const int ar = tid >> 2;
    const __half* aP = A + (long)ar*lda + kc*8;
    const long aStride64 = (long)64*lda;
    const uint32_t aDst0 = (uint32_t)(ar*64 + ((kc ^ ((ar>>1)&3)) << 4));

    // B fp32: each thread owns one 8-float "group" per chunk, split in 2 planes.
    const float* bP;
    if (TRB == 0) bP = B + (long)(bn + (tid >> 2))*ldb + (tid & 3)*8;
    else          bP = B + (long)(tid >> 3)*ldb + bn + (tid & 7)*8;
    const uint32_t b32d0 = (uint32_t)(B32_OFF + tid*16);
    const uint32_t b32d1 = (uint32_t)(B32_OFF + 4096 + tid*16);

    // half-B destination (swizzled fragment layout)
    uint32_t bhDst;
    if (TRB == 0) {
        const int row = tid >> 2, kcc = tid & 3;
        bhDst = (uint32_t)(BH_OFF + row*64 + ((kcc ^ ((row>>1)&3)) << 4));
    } else {
        const int kr = tid >> 3, g8 = tid & 7;
        bhDst = (uint32_t)(BH_OFF + kr*128 + ((g8 ^ (kr & 7)) << 4));
    }

    // ---- ldmatrix offsets ----
    uint32_t aLd[2], bLd[2][2];
    {
        const int mrow = wm + (lane & 7) + ((lane >> 3) & 1) * 8;
        const int msel = (mrow >> 1) & 3;
#pragma unroll
        for (int s = 0; s < 2; s++) {
            const int kcc = 2*s + (lane >> 4);
            aLd[s] = (uint32_t)(mrow*64 + ((kcc ^ msel) << 4));
        }
        if (TRB == 0) {
            const int nrow = wn + (lane & 7) + ((lane >> 4) << 3);
            const int nsel = (nrow >> 1) & 3;
#pragma unroll
            for (int s = 0; s < 2; s++) {
                const int kcc = 2*s + ((lane >> 3) & 1);
                bLd[s][0] = (uint32_t)(BH_OFF + nrow*64 + ((kcc ^ nsel) << 4));
                bLd[s][1] = bLd[s][0] + 1024;
            }
        } else {
#pragma unroll
            for (int s = 0; s < 2; s++) {
                const int krow = s*16 + ((lane >> 3) & 1)*8 + (lane & 7);
#pragma unroll
                for (int c = 0; c < 2; c++) {
                    const int n8 = (wn >> 3) + (lane >> 4) + 2*c;
                    bLd[s][c] = (uint32_t)(BH_OFF + krow*128 + ((n8 ^ (krow & 7)) << 4));
                }
            }
        }
    }

    float acc[4][4][4];
#pragma unroll
    for (int i = 0; i < 4; i++)
#pragma unroll
        for (int j = 0; j < 4; j++)
#pragma unroll
            for (int r = 0; r < 4; r++) acc[i][j][r] = 0.f;

    const int chunks = Kpart / 32;

    auto issue = [&](int slot) {
        const uint32_t base = sb + slot*ST_BYTES;
#pragma unroll
        for (int i = 0; i < 4; i++)
            CP_ASYNC16(base + aDst0 + i*4096, aP + i*aStride64);
        CP_ASYNC16(base + b32d0, bP);
        CP_ASYNC16(base + b32d1, bP + 4);
        aP += 32;
        bP += (TRB == 0) ? 32 : (long)32*ldb;
    };

    issue(0); CP_COMMIT();
    issue(1); CP_COMMIT();
    issue(2); CP_COMMIT();

    for (int c = 0; c < chunks; c++) {
        CP_WAIT2();
        __syncthreads();
        if (c + 3 < chunks) issue((c + 3) & 3);
        CP_COMMIT();

        const uint32_t base = sb + (c & 3)*ST_BYTES;
        // convert this chunk's fp32 B tile -> half fragment buffer
        {
            float4 f0, f1;
            asm volatile("ld.shared.v4.f32 {%0,%1,%2,%3}, [%4];"
                : "=f"(f0.x), "=f"(f0.y), "=f"(f0.z), "=f"(f0.w) : "r"(base + b32d0));
            asm volatile("ld.shared.v4.f32 {%0,%1,%2,%3}, [%4];"
                : "=f"(f1.x), "=f"(f1.y), "=f"(f1.z), "=f"(f1.w) : "r"(base + b32d1));
            __half2 h0 = __floats2half2_rn(f0.x, f0.y);
            __half2 h1 = __floats2half2_rn(f0.z, f0.w);
            __half2 h2 = __floats2half2_rn(f1.x, f1.y);
            __half2 h3 = __floats2half2_rn(f1.z, f1.w);
            asm volatile("st.shared.v4.b32 [%0], {%1,%2,%3,%4};"
                :: "r"(sb + bhDst),
                   "r"(*reinterpret_cast<unsigned*>(&h0)),
                   "r"(*reinterpret_cast<unsigned*>(&h1)),
                   "r"(*reinterpret_cast<unsigned*>(&h2)),
                   "r"(*reinterpret_cast<unsigned*>(&h3)) : "memory");
        }
        __syncthreads();

#pragma unroll
        for (int s = 0; s < 2; s++) {
            unsigned af[4][4], bq[8];
#pragma unroll
            for (int mt = 0; mt < 4; mt++)
                LDSM4(af[mt], base + aLd[s] + mt*1024);
            if (TRB == 0) {
                LDSM4(bq + 0, sb + bLd[s][0]);
                LDSM4(bq + 4, sb + bLd[s][1]);
            } else {
                LDSM4_T(bq + 0, sb + bLd[s][0]);
                LDSM4_T(bq + 4, sb + bLd[s][1]);
            }
#pragma unroll
            for (int i = 0; i < 4; i++)
#pragma unroll
                for (int j = 0; j < 4; j++)
                    mma_f16(acc[i][j], af[i], &bq[j*2]);
        }
    }

    // ---- epilogue ----
#pragma unroll
    for (int i = 0; i < 4; i++) {
        const int row0 = wm + i*16 + g;
        float s0 = 0.f, s1 = 0.f;
#pragma unroll
        for (int j = 0; j < 4; j++) {
            const int col = bn + wn + j*8 + 2*tg;
            if (DOEXP) {
                float e0 = expf(acc[i][j][0]);
                float e1 = expf(acc[i][j][1]);
                float e2 = expf(acc[i][j][2]);
                float e3 = expf(acc[i][j][3]);
                s0 += e0 + e1;  s1 += e2 + e3;
                *reinterpret_cast<__half2*>(&((__half*)C)[(long)row0*ldc + col]) =
                    __floats2half2_rn(e0, e1);
                *reinterpret_cast<__half2*>(&((__half*)C)[(long)(row0 + 8)*ldc + col]) =
                    __floats2half2_rn(e2, e3);
            } else if (sizeof(CT) == 4) {
                *reinterpret_cast<float2*>(&((float*)C)[(long)row0*ldc + col]) =
                    make_float2(acc[i][j][0], acc[i][j][1]);
                *reinterpret_cast<float2*>(&((float*)C)[(long)(row0 + 8)*ldc + col]) =
                    make_float2(acc[i][j][2], acc[i][j][3]);
            } else {
                *reinterpret_cast<__half2*>(&((__half*)C)[(long)row0*ldc + col]) =
                    __floats2half2_rn(acc[i][j][0], acc[i][j][1]);
                *reinterpret_cast<__half2*>(&((__half*)C)[(long)(row0 + 8)*ldc + col]) =
                    __floats2half2_rn(acc[i][j][2], acc[i][j][3]);
            }
        }
        if (DOEXP) {
            s0 += __shfl_xor_sync(0xffffffffu, s0, 1);
            s0 += __shfl_xor_sync(0xffffffffu, s0, 2);
            s1 += __shfl_xor_sync(0xffffffffu, s1, 1);
            s1 += __shfl_xor_sync(0xffffffffu, s1, 2);
            if (tg == 0) {
                float* rs = rowsum + (long)blockIdx.z * RPB;
                atomicAdd(&rs[row0],     s0);
                atomicAdd(&rs[row0 + 8], s1);
            }
        }
    }
}

// =====================================================================
// fp32 FFMA NT GEMM for small projections K1/K7
// =====================================================================
template<int BM,int BN,int BK,int TM,int TN,bool BIAS>
__global__ void __launch_bounds__((BM/TM)*(BN/TN))
gemm_nt(const float* __restrict__ A, const float* __restrict__ Bm,
        const float* __restrict__ bias, float* __restrict__ C,
        int K, int lda, int ldb, int ldc)
{
    constexpr int TX = BN/TN, TY = BM/TM, NT = TX*TY;
    const int tid = threadIdx.x;
    const int tx  = tid % TX, ty = tid / TX;
    const int bm  = blockIdx.y*BM, bn = blockIdx.x*BN;

    __shared__ float As[BK][BM+4];
    __shared__ float Bs[BK][BN+4];

    float acc[TM][TN];
#pragma unroll
    for (int i=0;i<TM;i++)
#pragma unroll
        for (int j=0;j<TN;j++) acc[i][j] = 0.f;

    for (int k0 = 0; k0 < K; k0 += BK) {
#pragma unroll
        for (int i = tid; i < BM*BK/4; i += NT) {
            int m  = i / (BK/4);
            int k4 = (i % (BK/4)) * 4;
            float4 v = *reinterpret_cast<const float4*>(&A[(long)(bm+m)*lda + k0 + k4]);
            As[k4+0][m] = v.x; As[k4+1][m] = v.y; As[k4+2][m] = v.z; As[k4+3][m] = v.w;
        }
#pragma unroll
        for (int i = tid; i < BN*BK/4; i += NT) {
            int n  = i / (BK/4);
            int k4 = (i % (BK/4)) * 4;
            float4 v = *reinterpret_cast<const float4*>(&Bm[(long)(bn+n)*ldb + k0 + k4]);
            Bs[k4+0][n] = v.x; Bs[k4+1][n] = v.y; Bs[k4+2][n] = v.z; Bs[k4+3][n] = v.w;
        }
        __syncthreads();
#pragma unroll
        for (int k = 0; k < BK; k++) {
            float af[TM], bf[TN];
#pragma unroll
            for (int i=0;i<TM;i+=4)
                *reinterpret_cast<float4*>(&af[i]) =
                    *reinterpret_cast<const float4*>(&As[k][ty*TM + i]);
#pragma unroll
            for (int j=0;j<TN;j+=4)
                *reinterpret_cast<float4*>(&bf[j]) =
                    *reinterpret_cast<const float4*>(&Bs[k][tx*TN + j]);
#pragma unroll
            for (int i=0;i<TM;i++)
#pragma unroll
                for (int j=0;j<TN;j++)
                    acc[i][j] = fmaf(af[i], bf[j], acc[i][j]);
        }
        __syncthreads();
    }

#pragma unroll
    for (int i=0;i<TM;i++) {
        const int m = bm + ty*TM + i;
        float* crow = &C[(long)m*ldc + bn + tx*TN];
#pragma unroll
        for (int j=0;j<TN;j+=4) {
            float4 v;
            v.x = acc[i][j+0]; v.y = acc[i][j+1]; v.z = acc[i][j+2]; v.w = acc[i][j+3];
            if (BIAS) {
                const float* bp = &bias[bn + tx*TN + j];
                v.x += bp[0]; v.y += bp[1]; v.z += bp[2]; v.w += bp[3];
            }
            *reinterpret_cast<float4*>(&crow[j]) = v;
        }
    }
}

// =====================================================================
// qk = scale * q_h @ Wk_h -> half; also zeroes g_rowsum (runs before K3)
// =====================================================================
__global__ void qk_kernel(const float* __restrict__ q,
                          const float* __restrict__ Wk,
                          __half* __restrict__ qkh,
                          float* __restrict__ rowsum)
{
    const int bh = blockIdx.y;
    const int b = bh >> 4, h = bh & 15;
    const int col = blockIdx.x*128 + threadIdx.x;
    if (blockIdx.x == 0 && bh == 0) {
#pragma unroll
        for (int r = 0; r < BB*RPB/128; r++)
            rowsum[r*128 + threadIdx.x] = 0.f;
    }
    __shared__ __align__(16) float at[HDIM][LQ];
    for (int i = threadIdx.x; i < LQ*HDIM; i += 128) {
        int qq = i >> 6, e = i & 63;
        at[e][qq] = q[(b*LQ + qq)*HID + h*HDIM + e];
    }
    __syncthreads();
    float acc[LQ];
#pragma unroll
    for (int i = 0; i < LQ; i++) acc[i] = 0.f;
#pragma unroll 4
    for (int e = 0; e < HDIM; e++) {
        const float wv = Wk[(h*HDIM + e)*HID + col];
        float4 a0 = *reinterpret_cast<const float4*>(&at[e][0]);
        float4 a1 = *reinterpret_cast<const float4*>(&at[e][4]);
        float4 a2 = *reinterpret_cast<const float4*>(&at[e][8]);
        float4 a3 = *reinterpret_cast<const float4*>(&at[e][12]);
        acc[0]  = fmaf(a0.x, wv, acc[0]);  acc[1]  = fmaf(a0.y, wv, acc[1]);
        acc[2]  = fmaf(a0.z, wv, acc[2]);  acc[3]  = fmaf(a0.w, wv, acc[3]);
        acc[4]  = fmaf(a1.x, wv, acc[4]);  acc[5]  = fmaf(a1.y, wv, acc[5]);
        acc[6]  = fmaf(a1.z, wv, acc[6]);  acc[7]  = fmaf(a1.w, wv, acc[7]);
        acc[8]  = fmaf(a2.x, wv, acc[8]);  acc[9]  = fmaf(a2.y, wv, acc[9]);
        acc[10] = fmaf(a2.z, wv, acc[10]); acc[11] = fmaf(a2.w, wv, acc[11]);
        acc[12] = fmaf(a3.x, wv, acc[12]); acc[13] = fmaf(a3.y, wv, acc[13]);
        acc[14] = fmaf(a3.z, wv, acc[14]); acc[15] = fmaf(a3.w, wv, acc[15]);
    }
    const float scale = 0.125f;
#pragma unroll
    for (int qq = 0; qq < LQ; qq++)
        qkh[((long)b*RPB + h*LQ + qq)*HID + col] = __float2half_rn(acc[qq] * scale);
}

// =====================================================================
// attn = inv_rowsum * (ctx slab A + slab B) @ Wv_h^T + bv, per (b,h)
// =====================================================================
__global__ void attnv_kernel(const float* __restrict__ ctx,
                             const float* __restrict__ rowsum,
                             const float* __restrict__ Wv,
                             const float* __restrict__ bv,
                             float* __restrict__ attn)
{
    const int bh = blockIdx.x;
    const int b = bh >> 4, h = bh & 15;
    const int t = threadIdx.x;
    const int d = t & 63, qg = t >> 6;
    __shared__ float cs[LQ][129];
    __shared__ float ws[HDIM][129];
    __shared__ float inv[LQ];
    float acc[4] = {0.f,0.f,0.f,0.f};

    if (t < LQ) inv[t] = 1.f / rowsum[b*RPB + h*LQ + t];

    const long rowA = (long)(b*2    )*RPB + h*LQ;
    const long rowB = (long)(b*2 + 1)*RPB + h*LQ;

    for (int e0 = 0; e0 < HID; e0 += 128) {
        __syncthreads();
        for (int i = t; i < LQ*128; i += 256) {
            int qq = i >> 7, e = i & 127;
            cs[qq][e] = (ctx[(rowA + qq)*HID + e0 + e] + ctx[(rowB + qq)*HID + e0 + e]) * inv[qq];
        }
        for (int i = t; i < HDIM*128; i += 256) {
            int dd = i >> 7, e = i & 127;
            ws[dd][e] = Wv[(long)(h*HDIM + dd)*HID + e0 + e];
        }
        __syncthreads();
#pragma unroll 4
        for (int e = 0; e < 128; e++) {
            float wv = ws[d][e];
#pragma unroll
            for (int j = 0; j < 4; j++)
                acc[j] = fmaf(cs[qg*4 + j][e], wv, acc[j]);
        }
    }
    const float bvv = bv[h*HDIM + d];
#pragma unroll
    for (int j = 0; j < 4; j++)
        attn[(long)(b*LQ + qg*4 + j)*HID + h*HDIM + d] = acc[j] + bvv;
}

// =====================================================================
// launch  (K5 is now the 4th launch -> profiled for the first time)
// =====================================================================
extern "C" void kernel_launch(void* const* d_in, const int* in_sizes, int n_in,
                              void* d_out, int out_size)
{
    const float* query = (const float*)d_in[0];
    const float* key   = (const float*)d_in[1];
    const float* value = (const float*)d_in[2];
    const float* Wq    = (const float*)d_in[3];
    const float* bq    = (const float*)d_in[4];
    const float* Wk    = (const float*)d_in[5];
    /* bk = d_in[6] : softmax-invariant, dropped */
    const float* Wv    = (const float*)d_in[7];
    const float* bv    = (const float*)d_in[8];
    const float* Wo    = (const float*)d_in[9];
    const float* bo    = (const float*)d_in[10];
    float* out = (float*)d_out;

    float *gq, *gctx, *gattn, *grs;
    __half *gqkh, *geh;
    cudaGetSymbolAddress((void**)&gq,    g_q);
    cudaGetSymbolAddress((void**)&gqkh,  g_qkh);
    cudaGetSymbolAddress((void**)&geh,   g_eh);
    cudaGetSymbolAddress((void**)&grs,   g_rowsum);
    cudaGetSymbolAddress((void**)&gctx,  g_ctx);
    cudaGetSymbolAddress((void**)&gattn, g_attn);

    cudaFuncSetAttribute((const void*)gemm_hf<__half,0,1>, cudaFuncAttributeMaxDynamicSharedMemorySize, GH_SMEM);
    cudaFuncSetAttribute((const void*)gemm_hf<float,1,0>,  cudaFuncAttributeMaxDynamicSharedMemorySize, GH_SMEM);

    // #1  K1: q = query @ Wq^T + bq (fp32)
    gemm_nt<64,64,16,4,4,true><<<dim3(HID/64, (BB*LQ)/64), 256>>>(
        query, Wq, bq, gq, HID, HID, HID, HID);

    // #2  K2: qk = scale * q_h @ Wk_h -> half  (also zeroes rowsum)
    qk_kernel<<<dim3(HID/128, BB*NHEAD), 128>>>(gq, Wk, gqkh, grs);

    // #3  K3: e = exp(qkh @ key^T) + row sums  [256 x 8192] per batch (B fp32 in-kernel cvt)
    gemm_hf<__half,0,1><<<dim3(LK/64, 1, BB), 256, GH_SMEM>>>(
        gqkh, key, geh, grs, HID, HID, HID, LK,
        (long)RPB*HID, (long)LK*HID, (long)RPB*LK, 1);

    // #4  K5: ctx = e @ value (NN via ldmatrix.trans, B fp32 in-kernel cvt)  (PROFILED)
    gemm_hf<float,1,0><<<dim3(HID/64, 1, BB*2), 256, GH_SMEM>>>(
        geh, value, gctx, nullptr, LK/2, LK, HID, HID,
        (long)RPB*LK, (long)LK*HID, (long)RPB*HID, 2);

    // #5  K6: attn = inv_rowsum * ctx @ Wv_h^T + bv
    attnv_kernel<<<BB*NHEAD, 256>>>(gctx, grs, Wv, bv, gattn);

    // #6  K7: out = attn @ Wo^T + bo
    gemm_nt<64,64,16,4,4,true><<<dim3(HID/64, (BB*LQ)/64), 256>>>(
        gattn, Wo, bo, out, HID, HID, HID, HID);
}